// round 4
// baseline (speedup 1.0000x reference)
#include <cuda_runtime.h>
#include <math.h>

#define TTOK 3072
#define HID  4096
#define NH   32
#define HD   128
#define MAXB 24

// Intermediate scratch (device globals: no allocations allowed)
__device__ float g_q[TTOK * HID];
__device__ float g_k[TTOK * HID];
__device__ float g_v[TTOK * HID];
__device__ float g_att[TTOK * HID];

// ---------------------------------------------------------------------------
// SGEMM: C[M,N] = A[M,K] @ B[N,K]^T + bias   (nn.Linear layout, K-major both)
// 128x128 block tile, BK=16, 256 threads, 8x8 per thread, double-buffered smem
// M=TTOK, N=K=HID (compile-time), all divide tiles exactly.
// ---------------------------------------------------------------------------
#define BM 128
#define BN 128
#define BKD 16

__device__ __forceinline__ void sgemm_body(
    const float* __restrict__ A, const float* __restrict__ B,
    const float* __restrict__ bias, float* __restrict__ C,
    float* As, float* Bs)   // As,Bs: 2*BKD*128 floats each
{
    const int tid = threadIdx.x;
    const int tx = tid & 15, ty = tid >> 4;
    const int m0 = blockIdx.y * BM;
    const int n0 = blockIdx.x * BN;
    const int lr = tid >> 2;            // 0..63
    const int lc = (tid & 3) << 2;      // 0,4,8,12

    const float* Ap = A + (size_t)(m0 + lr) * HID + lc;
    const float* Bp = B + (size_t)(n0 + lr) * HID + lc;
    const size_t rstep = (size_t)64 * HID;

    float4 ra0, ra1, rb0, rb1;
    ra0 = *(const float4*)(Ap);
    ra1 = *(const float4*)(Ap + rstep);
    rb0 = *(const float4*)(Bp);
    rb1 = *(const float4*)(Bp + rstep);
#pragma unroll
    for (int i = 0; i < 4; i++) {
        As[(lc + i) * BM + lr]      = ((const float*)&ra0)[i];
        As[(lc + i) * BM + lr + 64] = ((const float*)&ra1)[i];
        Bs[(lc + i) * BN + lr]      = ((const float*)&rb0)[i];
        Bs[(lc + i) * BN + lr + 64] = ((const float*)&rb1)[i];
    }
    __syncthreads();

    float acc[8][8];
#pragma unroll
    for (int i = 0; i < 8; i++)
#pragma unroll
        for (int j = 0; j < 8; j++) acc[i][j] = 0.f;

    const int nt = HID / BKD;   // 256
    int buf = 0;
    for (int kt = 1; kt < nt; kt++) {
        const float* Ap2 = Ap + kt * BKD;
        const float* Bp2 = Bp + kt * BKD;
        ra0 = *(const float4*)(Ap2);
        ra1 = *(const float4*)(Ap2 + rstep);
        rb0 = *(const float4*)(Bp2);
        rb1 = *(const float4*)(Bp2 + rstep);

        const float* as = As + buf * (BKD * BM);
        const float* bs = Bs + buf * (BKD * BN);
#pragma unroll
        for (int kk = 0; kk < BKD; kk++) {
            float4 a0 = *(const float4*)&as[kk * BM + ty * 4];
            float4 a1 = *(const float4*)&as[kk * BM + 64 + ty * 4];
            float4 b0 = *(const float4*)&bs[kk * BN + tx * 4];
            float4 b1 = *(const float4*)&bs[kk * BN + 64 + tx * 4];
            float ar[8] = {a0.x, a0.y, a0.z, a0.w, a1.x, a1.y, a1.z, a1.w};
            float br[8] = {b0.x, b0.y, b0.z, b0.w, b1.x, b1.y, b1.z, b1.w};
#pragma unroll
            for (int i = 0; i < 8; i++)
#pragma unroll
                for (int j = 0; j < 8; j++) acc[i][j] += ar[i] * br[j];
        }
        const int nb = buf ^ 1;
        float* asw = As + nb * (BKD * BM);
        float* bsw = Bs + nb * (BKD * BN);
#pragma unroll
        for (int i = 0; i < 4; i++) {
            asw[(lc + i) * BM + lr]      = ((const float*)&ra0)[i];
            asw[(lc + i) * BM + lr + 64] = ((const float*)&ra1)[i];
            bsw[(lc + i) * BN + lr]      = ((const float*)&rb0)[i];
            bsw[(lc + i) * BN + lr + 64] = ((const float*)&rb1)[i];
        }
        __syncthreads();
        buf = nb;
    }
    {   // last tile compute
        const float* as = As + buf * (BKD * BM);
        const float* bs = Bs + buf * (BKD * BN);
#pragma unroll
        for (int kk = 0; kk < BKD; kk++) {
            float4 a0 = *(const float4*)&as[kk * BM + ty * 4];
            float4 a1 = *(const float4*)&as[kk * BM + 64 + ty * 4];
            float4 b0 = *(const float4*)&bs[kk * BN + tx * 4];
            float4 b1 = *(const float4*)&bs[kk * BN + 64 + tx * 4];
            float ar[8] = {a0.x, a0.y, a0.z, a0.w, a1.x, a1.y, a1.z, a1.w};
            float br[8] = {b0.x, b0.y, b0.z, b0.w, b1.x, b1.y, b1.z, b1.w};
#pragma unroll
            for (int i = 0; i < 8; i++)
#pragma unroll
                for (int j = 0; j < 8; j++) acc[i][j] += ar[i] * br[j];
        }
    }

    float4 bi0 = *(const float4*)&bias[n0 + tx * 4];
    float4 bi1 = *(const float4*)&bias[n0 + 64 + tx * 4];
#pragma unroll
    for (int i = 0; i < 8; i++) {
        int r = m0 + ((i < 4) ? (ty * 4 + i) : (64 + ty * 4 + (i - 4)));
        float4 c0 = make_float4(acc[i][0] + bi0.x, acc[i][1] + bi0.y,
                                acc[i][2] + bi0.z, acc[i][3] + bi0.w);
        float4 c1 = make_float4(acc[i][4] + bi1.x, acc[i][5] + bi1.y,
                                acc[i][6] + bi1.z, acc[i][7] + bi1.w);
        *(float4*)&C[(size_t)r * HID + n0 + tx * 4]      = c0;
        *(float4*)&C[(size_t)r * HID + n0 + 64 + tx * 4] = c1;
    }
}

__global__ __launch_bounds__(256, 2)
void qkv_kernel(const float* __restrict__ X,
                const float* __restrict__ Wq, const float* __restrict__ bq,
                const float* __restrict__ Wk, const float* __restrict__ bk,
                const float* __restrict__ Wv, const float* __restrict__ bv)
{
    __shared__ float As[2 * BKD * BM];
    __shared__ float Bs[2 * BKD * BN];
    const float* W; const float* bia; float* C;
    if (blockIdx.z == 0)      { W = Wq; bia = bq; C = g_q; }
    else if (blockIdx.z == 1) { W = Wk; bia = bk; C = g_k; }
    else                      { W = Wv; bia = bv; C = g_v; }
    sgemm_body(X, W, bia, C, As, Bs);
}

__global__ __launch_bounds__(256, 2)
void out_kernel(const float* __restrict__ Wo, const float* __restrict__ bo,
                float* __restrict__ out)
{
    __shared__ float As[2 * BKD * BM];
    __shared__ float Bs[2 * BKD * BN];
    sgemm_body(g_att, Wo, bo, out, As, Bs);
}

// ---------------------------------------------------------------------------
// RoPE (Llama rotate_half) in-place on g_q and g_k.
// double sincos => accurate for pos up to 2047 even under fast-math builds.
// ---------------------------------------------------------------------------
__global__ void rope_kernel(const int* __restrict__ pos)
{
    int idx = blockIdx.x * blockDim.x + threadIdx.x;
    if (idx >= TTOK * NH * 64) return;
    int p  = idx & 63;          // pair index 0..63
    int th = idx >> 6;          // t*NH + h
    int t  = th >> 5;

    // inv_freq = 10000^(-p/64)
    double inv = exp(-(double)p * (9.210340371976184 / 64.0));
    double f = (double)pos[t] * inv;
    double sd, cd;
    sincos(f, &sd, &cd);
    float c = (float)cd, s = (float)sd;

    size_t base = (size_t)th * HD;   // == t*HID + h*HD
    float q1 = g_q[base + p], q2 = g_q[base + 64 + p];
    g_q[base + p]      = q1 * c - q2 * s;
    g_q[base + 64 + p] = q2 * c + q1 * s;
    float k1 = g_k[base + p], k2 = g_k[base + 64 + p];
    g_k[base + p]      = k1 * c - k2 * s;
    g_k[base + 64 + p] = k2 * c + k1 * s;
}

// ---------------------------------------------------------------------------
// Flash-style paged causal attention, fp32.
// Block = (q-tile of 64, head, batch), 256 threads.
// K/V sourced directly: j >= hist -> packed new K/V; j < hist -> paged cache
// (the reference's fill_kv_cache scatter is thereby eliminated entirely).
// Thread (rg,cg): rg=tid>>4 owns q-rows 4rg..4rg+3; cg=tid&15 owns
// S-cols 4cg..4cg+3 and O d-cols 8cg..8cg+7. Row reductions via shfl over cg.
// ---------------------------------------------------------------------------
#define AQ 64
#define AK 64
#define VSTR 132   // padded V row stride (kills transpose-store bank conflicts)

// smem floats: Qt 128*64 + Kt 128*64 + Vs 64*132 + Ps 64*64
#define ATTN_SMEM_FLOATS (HD * 64 * 2 + 64 * VSTR + 64 * 64)

__global__ __launch_bounds__(256, 1)
void attn_kernel(const float* __restrict__ past_k, const float* __restrict__ past_v,
                 const int* __restrict__ q_start, const int* __restrict__ q_lens,
                 const int* __restrict__ kv_lens, const int* __restrict__ blk_off)
{
    extern __shared__ float sm[];
    float* Qt = sm;                 // [128][64]  (d-major, scaled)
    float* Kt = Qt + HD * 64;       // [128][64]
    float* Vs = Kt + HD * 64;       // [64][VSTR]
    float* Ps = Vs + 64 * VSTR;     // [64][64]

    const int qt = blockIdx.x, h = blockIdx.y, b = blockIdx.z;
    const int qlen = q_lens[b];
    if (qt * AQ >= qlen) return;
    const int kvlen = kv_lens[b];
    const int hist = kvlen - qlen;
    const int qs = q_start[b];
    const int tid = threadIdx.x;
    const int cg = tid & 15, rg = tid >> 4;
    const float scale = 0.088388347648318447f;  // 1/sqrt(128)

    // Load Q tile transposed into Qt[d][r], pre-scaled.
#pragma unroll
    for (int l = 0; l < 8; l++) {
        int f4 = tid + l * 256;
        int r = f4 & 63;
        int d = (f4 >> 6) << 2;
        int row = qt * AQ + r; if (row >= qlen) row = qlen - 1;
        float4 v = *(const float4*)(g_q + (size_t)(qs + row) * HID + h * HD + d);
        Qt[(d + 0) * 64 + r] = v.x * scale;
        Qt[(d + 1) * 64 + r] = v.y * scale;
        Qt[(d + 2) * 64 + r] = v.z * scale;
        Qt[(d + 3) * 64 + r] = v.w * scale;
    }

    float m_i[4], l_i[4], o[4][8];
#pragma unroll
    for (int i = 0; i < 4; i++) {
        m_i[i] = -3.0e38f; l_i[i] = 0.f;
#pragma unroll
        for (int j = 0; j < 8; j++) o[i][j] = 0.f;
    }

    int nkv = hist + qt * AQ + AQ; if (nkv > kvlen) nkv = kvlen;
    const int ntiles = (nkv + AK - 1) / AK;

    for (int kt = 0; kt < ntiles; kt++) {
        // ---- Load K tile (transposed) and V tile ----
#pragma unroll
        for (int l = 0; l < 8; l++) {
            int f4 = tid + l * 256;
            int c = f4 & 63;
            int d = (f4 >> 6) << 2;
            int j = kt * AK + c;
            float4 kv = make_float4(0.f, 0.f, 0.f, 0.f);
            float4 vv = make_float4(0.f, 0.f, 0.f, 0.f);
            if (j < kvlen) {
                size_t off;
                if (j >= hist) {
                    off = (size_t)(qs + j - hist) * HID + h * HD + d;
                    kv = *(const float4*)(g_k + off);
                    vv = *(const float4*)(g_v + off);
                } else {
                    int blk = blk_off[b * MAXB + (j >> 6)];
                    off = ((size_t)(blk * 64 + (j & 63)) * NH + h) * HD + d;
                    kv = *(const float4*)(past_k + off);
                    vv = *(const float4*)(past_v + off);
                }
            }
            Kt[(d + 0) * 64 + c] = kv.x;
            Kt[(d + 1) * 64 + c] = kv.y;
            Kt[(d + 2) * 64 + c] = kv.z;
            Kt[(d + 3) * 64 + c] = kv.w;
            *(float4*)&Vs[c * VSTR + d] = vv;
        }
        __syncthreads();

        // ---- S = Q K^T (4x4 per thread) ----
        float s[4][4];
#pragma unroll
        for (int i = 0; i < 4; i++)
#pragma unroll
            for (int j = 0; j < 4; j++) s[i][j] = 0.f;

#pragma unroll 8
        for (int k = 0; k < HD; k++) {
            float4 a  = *(const float4*)&Qt[k * 64 + rg * 4];
            float4 bb = *(const float4*)&Kt[k * 64 + cg * 4];
            float ar[4] = {a.x, a.y, a.z, a.w};
            float br[4] = {bb.x, bb.y, bb.z, bb.w};
#pragma unroll
            for (int i = 0; i < 4; i++)
#pragma unroll
                for (int j = 0; j < 4; j++) s[i][j] += ar[i] * br[j];
        }

        // ---- mask + online softmax (shfl reduce across the 16 col-groups) ----
        const int jb = kt * AK + cg * 4;
        const int ib = qt * AQ + rg * 4;
#pragma unroll
        for (int i = 0; i < 4; i++) {
            const int lim = hist + ib + i;
#pragma unroll
            for (int j = 0; j < 4; j++) {
                int jg = jb + j;
                if (jg > lim || jg >= kvlen) s[i][j] = -1e30f;
            }
            float mt = fmaxf(fmaxf(s[i][0], s[i][1]), fmaxf(s[i][2], s[i][3]));
#pragma unroll
            for (int w = 1; w < 16; w <<= 1)
                mt = fmaxf(mt, __shfl_xor_sync(0xffffffffu, mt, w));
            float mnew = fmaxf(m_i[i], mt);
            float alpha = __expf(m_i[i] - mnew);
            float p0 = __expf(s[i][0] - mnew);
            float p1 = __expf(s[i][1] - mnew);
            float p2 = __expf(s[i][2] - mnew);
            float p3 = __expf(s[i][3] - mnew);
            float psum = (p0 + p1) + (p2 + p3);
#pragma unroll
            for (int w = 1; w < 16; w <<= 1)
                psum += __shfl_xor_sync(0xffffffffu, psum, w);
            l_i[i] = l_i[i] * alpha + psum;
            m_i[i] = mnew;
#pragma unroll
            for (int jd = 0; jd < 8; jd++) o[i][jd] *= alpha;
            *(float4*)&Ps[(rg * 4 + i) * 64 + cg * 4] = make_float4(p0, p1, p2, p3);
        }
        __syncthreads();

        // ---- O += P @ V ----
#pragma unroll 4
        for (int c4 = 0; c4 < AK; c4 += 4) {
            float4 pr[4];
#pragma unroll
            for (int i = 0; i < 4; i++)
                pr[i] = *(const float4*)&Ps[(rg * 4 + i) * 64 + c4];
#pragma unroll
            for (int cc = 0; cc < 4; cc++) {
                float4 v0 = *(const float4*)&Vs[(c4 + cc) * VSTR + cg * 8];
                float4 v1 = *(const float4*)&Vs[(c4 + cc) * VSTR + cg * 8 + 4];
#pragma unroll
                for (int i = 0; i < 4; i++) {
                    float p = ((const float*)&pr[i])[cc];
                    o[i][0] += p * v0.x; o[i][1] += p * v0.y;
                    o[i][2] += p * v0.z; o[i][3] += p * v0.w;
                    o[i][4] += p * v1.x; o[i][5] += p * v1.y;
                    o[i][6] += p * v1.z; o[i][7] += p * v1.w;
                }
            }
        }
        __syncthreads();
    }

    // ---- epilogue: normalize and store to packed layout ----
#pragma unroll
    for (int i = 0; i < 4; i++) {
        int row = qt * AQ + rg * 4 + i;
        if (row < qlen) {
            float inv_l = 1.0f / l_i[i];
            size_t base = (size_t)(qs + row) * HID + h * HD + cg * 8;
            *(float4*)&g_att[base] = make_float4(o[i][0] * inv_l, o[i][1] * inv_l,
                                                 o[i][2] * inv_l, o[i][3] * inv_l);
            *(float4*)&g_att[base + 4] = make_float4(o[i][4] * inv_l, o[i][5] * inv_l,
                                                     o[i][6] * inv_l, o[i][7] * inv_l);
        }
    }
}

// ---------------------------------------------------------------------------
extern "C" void kernel_launch(void* const* d_in, const int* in_sizes, int n_in,
                              void* d_out, int out_size)
{
    const float* hidden  = (const float*)d_in[0];
    const int*   pos     = (const int*)d_in[1];
    const int*   q_start = (const int*)d_in[2];
    const int*   q_lens  = (const int*)d_in[3];
    const int*   kv_lens = (const int*)d_in[4];
    const int*   blk_off = (const int*)d_in[5];
    const float* past_k  = (const float*)d_in[6];
    const float* past_v  = (const float*)d_in[7];
    const float* Wq = (const float*)d_in[8];
    const float* bq = (const float*)d_in[9];
    const float* Wk = (const float*)d_in[10];
    const float* bk = (const float*)d_in[11];
    const float* Wv = (const float*)d_in[12];
    const float* bv = (const float*)d_in[13];
    const float* Wo = (const float*)d_in[14];
    const float* bo = (const float*)d_in[15];
    float* out = (float*)d_out;

    // 1) fused QKV projections
    dim3 gq(HID / BN, TTOK / BM, 3);
    qkv_kernel<<<gq, 256>>>(hidden, Wq, bq, Wk, bk, Wv, bv);

    // 2) RoPE on q and k
    int rth = TTOK * NH * 64;
    rope_kernel<<<(rth + 255) / 256, 256>>>(pos);

    // 3) paged causal flash attention
    constexpr int smem = ATTN_SMEM_FLOATS * (int)sizeof(float);
    (void)cudaFuncSetAttribute(attn_kernel, cudaFuncAttributeMaxDynamicSharedMemorySize, smem);
    dim3 ga(16, NH, 4);   // (max q-tiles, heads, batch); short seqs early-exit
    attn_kernel<<<ga, 256, smem>>>(past_k, past_v, q_start, q_lens, kv_lens, blk_off);

    // 4) output projection
    dim3 go(HID / BN, TTOK / BM, 1);
    out_kernel<<<go, 256>>>(Wo, bo, out);
}

// round 8
// speedup vs baseline: 1.3346x; 1.3346x over previous
#include <cuda_runtime.h>
#include <math.h>
#include <stdint.h>

#define TTOK 3072
#define HID  4096
#define NH   32
#define HD   128
#define MAXB 24

// Intermediate scratch (device globals: no allocations allowed)
__device__ float g_q[TTOK * HID];
__device__ float g_k[TTOK * HID];
__device__ float g_v[TTOK * HID];
__device__ float g_att[TTOK * HID];

__device__ __forceinline__ float to_tf32(float x) {
    float y;
    asm("cvt.rna.tf32.f32 %0, %1;" : "=f"(y) : "f"(x));
    return y;
}

// ===========================================================================
// TF32 mma.sync GEMM:  C[M,N] = A[M,K] @ B[N,K]^T + bias  (nn.Linear layout)
// Block 128x128, BK=32, 256 threads = 8 warps (2 x 4), warp tile 64x32.
// mma.sync.m16n8k8 tf32. Staging pre-permutes operands into fragment order:
//   A: [kstep(4)][mtile(8)][lane^kstep(32)][j(4)]  (4096 words = 16 KB)
//   B: [kstep(4)][ntile(16)][lane^kstep(32)][j(2)] (4096 words = 16 KB)
// so fragment loads are conflict-free LDS.128 / LDS.64. Double-buffered.
// ===========================================================================
#define GM 128
#define GN 128
#define GK 32
#define NCHUNK (HID / GK)   // 128
#define GEMM_SMEM (2 * 8192 * 4)   // 64 KB

__device__ __forceinline__ void stage_tile(
    float* __restrict__ Abuf, float* __restrict__ Bbuf,
    const float4* ra, const float4* rb, int tid)
{
#pragma unroll
    for (int l = 0; l < 4; l++) {
        const int row = (tid >> 3) + 32 * l;
        const int c4 = tid & 7;
        const int kstep = c4 >> 1;
        // A scatter: j = (c4&1)<<1 | (row>>3)&1 ; lane = ((row&7)<<2|s)^kstep
        {
            const int j = ((c4 & 1) << 1) | ((row >> 3) & 1);
            const int base = ((kstep * 8 + (row >> 4)) * 128) + j;
            const int flb = (row & 7) << 2;
            const float vv[4] = {ra[l].x, ra[l].y, ra[l].z, ra[l].w};
#pragma unroll
            for (int s = 0; s < 4; s++)
                Abuf[base + ((flb | s) ^ kstep) * 4] = to_tf32(vv[s]);
        }
        // B scatter: j = c4&1 ; ntile = row>>3
        {
            const int j = c4 & 1;
            const int base = ((kstep * 16 + (row >> 3)) * 64) + j;
            const int flb = (row & 7) << 2;
            const float vv[4] = {rb[l].x, rb[l].y, rb[l].z, rb[l].w};
#pragma unroll
            for (int s = 0; s < 4; s++)
                Bbuf[base + ((flb | s) ^ kstep) * 2] = to_tf32(vv[s]);
        }
    }
}

__device__ __forceinline__ void mma_chunk(
    const float* __restrict__ Abuf, const float* __restrict__ Bbuf,
    float acc[4][4][4], int wm, int wn, int lane)
{
#pragma unroll
    for (int k = 0; k < 4; k++) {
        const int ls = lane ^ k;
        uint4 af[4];
        uint2 bf[4];
#pragma unroll
        for (int i = 0; i < 4; i++)
            af[i] = ((const uint4*)Abuf)[(k * 8 + wm * 4 + i) * 32 + ls];
#pragma unroll
        for (int i = 0; i < 4; i++)
            bf[i] = ((const uint2*)Bbuf)[(k * 16 + wn * 4 + i) * 32 + ls];
#pragma unroll
        for (int i = 0; i < 4; i++)
#pragma unroll
            for (int jn = 0; jn < 4; jn++) {
                asm volatile(
                    "mma.sync.aligned.m16n8k8.row.col.f32.tf32.tf32.f32 "
                    "{%0,%1,%2,%3}, {%4,%5,%6,%7}, {%8,%9}, {%0,%1,%2,%3};"
                    : "+f"(acc[i][jn][0]), "+f"(acc[i][jn][1]),
                      "+f"(acc[i][jn][2]), "+f"(acc[i][jn][3])
                    : "r"(af[i].x), "r"(af[i].y), "r"(af[i].z), "r"(af[i].w),
                      "r"(bf[jn].x), "r"(bf[jn].y));
            }
    }
}

__device__ __forceinline__ void gemm128_body(
    const float* __restrict__ A, const float* __restrict__ B,
    const float* __restrict__ bias, float* __restrict__ C, float* smx)
{
    const int tid = threadIdx.x;
    const int w = tid >> 5, lane = tid & 31;
    const int wm = w >> 2, wn = w & 3;
    const int m0 = blockIdx.y * GM, n0 = blockIdx.x * GN;

    float* Ab[2] = {smx,        smx + 8192};
    float* Bb[2] = {smx + 4096, smx + 12288};

    const int r0 = tid >> 3, c4 = tid & 7;
    const float* Aptr = A + (size_t)(m0 + r0) * HID + c4 * 4;
    const float* Bptr = B + (size_t)(n0 + r0) * HID + c4 * 4;
    const size_t lstep = (size_t)32 * HID;

    float4 ra[4], rb[4];
#pragma unroll
    for (int l = 0; l < 4; l++) {
        ra[l] = *(const float4*)(Aptr + l * lstep);
        rb[l] = *(const float4*)(Bptr + l * lstep);
    }
    stage_tile(Ab[0], Bb[0], ra, rb, tid);
    __syncthreads();

    float acc[4][4][4];
#pragma unroll
    for (int i = 0; i < 4; i++)
#pragma unroll
        for (int j = 0; j < 4; j++)
#pragma unroll
            for (int r = 0; r < 4; r++) acc[i][j][r] = 0.f;

    int buf = 0;
    for (int kt = 1; kt < NCHUNK; kt++) {
#pragma unroll
        for (int l = 0; l < 4; l++) {
            ra[l] = *(const float4*)(Aptr + kt * GK + l * lstep);
            rb[l] = *(const float4*)(Bptr + kt * GK + l * lstep);
        }
        mma_chunk(Ab[buf], Bb[buf], acc, wm, wn, lane);
        stage_tile(Ab[buf ^ 1], Bb[buf ^ 1], ra, rb, tid);
        __syncthreads();
        buf ^= 1;
    }
    mma_chunk(Ab[buf], Bb[buf], acc, wm, wn, lane);

    // Epilogue: c0,c1 @ (row, col..col+1); c2,c3 @ (row+8, col..col+1)
    const int qrow = lane >> 2, qcol = (lane & 3) * 2;
#pragma unroll
    for (int jn = 0; jn < 4; jn++) {
        const int colg = n0 + wn * 32 + jn * 8 + qcol;
        const float2 bi = *(const float2*)&bias[colg];
#pragma unroll
        for (int i = 0; i < 4; i++) {
            const int rg = m0 + wm * 64 + i * 16 + qrow;
            float2 v0 = make_float2(acc[i][jn][0] + bi.x, acc[i][jn][1] + bi.y);
            float2 v1 = make_float2(acc[i][jn][2] + bi.x, acc[i][jn][3] + bi.y);
            *(float2*)&C[(size_t)rg * HID + colg] = v0;
            *(float2*)&C[(size_t)(rg + 8) * HID + colg] = v1;
        }
    }
}

__global__ __launch_bounds__(256)
void qkv_kernel(const float* __restrict__ X,
                const float* __restrict__ Wq, const float* __restrict__ bq,
                const float* __restrict__ Wk, const float* __restrict__ bk,
                const float* __restrict__ Wv, const float* __restrict__ bv)
{
    extern __shared__ float smx[];
    const float* W; const float* bia; float* C;
    if (blockIdx.z == 0)      { W = Wq; bia = bq; C = g_q; }
    else if (blockIdx.z == 1) { W = Wk; bia = bk; C = g_k; }
    else                      { W = Wv; bia = bv; C = g_v; }
    gemm128_body(X, W, bia, C, smx);
}

__global__ __launch_bounds__(256)
void out_kernel(const float* __restrict__ Wo, const float* __restrict__ bo,
                float* __restrict__ out)
{
    extern __shared__ float smx[];
    gemm128_body(g_att, Wo, bo, out, smx);
}

// ---------------------------------------------------------------------------
// RoPE (Llama rotate_half) in-place on g_q and g_k. double sincos for accuracy.
// ---------------------------------------------------------------------------
__global__ void rope_kernel(const int* __restrict__ pos)
{
    int idx = blockIdx.x * blockDim.x + threadIdx.x;
    if (idx >= TTOK * NH * 64) return;
    int p  = idx & 63;
    int th = idx >> 6;
    int t  = th >> 5;

    double inv = exp(-(double)p * (9.210340371976184 / 64.0));
    double f = (double)pos[t] * inv;
    double sd, cd;
    sincos(f, &sd, &cd);
    float c = (float)cd, s = (float)sd;

    size_t base = (size_t)th * HD;
    float q1 = g_q[base + p], q2 = g_q[base + 64 + p];
    g_q[base + p]      = q1 * c - q2 * s;
    g_q[base + 64 + p] = q2 * c + q1 * s;
    float k1 = g_k[base + p], k2 = g_k[base + 64 + p];
    g_k[base + p]      = k1 * c - k2 * s;
    g_k[base + 64 + p] = k2 * c + k1 * s;
}

// ---------------------------------------------------------------------------
// Flash-style paged causal attention, fp32 (unchanged from passing R4 kernel).
// ---------------------------------------------------------------------------
#define AQ 64
#define AK 64
#define VSTR 132
#define ATTN_SMEM_FLOATS (HD * 64 * 2 + 64 * VSTR + 64 * 64)

__global__ __launch_bounds__(256, 1)
void attn_kernel(const float* __restrict__ past_k, const float* __restrict__ past_v,
                 const int* __restrict__ q_start, const int* __restrict__ q_lens,
                 const int* __restrict__ kv_lens, const int* __restrict__ blk_off)
{
    extern __shared__ float sm[];
    float* Qt = sm;
    float* Kt = Qt + HD * 64;
    float* Vs = Kt + HD * 64;
    float* Ps = Vs + 64 * VSTR;

    const int qt = blockIdx.x, h = blockIdx.y, b = blockIdx.z;
    const int qlen = q_lens[b];
    if (qt * AQ >= qlen) return;
    const int kvlen = kv_lens[b];
    const int hist = kvlen - qlen;
    const int qs = q_start[b];
    const int tid = threadIdx.x;
    const int cg = tid & 15, rg = tid >> 4;
    const float scale = 0.088388347648318447f;

#pragma unroll
    for (int l = 0; l < 8; l++) {
        int f4 = tid + l * 256;
        int r = f4 & 63;
        int d = (f4 >> 6) << 2;
        int row = qt * AQ + r; if (row >= qlen) row = qlen - 1;
        float4 v = *(const float4*)(g_q + (size_t)(qs + row) * HID + h * HD + d);
        Qt[(d + 0) * 64 + r] = v.x * scale;
        Qt[(d + 1) * 64 + r] = v.y * scale;
        Qt[(d + 2) * 64 + r] = v.z * scale;
        Qt[(d + 3) * 64 + r] = v.w * scale;
    }

    float m_i[4], l_i[4], o[4][8];
#pragma unroll
    for (int i = 0; i < 4; i++) {
        m_i[i] = -3.0e38f; l_i[i] = 0.f;
#pragma unroll
        for (int j = 0; j < 8; j++) o[i][j] = 0.f;
    }

    int nkv = hist + qt * AQ + AQ; if (nkv > kvlen) nkv = kvlen;
    const int ntiles = (nkv + AK - 1) / AK;

    for (int kt = 0; kt < ntiles; kt++) {
#pragma unroll
        for (int l = 0; l < 8; l++) {
            int f4 = tid + l * 256;
            int c = f4 & 63;
            int d = (f4 >> 6) << 2;
            int j = kt * AK + c;
            float4 kv = make_float4(0.f, 0.f, 0.f, 0.f);
            float4 vv = make_float4(0.f, 0.f, 0.f, 0.f);
            if (j < kvlen) {
                size_t off;
                if (j >= hist) {
                    off = (size_t)(qs + j - hist) * HID + h * HD + d;
                    kv = *(const float4*)(g_k + off);
                    vv = *(const float4*)(g_v + off);
                } else {
                    int blk = blk_off[b * MAXB + (j >> 6)];
                    off = ((size_t)(blk * 64 + (j & 63)) * NH + h) * HD + d;
                    kv = *(const float4*)(past_k + off);
                    vv = *(const float4*)(past_v + off);
                }
            }
            Kt[(d + 0) * 64 + c] = kv.x;
            Kt[(d + 1) * 64 + c] = kv.y;
            Kt[(d + 2) * 64 + c] = kv.z;
            Kt[(d + 3) * 64 + c] = kv.w;
            *(float4*)&Vs[c * VSTR + d] = vv;
        }
        __syncthreads();

        float s[4][4];
#pragma unroll
        for (int i = 0; i < 4; i++)
#pragma unroll
            for (int j = 0; j < 4; j++) s[i][j] = 0.f;

#pragma unroll 8
        for (int k = 0; k < HD; k++) {
            float4 a  = *(const float4*)&Qt[k * 64 + rg * 4];
            float4 bb = *(const float4*)&Kt[k * 64 + cg * 4];
            float ar[4] = {a.x, a.y, a.z, a.w};
            float br[4] = {bb.x, bb.y, bb.z, bb.w};
#pragma unroll
            for (int i = 0; i < 4; i++)
#pragma unroll
                for (int j = 0; j < 4; j++) s[i][j] += ar[i] * br[j];
        }

        const int jb = kt * AK + cg * 4;
        const int ib = qt * AQ + rg * 4;
#pragma unroll
        for (int i = 0; i < 4; i++) {
            const int lim = hist + ib + i;
#pragma unroll
            for (int j = 0; j < 4; j++) {
                int jg = jb + j;
                if (jg > lim || jg >= kvlen) s[i][j] = -1e30f;
            }
            float mt = fmaxf(fmaxf(s[i][0], s[i][1]), fmaxf(s[i][2], s[i][3]));
#pragma unroll
            for (int w2 = 1; w2 < 16; w2 <<= 1)
                mt = fmaxf(mt, __shfl_xor_sync(0xffffffffu, mt, w2));
            float mnew = fmaxf(m_i[i], mt);
            float alpha = __expf(m_i[i] - mnew);
            float p0 = __expf(s[i][0] - mnew);
            float p1 = __expf(s[i][1] - mnew);
            float p2 = __expf(s[i][2] - mnew);
            float p3 = __expf(s[i][3] - mnew);
            float psum = (p0 + p1) + (p2 + p3);
#pragma unroll
            for (int w2 = 1; w2 < 16; w2 <<= 1)
                psum += __shfl_xor_sync(0xffffffffu, psum, w2);
            l_i[i] = l_i[i] * alpha + psum;
            m_i[i] = mnew;
#pragma unroll
            for (int jd = 0; jd < 8; jd++) o[i][jd] *= alpha;
            *(float4*)&Ps[(rg * 4 + i) * 64 + cg * 4] = make_float4(p0, p1, p2, p3);
        }
        __syncthreads();

#pragma unroll 4
        for (int c4i = 0; c4i < AK; c4i += 4) {
            float4 pr[4];
#pragma unroll
            for (int i = 0; i < 4; i++)
                pr[i] = *(const float4*)&Ps[(rg * 4 + i) * 64 + c4i];
#pragma unroll
            for (int cc = 0; cc < 4; cc++) {
                float4 v0 = *(const float4*)&Vs[(c4i + cc) * VSTR + cg * 8];
                float4 v1 = *(const float4*)&Vs[(c4i + cc) * VSTR + cg * 8 + 4];
#pragma unroll
                for (int i = 0; i < 4; i++) {
                    float p = ((const float*)&pr[i])[cc];
                    o[i][0] += p * v0.x; o[i][1] += p * v0.y;
                    o[i][2] += p * v0.z; o[i][3] += p * v0.w;
                    o[i][4] += p * v1.x; o[i][5] += p * v1.y;
                    o[i][6] += p * v1.z; o[i][7] += p * v1.w;
                }
            }
        }
        __syncthreads();
    }

#pragma unroll
    for (int i = 0; i < 4; i++) {
        int row = qt * AQ + rg * 4 + i;
        if (row < qlen) {
            float inv_l = 1.0f / l_i[i];
            size_t base = (size_t)(qs + row) * HID + h * HD + cg * 8;
            *(float4*)&g_att[base] = make_float4(o[i][0] * inv_l, o[i][1] * inv_l,
                                                 o[i][2] * inv_l, o[i][3] * inv_l);
            *(float4*)&g_att[base + 4] = make_float4(o[i][4] * inv_l, o[i][5] * inv_l,
                                                     o[i][6] * inv_l, o[i][7] * inv_l);
        }
    }
}

// ---------------------------------------------------------------------------
extern "C" void kernel_launch(void* const* d_in, const int* in_sizes, int n_in,
                              void* d_out, int out_size)
{
    const float* hidden  = (const float*)d_in[0];
    const int*   pos     = (const int*)d_in[1];
    const int*   q_start = (const int*)d_in[2];
    const int*   q_lens  = (const int*)d_in[3];
    const int*   kv_lens = (const int*)d_in[4];
    const int*   blk_off = (const int*)d_in[5];
    const float* past_k  = (const float*)d_in[6];
    const float* past_v  = (const float*)d_in[7];
    const float* Wq = (const float*)d_in[8];
    const float* bq = (const float*)d_in[9];
    const float* Wk = (const float*)d_in[10];
    const float* bk = (const float*)d_in[11];
    const float* Wv = (const float*)d_in[12];
    const float* bv = (const float*)d_in[13];
    const float* Wo = (const float*)d_in[14];
    const float* bo = (const float*)d_in[15];
    float* out = (float*)d_out;

    (void)cudaFuncSetAttribute(qkv_kernel, cudaFuncAttributeMaxDynamicSharedMemorySize, GEMM_SMEM);
    (void)cudaFuncSetAttribute(out_kernel, cudaFuncAttributeMaxDynamicSharedMemorySize, GEMM_SMEM);

    // 1) fused QKV projections (tf32 mma.sync)
    dim3 gq(HID / GN, TTOK / GM, 3);
    qkv_kernel<<<gq, 256, GEMM_SMEM>>>(hidden, Wq, bq, Wk, bk, Wv, bv);

    // 2) RoPE on q and k
    int rth = TTOK * NH * 64;
    rope_kernel<<<(rth + 255) / 256, 256>>>(pos);

    // 3) paged causal flash attention (fp32)
    constexpr int smem = ATTN_SMEM_FLOATS * (int)sizeof(float);
    (void)cudaFuncSetAttribute(attn_kernel, cudaFuncAttributeMaxDynamicSharedMemorySize, smem);
    dim3 ga(16, NH, 4);
    attn_kernel<<<ga, 256, smem>>>(past_k, past_v, q_start, q_lens, kv_lens, blk_off);

    // 4) output projection (tf32 mma.sync)
    dim3 go(HID / GN, TTOK / GM, 1);
    out_kernel<<<go, 256, GEMM_SMEM>>>(Wo, bo, out);
}

// round 9
// speedup vs baseline: 2.3388x; 1.7524x over previous
#include <cuda_runtime.h>
#include <math.h>
#include <stdint.h>

#define TTOK 3072
#define HID  4096
#define NH   32
#define HD   128
#define MAXB 24

// Device-global scratch (no allocations allowed)
__device__ float g_q[TTOK * HID];
__device__ float g_k[TTOK * HID];
__device__ float g_v[TTOK * HID];
__device__ float g_att[TTOK * HID];       // tf32-rounded at production
__device__ float g_x[TTOK * HID];         // tf32-rounded hidden_states
__device__ float g_w[4][HID * HID];       // tf32-rounded Wq,Wk,Wv,Wo

__device__ __forceinline__ float to_tf32(float x) {
    float y;
    asm("cvt.rna.tf32.f32 %0, %1;" : "=f"(y) : "f"(x));
    return y;
}
__device__ __forceinline__ uint32_t smem_u32(const void* p) {
    uint32_t a;
    asm("{ .reg .u64 t; cvta.to.shared.u64 t, %1; cvt.u32.u64 %0, t; }"
        : "=r"(a) : "l"(p));
    return a;
}

#define CP_ASYNC16(dst, src) \
    asm volatile("cp.async.cg.shared.global [%0], [%1], 16;" :: "r"(dst), "l"(src))
#define CP_COMMIT() asm volatile("cp.async.commit_group;" ::: "memory")
#define CP_WAIT1()  asm volatile("cp.async.wait_group 1;"  ::: "memory")
#define CP_WAIT0()  asm volatile("cp.async.wait_group 0;"  ::: "memory")

// ===========================================================================
// Prepass: round inputs once to tf32 (removes cvt from GEMM hot loops and
// lets cp.async feed raw bits with identical numerics to R8's RNA rounding).
// ===========================================================================
__global__ void cvt_prepass(const float4* __restrict__ X,
                            const float4* __restrict__ Wq, const float4* __restrict__ Wk,
                            const float4* __restrict__ Wv, const float4* __restrict__ Wo)
{
    const int which = blockIdx.y;
    const size_t i = (size_t)blockIdx.x * blockDim.x + threadIdx.x;
    const float4* src;
    float4* dst;
    size_t n;
    if (which < 4) {
        src = (which == 0) ? Wq : (which == 1) ? Wk : (which == 2) ? Wv : Wo;
        dst = (float4*)g_w[which];
        n = (size_t)HID * HID / 4;
    } else {
        src = X; dst = (float4*)g_x; n = (size_t)TTOK * HID / 4;
    }
    if (i < n) {
        float4 v = src[i];
        v.x = to_tf32(v.x); v.y = to_tf32(v.y);
        v.z = to_tf32(v.z); v.w = to_tf32(v.w);
        dst[i] = v;
    }
}

// ===========================================================================
// TF32 mma.sync GEMM v2: C[M,N] = A[M,K] @ B[N,K]^T + bias
// Block 128x128, BK=32, 256 thr = 8 warps (2x4), warp tile 64x32.
// cp.async 3-stage pipeline; smem row-major padded [128][36] (conflict-free
// LDS.32 fragments: bank = (4*row + col) & 31). Inputs pre-rounded to tf32.
// ===========================================================================
#define GM 128
#define GN 128
#define GK 32
#define NCHUNK (HID / GK)            // 128
#define ASTRIDE 36
#define TILE_WORDS (128 * ASTRIDE)   // per operand per stage (4608 floats)
#define STAGE_WORDS (2 * TILE_WORDS)
#define GEMM_SMEM (3 * STAGE_WORDS * 4)   // 110592 bytes

__device__ __forceinline__ void gemm_issue_stage(
    const float* __restrict__ A, const float* __restrict__ B,
    int m0, int n0, int kt, uint32_t stage_base, int srow, int quad)
{
    const float* ag = A + (size_t)(m0 + srow) * HID + kt * GK + quad * 4;
    const float* bg = B + (size_t)(n0 + srow) * HID + kt * GK + quad * 4;
    const uint32_t off = (uint32_t)(srow * ASTRIDE + quad * 4) * 4;
    const uint32_t as = stage_base + off;
    const uint32_t bs = stage_base + TILE_WORDS * 4 + off;
#pragma unroll
    for (int l = 0; l < 4; l++) {
        CP_ASYNC16(as + l * 32 * ASTRIDE * 4, ag + (size_t)(l * 32) * HID);
        CP_ASYNC16(bs + l * 32 * ASTRIDE * 4, bg + (size_t)(l * 32) * HID);
    }
}

__device__ __forceinline__ void gemm_mma_stage(
    const float* __restrict__ As, const float* __restrict__ Bs,
    float acc[4][4][4], int wm, int wn, int lane)
{
#pragma unroll
    for (int k = 0; k < 4; k++) {
        const int c0 = k * 8 + (lane & 3);
        uint32_t af[4][4];
        uint32_t bf[4][2];
#pragma unroll
        for (int i = 0; i < 4; i++) {
            const int r0 = wm * 64 + i * 16 + (lane >> 2);
            af[i][0] = __float_as_uint(As[r0 * ASTRIDE + c0]);
            af[i][1] = __float_as_uint(As[(r0 + 8) * ASTRIDE + c0]);
            af[i][2] = __float_as_uint(As[r0 * ASTRIDE + c0 + 4]);
            af[i][3] = __float_as_uint(As[(r0 + 8) * ASTRIDE + c0 + 4]);
        }
#pragma unroll
        for (int j = 0; j < 4; j++) {
            const int nn = wn * 32 + j * 8 + (lane >> 2);
            bf[j][0] = __float_as_uint(Bs[nn * ASTRIDE + c0]);
            bf[j][1] = __float_as_uint(Bs[nn * ASTRIDE + c0 + 4]);
        }
#pragma unroll
        for (int i = 0; i < 4; i++)
#pragma unroll
            for (int jn = 0; jn < 4; jn++) {
                asm volatile(
                    "mma.sync.aligned.m16n8k8.row.col.f32.tf32.tf32.f32 "
                    "{%0,%1,%2,%3}, {%4,%5,%6,%7}, {%8,%9}, {%0,%1,%2,%3};"
                    : "+f"(acc[i][jn][0]), "+f"(acc[i][jn][1]),
                      "+f"(acc[i][jn][2]), "+f"(acc[i][jn][3])
                    : "r"(af[i][0]), "r"(af[i][1]), "r"(af[i][2]), "r"(af[i][3]),
                      "r"(bf[jn][0]), "r"(bf[jn][1]));
            }
    }
}

__device__ __forceinline__ void gemm128_body(
    const float* __restrict__ A, const float* __restrict__ B,
    const float* __restrict__ bias, float* __restrict__ C, float* smx)
{
    const int tid = threadIdx.x;
    const int w = tid >> 5, lane = tid & 31;
    const int wm = w >> 2, wn = w & 3;
    const int m0 = blockIdx.y * GM, n0 = blockIdx.x * GN;
    const int srow = tid >> 3, quad = tid & 7;
    const uint32_t sbase = smem_u32(smx);
    const uint32_t stage_addr[3] = {sbase, sbase + STAGE_WORDS * 4,
                                    sbase + 2 * STAGE_WORDS * 4};

    float acc[4][4][4];
#pragma unroll
    for (int i = 0; i < 4; i++)
#pragma unroll
        for (int j = 0; j < 4; j++)
#pragma unroll
            for (int r = 0; r < 4; r++) acc[i][j][r] = 0.f;

    gemm_issue_stage(A, B, m0, n0, 0, stage_addr[0], srow, quad);
    CP_COMMIT();
    gemm_issue_stage(A, B, m0, n0, 1, stage_addr[1], srow, quad);
    CP_COMMIT();

    for (int kt = 0; kt < NCHUNK; kt++) {
        const int s = kt % 3;
        CP_WAIT1();
        __syncthreads();
        const float* As = smx + s * STAGE_WORDS;
        const float* Bs = As + TILE_WORDS;
        gemm_mma_stage(As, Bs, acc, wm, wn, lane);
        if (kt + 2 < NCHUNK)
            gemm_issue_stage(A, B, m0, n0, kt + 2, stage_addr[(kt + 2) % 3], srow, quad);
        CP_COMMIT();   // always commit (possibly empty) to keep group count fixed
    }
    CP_WAIT0();

    // Epilogue: c0,c1 @ (row, col..col+1); c2,c3 @ (row+8, col..col+1)
    const int qrow = lane >> 2, qcol = (lane & 3) * 2;
#pragma unroll
    for (int jn = 0; jn < 4; jn++) {
        const int colg = n0 + wn * 32 + jn * 8 + qcol;
        const float2 bi = *(const float2*)&bias[colg];
#pragma unroll
        for (int i = 0; i < 4; i++) {
            const int rg = m0 + wm * 64 + i * 16 + qrow;
            float2 v0 = make_float2(acc[i][jn][0] + bi.x, acc[i][jn][1] + bi.y);
            float2 v1 = make_float2(acc[i][jn][2] + bi.x, acc[i][jn][3] + bi.y);
            *(float2*)&C[(size_t)rg * HID + colg] = v0;
            *(float2*)&C[(size_t)(rg + 8) * HID + colg] = v1;
        }
    }
}

__global__ __launch_bounds__(256, 2)
void qkv_kernel(const float* __restrict__ Wdummy)
{
    extern __shared__ float smx[];
    const float* W = g_w[blockIdx.z];
    float* C = (blockIdx.z == 0) ? g_q : (blockIdx.z == 1) ? g_k : g_v;
    gemm128_body(g_x, W, Wdummy + (size_t)blockIdx.z * HID, C, smx);
}

__global__ __launch_bounds__(256, 2)
void out_kernel(const float* __restrict__ bo, float* __restrict__ out)
{
    extern __shared__ float smx[];
    gemm128_body(g_att, g_w[3], bo, out, smx);
}

// ---------------------------------------------------------------------------
// RoPE v2: one thread per (t, pair). Angle computed once, applied to all 32
// heads (32x less transcendental work). Double used only for exp + range
// reduction; __sincosf on the reduced argument (|r| <= pi, abs err ~4e-7).
// ---------------------------------------------------------------------------
__global__ void rope_kernel(const int* __restrict__ pos)
{
    int idx = blockIdx.x * blockDim.x + threadIdx.x;
    if (idx >= TTOK * 64) return;
    const int p = idx & 63, t = idx >> 6;

    const double inv = exp(-(double)p * (9.210340371976184 / 64.0));
    const double f = (double)pos[t] * inv;
    const double n = rint(f * 0.15915494309189535);   // f / (2*pi)
    const float r = (float)(f - n * 6.283185307179586);
    float s, c;
    __sincosf(r, &s, &c);

    size_t base = (size_t)t * HID + p;
#pragma unroll 4
    for (int h = 0; h < NH; h++) {
        const size_t o = base + (size_t)h * HD;
        float q1 = g_q[o], q2 = g_q[o + 64];
        g_q[o]      = q1 * c - q2 * s;
        g_q[o + 64] = q2 * c + q1 * s;
        float k1 = g_k[o], k2 = g_k[o + 64];
        g_k[o]      = k1 * c - k2 * s;
        g_k[o + 64] = k2 * c + k1 * s;
    }
}

// ---------------------------------------------------------------------------
// Flash-style paged causal attention, fp32 (R4-proven). Epilogue now rounds
// g_att to tf32 (numerically identical to R8's staging-time rounding).
// ---------------------------------------------------------------------------
#define AQ 64
#define AK 64
#define VSTR 132
#define ATTN_SMEM_FLOATS (HD * 64 * 2 + 64 * VSTR + 64 * 64)

__global__ __launch_bounds__(256, 1)
void attn_kernel(const float* __restrict__ past_k, const float* __restrict__ past_v,
                 const int* __restrict__ q_start, const int* __restrict__ q_lens,
                 const int* __restrict__ kv_lens, const int* __restrict__ blk_off)
{
    extern __shared__ float sm[];
    float* Qt = sm;
    float* Kt = Qt + HD * 64;
    float* Vs = Kt + HD * 64;
    float* Ps = Vs + 64 * VSTR;

    const int qt = blockIdx.x, h = blockIdx.y, b = blockIdx.z;
    const int qlen = q_lens[b];
    if (qt * AQ >= qlen) return;
    const int kvlen = kv_lens[b];
    const int hist = kvlen - qlen;
    const int qs = q_start[b];
    const int tid = threadIdx.x;
    const int cg = tid & 15, rg = tid >> 4;
    const float scale = 0.088388347648318447f;

#pragma unroll
    for (int l = 0; l < 8; l++) {
        int f4 = tid + l * 256;
        int r = f4 & 63;
        int d = (f4 >> 6) << 2;
        int row = qt * AQ + r; if (row >= qlen) row = qlen - 1;
        float4 v = *(const float4*)(g_q + (size_t)(qs + row) * HID + h * HD + d);
        Qt[(d + 0) * 64 + r] = v.x * scale;
        Qt[(d + 1) * 64 + r] = v.y * scale;
        Qt[(d + 2) * 64 + r] = v.z * scale;
        Qt[(d + 3) * 64 + r] = v.w * scale;
    }

    float m_i[4], l_i[4], o[4][8];
#pragma unroll
    for (int i = 0; i < 4; i++) {
        m_i[i] = -3.0e38f; l_i[i] = 0.f;
#pragma unroll
        for (int j = 0; j < 8; j++) o[i][j] = 0.f;
    }

    int nkv = hist + qt * AQ + AQ; if (nkv > kvlen) nkv = kvlen;
    const int ntiles = (nkv + AK - 1) / AK;

    for (int kt = 0; kt < ntiles; kt++) {
#pragma unroll
        for (int l = 0; l < 8; l++) {
            int f4 = tid + l * 256;
            int c = f4 & 63;
            int d = (f4 >> 6) << 2;
            int j = kt * AK + c;
            float4 kv = make_float4(0.f, 0.f, 0.f, 0.f);
            float4 vv = make_float4(0.f, 0.f, 0.f, 0.f);
            if (j < kvlen) {
                size_t off;
                if (j >= hist) {
                    off = (size_t)(qs + j - hist) * HID + h * HD + d;
                    kv = *(const float4*)(g_k + off);
                    vv = *(const float4*)(g_v + off);
                } else {
                    int blk = blk_off[b * MAXB + (j >> 6)];
                    off = ((size_t)(blk * 64 + (j & 63)) * NH + h) * HD + d;
                    kv = *(const float4*)(past_k + off);
                    vv = *(const float4*)(past_v + off);
                }
            }
            Kt[(d + 0) * 64 + c] = kv.x;
            Kt[(d + 1) * 64 + c] = kv.y;
            Kt[(d + 2) * 64 + c] = kv.z;
            Kt[(d + 3) * 64 + c] = kv.w;
            *(float4*)&Vs[c * VSTR + d] = vv;
        }
        __syncthreads();

        float s[4][4];
#pragma unroll
        for (int i = 0; i < 4; i++)
#pragma unroll
            for (int j = 0; j < 4; j++) s[i][j] = 0.f;

#pragma unroll 8
        for (int k = 0; k < HD; k++) {
            float4 a  = *(const float4*)&Qt[k * 64 + rg * 4];
            float4 bb = *(const float4*)&Kt[k * 64 + cg * 4];
            float ar[4] = {a.x, a.y, a.z, a.w};
            float br[4] = {bb.x, bb.y, bb.z, bb.w};
#pragma unroll
            for (int i = 0; i < 4; i++)
#pragma unroll
                for (int j = 0; j < 4; j++) s[i][j] += ar[i] * br[j];
        }

        const int jb = kt * AK + cg * 4;
        const int ib = qt * AQ + rg * 4;
#pragma unroll
        for (int i = 0; i < 4; i++) {
            const int lim = hist + ib + i;
#pragma unroll
            for (int j = 0; j < 4; j++) {
                int jg = jb + j;
                if (jg > lim || jg >= kvlen) s[i][j] = -1e30f;
            }
            float mt = fmaxf(fmaxf(s[i][0], s[i][1]), fmaxf(s[i][2], s[i][3]));
#pragma unroll
            for (int w2 = 1; w2 < 16; w2 <<= 1)
                mt = fmaxf(mt, __shfl_xor_sync(0xffffffffu, mt, w2));
            float mnew = fmaxf(m_i[i], mt);
            float alpha = __expf(m_i[i] - mnew);
            float p0 = __expf(s[i][0] - mnew);
            float p1 = __expf(s[i][1] - mnew);
            float p2 = __expf(s[i][2] - mnew);
            float p3 = __expf(s[i][3] - mnew);
            float psum = (p0 + p1) + (p2 + p3);
#pragma unroll
            for (int w2 = 1; w2 < 16; w2 <<= 1)
                psum += __shfl_xor_sync(0xffffffffu, psum, w2);
            l_i[i] = l_i[i] * alpha + psum;
            m_i[i] = mnew;
#pragma unroll
            for (int jd = 0; jd < 8; jd++) o[i][jd] *= alpha;
            *(float4*)&Ps[(rg * 4 + i) * 64 + cg * 4] = make_float4(p0, p1, p2, p3);
        }
        __syncthreads();

#pragma unroll 4
        for (int c4i = 0; c4i < AK; c4i += 4) {
            float4 pr[4];
#pragma unroll
            for (int i = 0; i < 4; i++)
                pr[i] = *(const float4*)&Ps[(rg * 4 + i) * 64 + c4i];
#pragma unroll
            for (int cc = 0; cc < 4; cc++) {
                float4 v0 = *(const float4*)&Vs[(c4i + cc) * VSTR + cg * 8];
                float4 v1 = *(const float4*)&Vs[(c4i + cc) * VSTR + cg * 8 + 4];
#pragma unroll
                for (int i = 0; i < 4; i++) {
                    float p = ((const float*)&pr[i])[cc];
                    o[i][0] += p * v0.x; o[i][1] += p * v0.y;
                    o[i][2] += p * v0.z; o[i][3] += p * v0.w;
                    o[i][4] += p * v1.x; o[i][5] += p * v1.y;
                    o[i][6] += p * v1.z; o[i][7] += p * v1.w;
                }
            }
        }
        __syncthreads();
    }

#pragma unroll
    for (int i = 0; i < 4; i++) {
        int row = qt * AQ + rg * 4 + i;
        if (row < qlen) {
            float inv_l = 1.0f / l_i[i];
            size_t base = (size_t)(qs + row) * HID + h * HD + cg * 8;
            *(float4*)&g_att[base] = make_float4(
                to_tf32(o[i][0] * inv_l), to_tf32(o[i][1] * inv_l),
                to_tf32(o[i][2] * inv_l), to_tf32(o[i][3] * inv_l));
            *(float4*)&g_att[base + 4] = make_float4(
                to_tf32(o[i][4] * inv_l), to_tf32(o[i][5] * inv_l),
                to_tf32(o[i][6] * inv_l), to_tf32(o[i][7] * inv_l));
        }
    }
}

// ---------------------------------------------------------------------------
// Bias packing: qkv_kernel indexes biases as one array [3][HID]; we pass bq
// and rely on bq,bk,bv being separate buffers -> pack into a device global.
// ---------------------------------------------------------------------------
__device__ float g_bias[3 * HID];
__global__ void pack_bias(const float* __restrict__ bq, const float* __restrict__ bk,
                          const float* __restrict__ bv)
{
    int i = blockIdx.x * blockDim.x + threadIdx.x;
    if (i < HID) {
        g_bias[i] = bq[i];
        g_bias[HID + i] = bk[i];
        g_bias[2 * HID + i] = bv[i];
    }
}

// ---------------------------------------------------------------------------
extern "C" void kernel_launch(void* const* d_in, const int* in_sizes, int n_in,
                              void* d_out, int out_size)
{
    const float* hidden  = (const float*)d_in[0];
    const int*   pos     = (const int*)d_in[1];
    const int*   q_start = (const int*)d_in[2];
    const int*   q_lens  = (const int*)d_in[3];
    const int*   kv_lens = (const int*)d_in[4];
    const int*   blk_off = (const int*)d_in[5];
    const float* past_k  = (const float*)d_in[6];
    const float* past_v  = (const float*)d_in[7];
    const float* Wq = (const float*)d_in[8];
    const float* bq = (const float*)d_in[9];
    const float* Wk = (const float*)d_in[10];
    const float* bk = (const float*)d_in[11];
    const float* Wv = (const float*)d_in[12];
    const float* bv = (const float*)d_in[13];
    const float* Wo = (const float*)d_in[14];
    const float* bo = (const float*)d_in[15];
    float* out = (float*)d_out;

    (void)cudaFuncSetAttribute(qkv_kernel, cudaFuncAttributeMaxDynamicSharedMemorySize, GEMM_SMEM);
    (void)cudaFuncSetAttribute(out_kernel, cudaFuncAttributeMaxDynamicSharedMemorySize, GEMM_SMEM);

    // 0) tf32 prepass (X + 4 weights) and bias packing
    cvt_prepass<<<dim3(HID * HID / 4 / 256, 5), 256>>>(
        (const float4*)hidden, (const float4*)Wq, (const float4*)Wk,
        (const float4*)Wv, (const float4*)Wo);
    pack_bias<<<(HID + 255) / 256, 256>>>(bq, bk, bv);

    // 1) fused QKV projections (tf32 mma.sync + cp.async pipeline)
    float* g_bias_ptr = nullptr;
    (void)cudaGetSymbolAddress((void**)&g_bias_ptr, g_bias);
    dim3 gq(HID / GN, TTOK / GM, 3);
    qkv_kernel<<<gq, 256, GEMM_SMEM>>>(g_bias_ptr);

    // 2) RoPE on q and k (angle shared across heads)
    rope_kernel<<<(TTOK * 64 + 255) / 256, 256>>>(pos);

    // 3) paged causal flash attention (fp32)
    constexpr int smem = ATTN_SMEM_FLOATS * (int)sizeof(float);
    (void)cudaFuncSetAttribute(attn_kernel, cudaFuncAttributeMaxDynamicSharedMemorySize, smem);
    dim3 ga(16, NH, 4);
    attn_kernel<<<ga, 256, smem>>>(past_k, past_v, q_start, q_lens, kv_lens, blk_off);

    // 4) output projection
    dim3 go(HID / GN, TTOK / GM, 1);
    out_kernel<<<go, 256, GEMM_SMEM>>>(bo, out);
}

// round 10
// speedup vs baseline: 3.1106x; 1.3300x over previous
#include <cuda_runtime.h>
#include <math.h>
#include <stdint.h>

#define TTOK 3072
#define HID  4096
#define NH   32
#define HD   128
#define MAXB 24

// Device-global scratch (no allocations allowed)
__device__ float g_q[TTOK * HID];
__device__ float g_k[TTOK * HID];
__device__ float g_v[TTOK * HID];
__device__ float g_att[TTOK * HID];       // tf32-rounded at production
__device__ float g_x[TTOK * HID];         // tf32-rounded hidden_states
__device__ float g_w[4][HID * HID];       // tf32-rounded Wq,Wk,Wv,Wo

__device__ __forceinline__ float to_tf32(float x) {
    float y;
    asm("cvt.rna.tf32.f32 %0, %1;" : "=f"(y) : "f"(x));
    return y;
}
__device__ __forceinline__ uint32_t smem_u32(const void* p) {
    uint32_t a;
    asm("{ .reg .u64 t; cvta.to.shared.u64 t, %1; cvt.u32.u64 %0, t; }"
        : "=r"(a) : "l"(p));
    return a;
}

#define CP_ASYNC16(dst, src) \
    asm volatile("cp.async.cg.shared.global [%0], [%1], 16;" :: "r"(dst), "l"(src))
#define CP_COMMIT() asm volatile("cp.async.commit_group;" ::: "memory")
#define CP_WAIT1()  asm volatile("cp.async.wait_group 1;"  ::: "memory")
#define CP_WAIT0()  asm volatile("cp.async.wait_group 0;"  ::: "memory")

#define MMA_TF32(acc, a, b) \
    asm volatile("mma.sync.aligned.m16n8k8.row.col.f32.tf32.tf32.f32 " \
        "{%0,%1,%2,%3}, {%4,%5,%6,%7}, {%8,%9}, {%0,%1,%2,%3};" \
        : "+f"((acc)[0]), "+f"((acc)[1]), "+f"((acc)[2]), "+f"((acc)[3]) \
        : "r"((a)[0]), "r"((a)[1]), "r"((a)[2]), "r"((a)[3]), \
          "r"((b)[0]), "r"((b)[1]))

// ===========================================================================
// Prepass: round inputs once to tf32.
// ===========================================================================
__global__ void cvt_prepass(const float4* __restrict__ X,
                            const float4* __restrict__ Wq, const float4* __restrict__ Wk,
                            const float4* __restrict__ Wv, const float4* __restrict__ Wo)
{
    const int which = blockIdx.y;
    const size_t i = (size_t)blockIdx.x * blockDim.x + threadIdx.x;
    const float4* src;
    float4* dst;
    size_t n;
    if (which < 4) {
        src = (which == 0) ? Wq : (which == 1) ? Wk : (which == 2) ? Wv : Wo;
        dst = (float4*)g_w[which];
        n = (size_t)HID * HID / 4;
    } else {
        src = X; dst = (float4*)g_x; n = (size_t)TTOK * HID / 4;
    }
    if (i < n) {
        float4 v = src[i];
        v.x = to_tf32(v.x); v.y = to_tf32(v.y);
        v.z = to_tf32(v.z); v.w = to_tf32(v.w);
        dst[i] = v;
    }
}

// ===========================================================================
// TF32 mma.sync GEMM (R9, unchanged): 128x128 block, cp.async 3-stage.
// ===========================================================================
#define GM 128
#define GN 128
#define GK 32
#define NCHUNK (HID / GK)
#define ASTRIDE 36
#define TILE_WORDS (128 * ASTRIDE)
#define STAGE_WORDS (2 * TILE_WORDS)
#define GEMM_SMEM (3 * STAGE_WORDS * 4)

__device__ __forceinline__ void gemm_issue_stage(
    const float* __restrict__ A, const float* __restrict__ B,
    int m0, int n0, int kt, uint32_t stage_base, int srow, int quad)
{
    const float* ag = A + (size_t)(m0 + srow) * HID + kt * GK + quad * 4;
    const float* bg = B + (size_t)(n0 + srow) * HID + kt * GK + quad * 4;
    const uint32_t off = (uint32_t)(srow * ASTRIDE + quad * 4) * 4;
    const uint32_t as = stage_base + off;
    const uint32_t bs = stage_base + TILE_WORDS * 4 + off;
#pragma unroll
    for (int l = 0; l < 4; l++) {
        CP_ASYNC16(as + l * 32 * ASTRIDE * 4, ag + (size_t)(l * 32) * HID);
        CP_ASYNC16(bs + l * 32 * ASTRIDE * 4, bg + (size_t)(l * 32) * HID);
    }
}

__device__ __forceinline__ void gemm_mma_stage(
    const float* __restrict__ As, const float* __restrict__ Bs,
    float acc[4][4][4], int wm, int wn, int lane)
{
#pragma unroll
    for (int k = 0; k < 4; k++) {
        const int c0 = k * 8 + (lane & 3);
        uint32_t af[4][4];
        uint32_t bf[4][2];
#pragma unroll
        for (int i = 0; i < 4; i++) {
            const int r0 = wm * 64 + i * 16 + (lane >> 2);
            af[i][0] = __float_as_uint(As[r0 * ASTRIDE + c0]);
            af[i][1] = __float_as_uint(As[(r0 + 8) * ASTRIDE + c0]);
            af[i][2] = __float_as_uint(As[r0 * ASTRIDE + c0 + 4]);
            af[i][3] = __float_as_uint(As[(r0 + 8) * ASTRIDE + c0 + 4]);
        }
#pragma unroll
        for (int j = 0; j < 4; j++) {
            const int nn = wn * 32 + j * 8 + (lane >> 2);
            bf[j][0] = __float_as_uint(Bs[nn * ASTRIDE + c0]);
            bf[j][1] = __float_as_uint(Bs[nn * ASTRIDE + c0 + 4]);
        }
#pragma unroll
        for (int i = 0; i < 4; i++)
#pragma unroll
            for (int jn = 0; jn < 4; jn++)
                MMA_TF32(acc[i][jn], af[i], bf[jn]);
    }
}

__device__ __forceinline__ void gemm128_body(
    const float* __restrict__ A, const float* __restrict__ B,
    const float* __restrict__ bias, float* __restrict__ C, float* smx)
{
    const int tid = threadIdx.x;
    const int w = tid >> 5, lane = tid & 31;
    const int wm = w >> 2, wn = w & 3;
    const int m0 = blockIdx.y * GM, n0 = blockIdx.x * GN;
    const int srow = tid >> 3, quad = tid & 7;
    const uint32_t sbase = smem_u32(smx);
    const uint32_t stage_addr[3] = {sbase, sbase + STAGE_WORDS * 4,
                                    sbase + 2 * STAGE_WORDS * 4};

    float acc[4][4][4];
#pragma unroll
    for (int i = 0; i < 4; i++)
#pragma unroll
        for (int j = 0; j < 4; j++)
#pragma unroll
            for (int r = 0; r < 4; r++) acc[i][j][r] = 0.f;

    gemm_issue_stage(A, B, m0, n0, 0, stage_addr[0], srow, quad);
    CP_COMMIT();
    gemm_issue_stage(A, B, m0, n0, 1, stage_addr[1], srow, quad);
    CP_COMMIT();

    for (int kt = 0; kt < NCHUNK; kt++) {
        const int s = kt % 3;
        CP_WAIT1();
        __syncthreads();
        const float* As = smx + s * STAGE_WORDS;
        const float* Bs = As + TILE_WORDS;
        gemm_mma_stage(As, Bs, acc, wm, wn, lane);
        if (kt + 2 < NCHUNK)
            gemm_issue_stage(A, B, m0, n0, kt + 2, stage_addr[(kt + 2) % 3], srow, quad);
        CP_COMMIT();
    }
    CP_WAIT0();

    const int qrow = lane >> 2, qcol = (lane & 3) * 2;
#pragma unroll
    for (int jn = 0; jn < 4; jn++) {
        const int colg = n0 + wn * 32 + jn * 8 + qcol;
        const float2 bi = *(const float2*)&bias[colg];
#pragma unroll
        for (int i = 0; i < 4; i++) {
            const int rg = m0 + wm * 64 + i * 16 + qrow;
            float2 v0 = make_float2(acc[i][jn][0] + bi.x, acc[i][jn][1] + bi.y);
            float2 v1 = make_float2(acc[i][jn][2] + bi.x, acc[i][jn][3] + bi.y);
            *(float2*)&C[(size_t)rg * HID + colg] = v0;
            *(float2*)&C[(size_t)(rg + 8) * HID + colg] = v1;
        }
    }
}

__global__ __launch_bounds__(256, 2)
void qkv_kernel(const float* __restrict__ Wdummy)
{
    extern __shared__ float smx[];
    const float* W = g_w[blockIdx.z];
    float* C = (blockIdx.z == 0) ? g_q : (blockIdx.z == 1) ? g_k : g_v;
    gemm128_body(g_x, W, Wdummy + (size_t)blockIdx.z * HID, C, smx);
}

__global__ __launch_bounds__(256, 2)
void out_kernel(const float* __restrict__ bo, float* __restrict__ out)
{
    extern __shared__ float smx[];
    gemm128_body(g_att, g_w[3], bo, out, smx);
}

// ---------------------------------------------------------------------------
// RoPE (R9, unchanged): one thread per (t, pair), angle shared across heads.
// ---------------------------------------------------------------------------
__global__ void rope_kernel(const int* __restrict__ pos)
{
    int idx = blockIdx.x * blockDim.x + threadIdx.x;
    if (idx >= TTOK * 64) return;
    const int p = idx & 63, t = idx >> 6;

    const double inv = exp(-(double)p * (9.210340371976184 / 64.0));
    const double f = (double)pos[t] * inv;
    const double n = rint(f * 0.15915494309189535);
    const float r = (float)(f - n * 6.283185307179586);
    float s, c;
    __sincosf(r, &s, &c);

    size_t base = (size_t)t * HID + p;
#pragma unroll 4
    for (int h = 0; h < NH; h++) {
        const size_t o = base + (size_t)h * HD;
        float q1 = g_q[o], q2 = g_q[o + 64];
        g_q[o]      = q1 * c - q2 * s;
        g_q[o + 64] = q2 * c + q1 * s;
        float k1 = g_k[o], k2 = g_k[o + 64];
        g_k[o]      = k1 * c - k2 * s;
        g_k[o + 64] = k2 * c + k1 * s;
    }
}

// ===========================================================================
// Attention v2: tensor-core flash attention, 64x64 tiles, 256 threads.
// S = Q K^T via 3xTF32 split (fp32-grade accuracy); PV via 1x tf32.
// Exploits workload alignment: hist, qlen, kvlen all multiples of 64 ->
// every kv tile is uniformly paged-or-packed; only the diagonal tile masks.
// Smem layout (strides chosen so fragment LDS are bank-conflict-free):
//   Qh/Ql/Kh/Kl [64][132], Vt [128][68] (transposed), Ps [64][68], red [4][64]
// ===========================================================================
#define AQ 64
#define AK 64
#define QH_OFF 0
#define QL_OFF 8448
#define KH_OFF 16896
#define KL_OFF 25344
#define VT_OFF 33792
#define PS_OFF 42496
#define RED_OFF 46848
#define ATTN_SMEM ((46848 + 256) * 4)   // 188416 bytes

__global__ __launch_bounds__(256, 1)
void attn_kernel(const float* __restrict__ past_k, const float* __restrict__ past_v,
                 const int* __restrict__ q_start, const int* __restrict__ q_lens,
                 const int* __restrict__ kv_lens, const int* __restrict__ blk_off)
{
    extern __shared__ float sm[];
    float* Qh = sm + QH_OFF;
    float* Ql = sm + QL_OFF;
    float* Kh = sm + KH_OFF;
    float* Kl = sm + KL_OFF;
    float* Vt = sm + VT_OFF;
    float* Ps = sm + PS_OFF;
    float* red = sm + RED_OFF;

    const int qt = blockIdx.x, h = blockIdx.y, b = blockIdx.z;
    const int qlen = q_lens[b];
    if (qt * AQ >= qlen) return;
    const int kvlen = kv_lens[b];
    const int hist = kvlen - qlen;
    const int qs = q_start[b];
    const int tid = threadIdx.x;
    const int w = tid >> 5, lane = tid & 31;
    const int wm = w & 1, wn = w >> 1;       // rows wm*32, cols wn*16 (S)
    const int lr = lane >> 2, lc = lane & 3;
    const float scale = 0.088388347648318447f;

    // ---- Stage Q once (scaled, hi/lo split) ----
#pragma unroll
    for (int l = 0; l < 8; l++) {
        int f4 = tid + l * 256;
        int r = f4 >> 5;
        int c = (f4 & 31) * 4;
        float4 v = *(const float4*)(g_q + (size_t)(qs + qt * AQ + r) * HID + h * HD + c);
        float xv[4] = {v.x * scale, v.y * scale, v.z * scale, v.w * scale};
#pragma unroll
        for (int s = 0; s < 4; s++) {
            float hi = to_tf32(xv[s]);
            Qh[r * 132 + c + s] = hi;
            Ql[r * 132 + c + s] = to_tf32(xv[s] - hi);
        }
    }

    float m_i[2][2], l_i[2][2], acco[2][4][4];
#pragma unroll
    for (int i = 0; i < 2; i++)
#pragma unroll
        for (int hf = 0; hf < 2; hf++) { m_i[i][hf] = -3.0e38f; l_i[i][hf] = 0.f; }
#pragma unroll
    for (int i = 0; i < 2; i++)
#pragma unroll
        for (int j = 0; j < 4; j++)
#pragma unroll
            for (int e = 0; e < 4; e++) acco[i][j][e] = 0.f;

    const int ntiles = hist / AK + qt + 1;   // hist % 64 == 0 for this workload

    for (int kt = 0; kt < ntiles; kt++) {
        // ---- Stage K (hi/lo) and V (transposed) ----
        const bool isnew = (kt * AK >= hist);
        const float* ksrc;
        const float* vsrc;
        int rstride;
        if (isnew) {
            size_t o = (size_t)(qs + kt * AK - hist) * HID + h * HD;
            ksrc = g_k + o; vsrc = g_v + o; rstride = HID;
        } else {
            int blk = blk_off[b * MAXB + kt];
            size_t o = ((size_t)(blk * 64) * NH + h) * HD;
            ksrc = past_k + o; vsrc = past_v + o; rstride = NH * HD;
        }
#pragma unroll
        for (int l = 0; l < 8; l++) {
            int f4 = tid + l * 256;
            int r = f4 >> 5;
            int c = (f4 & 31) * 4;
            float4 v = *(const float4*)(ksrc + (size_t)r * rstride + c);
            float xv[4] = {v.x, v.y, v.z, v.w};
#pragma unroll
            for (int s = 0; s < 4; s++) {
                float hi = to_tf32(xv[s]);
                Kh[r * 132 + c + s] = hi;
                Kl[r * 132 + c + s] = to_tf32(xv[s] - hi);
            }
        }
#pragma unroll
        for (int l = 0; l < 8; l++) {
            int f4 = tid + l * 256;
            int tok = f4 & 63;
            int d4 = (f4 >> 6) * 4;
            float4 v = *(const float4*)(vsrc + (size_t)tok * rstride + d4);
            Vt[(d4 + 0) * 68 + tok] = to_tf32(v.x);
            Vt[(d4 + 1) * 68 + tok] = to_tf32(v.y);
            Vt[(d4 + 2) * 68 + tok] = to_tf32(v.z);
            Vt[(d4 + 3) * 68 + tok] = to_tf32(v.w);
        }
        __syncthreads();

        // ---- S = Q K^T, 3xTF32 ----
        float accs[2][2][4];
#pragma unroll
        for (int i = 0; i < 2; i++)
#pragma unroll
            for (int j = 0; j < 2; j++)
#pragma unroll
                for (int e = 0; e < 4; e++) accs[i][j][e] = 0.f;

#pragma unroll
        for (int ks = 0; ks < 16; ks++) {
            const int cA = ks * 8 + lc;
            uint32_t ah[2][4], al[2][4], bh[2][2], bl[2][2];
#pragma unroll
            for (int i = 0; i < 2; i++) {
                const int r0 = wm * 32 + i * 16 + lr;
                ah[i][0] = __float_as_uint(Qh[r0 * 132 + cA]);
                ah[i][1] = __float_as_uint(Qh[(r0 + 8) * 132 + cA]);
                ah[i][2] = __float_as_uint(Qh[r0 * 132 + cA + 4]);
                ah[i][3] = __float_as_uint(Qh[(r0 + 8) * 132 + cA + 4]);
                al[i][0] = __float_as_uint(Ql[r0 * 132 + cA]);
                al[i][1] = __float_as_uint(Ql[(r0 + 8) * 132 + cA]);
                al[i][2] = __float_as_uint(Ql[r0 * 132 + cA + 4]);
                al[i][3] = __float_as_uint(Ql[(r0 + 8) * 132 + cA + 4]);
            }
#pragma unroll
            for (int j = 0; j < 2; j++) {
                const int n0 = wn * 16 + j * 8 + lr;
                bh[j][0] = __float_as_uint(Kh[n0 * 132 + cA]);
                bh[j][1] = __float_as_uint(Kh[n0 * 132 + cA + 4]);
                bl[j][0] = __float_as_uint(Kl[n0 * 132 + cA]);
                bl[j][1] = __float_as_uint(Kl[n0 * 132 + cA + 4]);
            }
#pragma unroll
            for (int i = 0; i < 2; i++)
#pragma unroll
                for (int j = 0; j < 2; j++) {
                    MMA_TF32(accs[i][j], ah[i], bh[j]);
                    MMA_TF32(accs[i][j], ah[i], bl[j]);
                    MMA_TF32(accs[i][j], al[i], bh[j]);
                }
        }

        // ---- Causal mask (only partially-allowed tiles) ----
        const int lim_off = hist + (qt - kt) * 64;
        if (lim_off < 63) {
#pragma unroll
            for (int i = 0; i < 2; i++)
#pragma unroll
                for (int j = 0; j < 2; j++) {
                    const int r0 = wm * 32 + i * 16 + lr;
                    const int c0 = wn * 16 + j * 8 + 2 * lc;
                    if (c0 > lim_off + r0)     accs[i][j][0] = -1e30f;
                    if (c0 + 1 > lim_off + r0) accs[i][j][1] = -1e30f;
                    if (c0 > lim_off + r0 + 8)     accs[i][j][2] = -1e30f;
                    if (c0 + 1 > lim_off + r0 + 8) accs[i][j][3] = -1e30f;
                }
        }

        // ---- Online softmax: cross-warp row max ----
#pragma unroll
        for (int i = 0; i < 2; i++)
#pragma unroll
            for (int hf = 0; hf < 2; hf++) {
                float v = fmaxf(fmaxf(accs[i][0][2 * hf], accs[i][0][2 * hf + 1]),
                                fmaxf(accs[i][1][2 * hf], accs[i][1][2 * hf + 1]));
                v = fmaxf(v, __shfl_xor_sync(0xffffffffu, v, 1));
                v = fmaxf(v, __shfl_xor_sync(0xffffffffu, v, 2));
                if (lc == 0)
                    red[wn * 64 + wm * 32 + i * 16 + hf * 8 + lr] = v;
            }
        __syncthreads();

        float alpha[2][2];
#pragma unroll
        for (int i = 0; i < 2; i++)
#pragma unroll
            for (int hf = 0; hf < 2; hf++) {
                const int r = wm * 32 + i * 16 + hf * 8 + lr;
                float tm = fmaxf(fmaxf(red[r], red[64 + r]),
                                 fmaxf(red[128 + r], red[192 + r]));
                float mnew = fmaxf(m_i[i][hf], tm);
                alpha[i][hf] = __expf(m_i[i][hf] - mnew);
                m_i[i][hf] = mnew;
            }
        __syncthreads();   // red reuse barrier (max reads done before sum writes)

        // ---- p = exp(s - m); partial sums; P -> smem; O rescale ----
#pragma unroll
        for (int i = 0; i < 2; i++)
#pragma unroll
            for (int j = 0; j < 2; j++)
#pragma unroll
                for (int e = 0; e < 4; e++)
                    accs[i][j][e] = __expf(accs[i][j][e] - m_i[i][e >> 1]);

#pragma unroll
        for (int i = 0; i < 2; i++)
#pragma unroll
            for (int hf = 0; hf < 2; hf++) {
                float ps = (accs[i][0][2 * hf] + accs[i][0][2 * hf + 1]) +
                           (accs[i][1][2 * hf] + accs[i][1][2 * hf + 1]);
                ps += __shfl_xor_sync(0xffffffffu, ps, 1);
                ps += __shfl_xor_sync(0xffffffffu, ps, 2);
                if (lc == 0)
                    red[wn * 64 + wm * 32 + i * 16 + hf * 8 + lr] = ps;
            }
#pragma unroll
        for (int i = 0; i < 2; i++)
#pragma unroll
            for (int j = 0; j < 2; j++) {
                const int r0 = wm * 32 + i * 16 + lr;
                const int cp = wn * 16 + j * 8 + 2 * lc;
                Ps[r0 * 68 + cp]           = to_tf32(accs[i][j][0]);
                Ps[r0 * 68 + cp + 1]       = to_tf32(accs[i][j][1]);
                Ps[(r0 + 8) * 68 + cp]     = to_tf32(accs[i][j][2]);
                Ps[(r0 + 8) * 68 + cp + 1] = to_tf32(accs[i][j][3]);
            }
#pragma unroll
        for (int i = 0; i < 2; i++)
#pragma unroll
            for (int j = 0; j < 4; j++)
#pragma unroll
                for (int e = 0; e < 4; e++)
                    acco[i][j][e] *= alpha[i][e >> 1];
        __syncthreads();

#pragma unroll
        for (int i = 0; i < 2; i++)
#pragma unroll
            for (int hf = 0; hf < 2; hf++) {
                const int r = wm * 32 + i * 16 + hf * 8 + lr;
                l_i[i][hf] = l_i[i][hf] * alpha[i][hf] +
                             ((red[r] + red[64 + r]) + (red[128 + r] + red[192 + r]));
            }

        // ---- O += P V (1x tf32) ----
#pragma unroll
        for (int ks = 0; ks < 8; ks++) {
            const int kk = ks * 8 + lc;
            uint32_t af[2][4], bf[4][2];
#pragma unroll
            for (int i = 0; i < 2; i++) {
                const int r0 = wm * 32 + i * 16 + lr;
                af[i][0] = __float_as_uint(Ps[r0 * 68 + kk]);
                af[i][1] = __float_as_uint(Ps[(r0 + 8) * 68 + kk]);
                af[i][2] = __float_as_uint(Ps[r0 * 68 + kk + 4]);
                af[i][3] = __float_as_uint(Ps[(r0 + 8) * 68 + kk + 4]);
            }
#pragma unroll
            for (int j = 0; j < 4; j++) {
                const int n0 = wn * 32 + j * 8 + lr;   // d index
                bf[j][0] = __float_as_uint(Vt[n0 * 68 + kk]);
                bf[j][1] = __float_as_uint(Vt[n0 * 68 + kk + 4]);
            }
#pragma unroll
            for (int i = 0; i < 2; i++)
#pragma unroll
                for (int j = 0; j < 4; j++)
                    MMA_TF32(acco[i][j], af[i], bf[j]);
        }
        __syncthreads();   // PV reads done before next staging overwrites
    }

    // ---- Epilogue: normalize, tf32-round, store packed ----
    float inv_l[2][2];
#pragma unroll
    for (int i = 0; i < 2; i++)
#pragma unroll
        for (int hf = 0; hf < 2; hf++) inv_l[i][hf] = 1.0f / l_i[i][hf];

#pragma unroll
    for (int i = 0; i < 2; i++)
#pragma unroll
        for (int j = 0; j < 4; j++) {
            const int r0 = qs + qt * AQ + wm * 32 + i * 16 + lr;
            const int col = h * HD + wn * 32 + j * 8 + 2 * lc;
            float2 v0 = make_float2(to_tf32(acco[i][j][0] * inv_l[i][0]),
                                    to_tf32(acco[i][j][1] * inv_l[i][0]));
            float2 v1 = make_float2(to_tf32(acco[i][j][2] * inv_l[i][1]),
                                    to_tf32(acco[i][j][3] * inv_l[i][1]));
            *(float2*)&g_att[(size_t)r0 * HID + col] = v0;
            *(float2*)&g_att[(size_t)(r0 + 8) * HID + col] = v1;
        }
}

// ---------------------------------------------------------------------------
__device__ float g_bias[3 * HID];
__global__ void pack_bias(const float* __restrict__ bq, const float* __restrict__ bk,
                          const float* __restrict__ bv)
{
    int i = blockIdx.x * blockDim.x + threadIdx.x;
    if (i < HID) {
        g_bias[i] = bq[i];
        g_bias[HID + i] = bk[i];
        g_bias[2 * HID + i] = bv[i];
    }
}

// ---------------------------------------------------------------------------
extern "C" void kernel_launch(void* const* d_in, const int* in_sizes, int n_in,
                              void* d_out, int out_size)
{
    const float* hidden  = (const float*)d_in[0];
    const int*   pos     = (const int*)d_in[1];
    const int*   q_start = (const int*)d_in[2];
    const int*   q_lens  = (const int*)d_in[3];
    const int*   kv_lens = (const int*)d_in[4];
    const int*   blk_off = (const int*)d_in[5];
    const float* past_k  = (const float*)d_in[6];
    const float* past_v  = (const float*)d_in[7];
    const float* Wq = (const float*)d_in[8];
    const float* bq = (const float*)d_in[9];
    const float* Wk = (const float*)d_in[10];
    const float* bk = (const float*)d_in[11];
    const float* Wv = (const float*)d_in[12];
    const float* bv = (const float*)d_in[13];
    const float* Wo = (const float*)d_in[14];
    const float* bo = (const float*)d_in[15];
    float* out = (float*)d_out;

    (void)cudaFuncSetAttribute(qkv_kernel, cudaFuncAttributeMaxDynamicSharedMemorySize, GEMM_SMEM);
    (void)cudaFuncSetAttribute(out_kernel, cudaFuncAttributeMaxDynamicSharedMemorySize, GEMM_SMEM);
    (void)cudaFuncSetAttribute(attn_kernel, cudaFuncAttributeMaxDynamicSharedMemorySize, ATTN_SMEM);

    // 0) tf32 prepass + bias packing
    cvt_prepass<<<dim3(HID * HID / 4 / 256, 5), 256>>>(
        (const float4*)hidden, (const float4*)Wq, (const float4*)Wk,
        (const float4*)Wv, (const float4*)Wo);
    pack_bias<<<(HID + 255) / 256, 256>>>(bq, bk, bv);

    // 1) fused QKV projections
    float* g_bias_ptr = nullptr;
    (void)cudaGetSymbolAddress((void**)&g_bias_ptr, g_bias);
    dim3 gq(HID / GN, TTOK / GM, 3);
    qkv_kernel<<<gq, 256, GEMM_SMEM>>>(g_bias_ptr);

    // 2) RoPE
    rope_kernel<<<(TTOK * 64 + 255) / 256, 256>>>(pos);

    // 3) tensor-core paged causal flash attention
    dim3 ga(16, NH, 4);
    attn_kernel<<<ga, 256, ATTN_SMEM>>>(past_k, past_v, q_start, q_lens, kv_lens, blk_off);

    // 4) output projection
    dim3 go(HID / GN, TTOK / GM, 1);
    out_kernel<<<go, 256, GEMM_SMEM>>>(bo, out);
}

// round 11
// speedup vs baseline: 3.2140x; 1.0332x over previous
#include <cuda_runtime.h>
#include <math.h>
#include <stdint.h>

#define TTOK 3072
#define HID  4096
#define NH   32
#define HD   128
#define MAXB 24

// Device-global scratch (no allocations allowed)
__device__ float g_q[TTOK * HID];
__device__ float g_k[TTOK * HID];
__device__ float g_v[TTOK * HID];
__device__ float g_att[TTOK * HID];       // tf32-rounded at production
__device__ float g_x[TTOK * HID];         // tf32-rounded hidden_states
__device__ float g_w[4][HID * HID];       // tf32-rounded Wq,Wk,Wv,Wo

__device__ __forceinline__ float to_tf32(float x) {
    float y;
    asm("cvt.rna.tf32.f32 %0, %1;" : "=f"(y) : "f"(x));
    return y;
}
__device__ __forceinline__ uint32_t smem_u32(const void* p) {
    uint32_t a;
    asm("{ .reg .u64 t; cvta.to.shared.u64 t, %1; cvt.u32.u64 %0, t; }"
        : "=r"(a) : "l"(p));
    return a;
}

#define CP_ASYNC16(dst, src) \
    asm volatile("cp.async.cg.shared.global [%0], [%1], 16;" :: "r"(dst), "l"(src))
#define CP_COMMIT() asm volatile("cp.async.commit_group;" ::: "memory")
#define CP_WAIT1()  asm volatile("cp.async.wait_group 1;"  ::: "memory")
#define CP_WAIT0()  asm volatile("cp.async.wait_group 0;"  ::: "memory")

#define MMA_TF32(acc, a, b) \
    asm volatile("mma.sync.aligned.m16n8k8.row.col.f32.tf32.tf32.f32 " \
        "{%0,%1,%2,%3}, {%4,%5,%6,%7}, {%8,%9}, {%0,%1,%2,%3};" \
        : "+f"((acc)[0]), "+f"((acc)[1]), "+f"((acc)[2]), "+f"((acc)[3]) \
        : "r"((a)[0]), "r"((a)[1]), "r"((a)[2]), "r"((a)[3]), \
          "r"((b)[0]), "r"((b)[1]))

// ===========================================================================
// Prepass: round inputs once to tf32.
// ===========================================================================
__global__ void cvt_prepass(const float4* __restrict__ X,
                            const float4* __restrict__ Wq, const float4* __restrict__ Wk,
                            const float4* __restrict__ Wv, const float4* __restrict__ Wo)
{
    const int which = blockIdx.y;
    const size_t i = (size_t)blockIdx.x * blockDim.x + threadIdx.x;
    const float4* src;
    float4* dst;
    size_t n;
    if (which < 4) {
        src = (which == 0) ? Wq : (which == 1) ? Wk : (which == 2) ? Wv : Wo;
        dst = (float4*)g_w[which];
        n = (size_t)HID * HID / 4;
    } else {
        src = X; dst = (float4*)g_x; n = (size_t)TTOK * HID / 4;
    }
    if (i < n) {
        float4 v = src[i];
        v.x = to_tf32(v.x); v.y = to_tf32(v.y);
        v.z = to_tf32(v.z); v.w = to_tf32(v.w);
        dst[i] = v;
    }
}

// ===========================================================================
// TF32 mma.sync GEMM v3: 256x128 block tile, BK=32, 512 threads (16 warps,
// 4x4), warp tile 64x32 (same warp-level code as the validated R9 kernel).
// cp.async 3-stage; smem padded [rows][36]. -25% L2 traffic vs 128x128.
// ===========================================================================
#define GM 256
#define GN 128
#define GK 32
#define NCHUNK (HID / GK)
#define ASTRIDE 36
#define A_WORDS (256 * ASTRIDE)
#define B_WORDS (128 * ASTRIDE)
#define STAGE_WORDS (A_WORDS + B_WORDS)          // 13824 floats
#define GEMM_SMEM (3 * STAGE_WORDS * 4)          // 165888 bytes

__device__ __forceinline__ void gemm_issue_stage(
    const float* __restrict__ A, const float* __restrict__ B,
    int m0, int n0, int kt, uint32_t stage_base, int srow, int quad)
{
    const float* ag = A + (size_t)(m0 + srow) * HID + kt * GK + quad * 4;
    const float* bg = B + (size_t)(n0 + srow) * HID + kt * GK + quad * 4;
    const uint32_t off = (uint32_t)(srow * ASTRIDE + quad * 4) * 4;
    const uint32_t as = stage_base + off;
    const uint32_t bs = stage_base + A_WORDS * 4 + off;
#pragma unroll
    for (int l = 0; l < 4; l++)
        CP_ASYNC16(as + l * 64 * ASTRIDE * 4, ag + (size_t)(l * 64) * HID);
#pragma unroll
    for (int l = 0; l < 2; l++)
        CP_ASYNC16(bs + l * 64 * ASTRIDE * 4, bg + (size_t)(l * 64) * HID);
}

__device__ __forceinline__ void gemm_mma_stage(
    const float* __restrict__ As, const float* __restrict__ Bs,
    float acc[4][4][4], int wm, int wn, int lane)
{
#pragma unroll
    for (int k = 0; k < 4; k++) {
        const int c0 = k * 8 + (lane & 3);
        uint32_t af[4][4];
        uint32_t bf[4][2];
#pragma unroll
        for (int i = 0; i < 4; i++) {
            const int r0 = wm * 64 + i * 16 + (lane >> 2);
            af[i][0] = __float_as_uint(As[r0 * ASTRIDE + c0]);
            af[i][1] = __float_as_uint(As[(r0 + 8) * ASTRIDE + c0]);
            af[i][2] = __float_as_uint(As[r0 * ASTRIDE + c0 + 4]);
            af[i][3] = __float_as_uint(As[(r0 + 8) * ASTRIDE + c0 + 4]);
        }
#pragma unroll
        for (int j = 0; j < 4; j++) {
            const int nn = wn * 32 + j * 8 + (lane >> 2);
            bf[j][0] = __float_as_uint(Bs[nn * ASTRIDE + c0]);
            bf[j][1] = __float_as_uint(Bs[nn * ASTRIDE + c0 + 4]);
        }
#pragma unroll
        for (int i = 0; i < 4; i++)
#pragma unroll
            for (int jn = 0; jn < 4; jn++)
                MMA_TF32(acc[i][jn], af[i], bf[jn]);
    }
}

__device__ __forceinline__ void gemm_body(
    const float* __restrict__ A, const float* __restrict__ B,
    const float* __restrict__ bias, float* __restrict__ C, float* smx)
{
    const int tid = threadIdx.x;
    const int w = tid >> 5, lane = tid & 31;
    const int wm = w >> 2, wn = w & 3;           // wm 0..3 (64 rows), wn 0..3 (32 cols)
    const int m0 = blockIdx.y * GM, n0 = blockIdx.x * GN;
    const int srow = tid >> 3, quad = tid & 7;   // srow 0..63
    const uint32_t sbase = smem_u32(smx);
    const uint32_t stage_addr[3] = {sbase, sbase + STAGE_WORDS * 4,
                                    sbase + 2 * STAGE_WORDS * 4};

    float acc[4][4][4];
#pragma unroll
    for (int i = 0; i < 4; i++)
#pragma unroll
        for (int j = 0; j < 4; j++)
#pragma unroll
            for (int r = 0; r < 4; r++) acc[i][j][r] = 0.f;

    gemm_issue_stage(A, B, m0, n0, 0, stage_addr[0], srow, quad);
    CP_COMMIT();
    gemm_issue_stage(A, B, m0, n0, 1, stage_addr[1], srow, quad);
    CP_COMMIT();

    for (int kt = 0; kt < NCHUNK; kt++) {
        const int s = kt % 3;
        CP_WAIT1();
        __syncthreads();
        const float* As = smx + s * STAGE_WORDS;
        const float* Bs = As + A_WORDS;
        gemm_mma_stage(As, Bs, acc, wm, wn, lane);
        if (kt + 2 < NCHUNK)
            gemm_issue_stage(A, B, m0, n0, kt + 2, stage_addr[(kt + 2) % 3], srow, quad);
        CP_COMMIT();
    }
    CP_WAIT0();

    const int qrow = lane >> 2, qcol = (lane & 3) * 2;
#pragma unroll
    for (int jn = 0; jn < 4; jn++) {
        const int colg = n0 + wn * 32 + jn * 8 + qcol;
        const float2 bi = *(const float2*)&bias[colg];
#pragma unroll
        for (int i = 0; i < 4; i++) {
            const int rg = m0 + wm * 64 + i * 16 + qrow;
            float2 v0 = make_float2(acc[i][jn][0] + bi.x, acc[i][jn][1] + bi.y);
            float2 v1 = make_float2(acc[i][jn][2] + bi.x, acc[i][jn][3] + bi.y);
            *(float2*)&C[(size_t)rg * HID + colg] = v0;
            *(float2*)&C[(size_t)(rg + 8) * HID + colg] = v1;
        }
    }
}

__global__ __launch_bounds__(512, 1)
void qkv_kernel(const float* __restrict__ biasq)
{
    extern __shared__ float smx[];
    const float* W = g_w[blockIdx.z];
    float* C = (blockIdx.z == 0) ? g_q : (blockIdx.z == 1) ? g_k : g_v;
    gemm_body(g_x, W, biasq + (size_t)blockIdx.z * HID, C, smx);
}

__global__ __launch_bounds__(512, 1)
void out_kernel(const float* __restrict__ bo, float* __restrict__ out)
{
    extern __shared__ float smx[];
    gemm_body(g_att, g_w[3], bo, out, smx);
}

// ---------------------------------------------------------------------------
// RoPE (unchanged): one thread per (t, pair), angle shared across heads.
// ---------------------------------------------------------------------------
__global__ void rope_kernel(const int* __restrict__ pos)
{
    int idx = blockIdx.x * blockDim.x + threadIdx.x;
    if (idx >= TTOK * 64) return;
    const int p = idx & 63, t = idx >> 6;

    const double inv = exp(-(double)p * (9.210340371976184 / 64.0));
    const double f = (double)pos[t] * inv;
    const double n = rint(f * 0.15915494309189535);
    const float r = (float)(f - n * 6.283185307179586);
    float s, c;
    __sincosf(r, &s, &c);

    size_t base = (size_t)t * HID + p;
#pragma unroll 4
    for (int h = 0; h < NH; h++) {
        const size_t o = base + (size_t)h * HD;
        float q1 = g_q[o], q2 = g_q[o + 64];
        g_q[o]      = q1 * c - q2 * s;
        g_q[o + 64] = q2 * c + q1 * s;
        float k1 = g_k[o], k2 = g_k[o + 64];
        g_k[o]      = k1 * c - k2 * s;
        g_k[o + 64] = k2 * c + k1 * s;
    }
}

// ===========================================================================
// Attention v3: tensor-core flash attention with cp.async raw K/V staging.
// S = Q K^T via 3xTF32 (Q hi/lo in smem; K hi/lo split in REGISTERS at
// fragment load from raw fp32 smem). PV via 1x tf32 with V read raw
// (tok-major, stride 136 words -> conflict-free fragment LDS).
// K/V single-buffered; K(t+1) prefetched during PV(t), V(t+1) during S(t+1).
// ===========================================================================
#define AQ 64
#define AK 64
#define QH_OFF 0
#define QL_OFF 8448
#define KR_OFF 16896
#define VR_OFF 25344
#define PS_OFF 34048
#define RED_OFF 38400
#define ATTN_SMEM ((38400 + 256) * 4)   // 154624 bytes

__global__ __launch_bounds__(256, 1)
void attn_kernel(const float* __restrict__ past_k, const float* __restrict__ past_v,
                 const int* __restrict__ q_start, const int* __restrict__ q_lens,
                 const int* __restrict__ kv_lens, const int* __restrict__ blk_off)
{
    extern __shared__ float sm[];
    float* Qh = sm + QH_OFF;          // [64][132]
    float* Ql = sm + QL_OFF;          // [64][132]
    float* Kr = sm + KR_OFF;          // [64][132] raw fp32
    float* Vr = sm + VR_OFF;          // [64][136] raw fp32
    float* Ps = sm + PS_OFF;          // [64][68]
    float* red = sm + RED_OFF;        // [4][64]

    const int qt = blockIdx.x, h = blockIdx.y, b = blockIdx.z;
    const int qlen = q_lens[b];
    if (qt * AQ >= qlen) return;
    const int kvlen = kv_lens[b];
    const int hist = kvlen - qlen;
    const int qs = q_start[b];
    const int tid = threadIdx.x;
    const int w = tid >> 5, lane = tid & 31;
    const int wm = w & 1, wn = w >> 1;
    const int lr = lane >> 2, lc = lane & 3;
    const float scale = 0.088388347648318447f;
    const uint32_t sbase = smem_u32(sm);
    const uint32_t kr_base = sbase + KR_OFF * 4;
    const uint32_t vr_base = sbase + VR_OFF * 4;

    // KV tile source resolver (hist % 64 == 0 for this workload)
    const int ntiles = hist / AK + qt + 1;
    auto kv_src = [&](int kt, const float*& ks, const float*& vs, int& rstr) {
        if (kt * AK >= hist) {
            size_t o = (size_t)(qs + kt * AK - hist) * HID + h * HD;
            ks = g_k + o; vs = g_v + o; rstr = HID;
        } else {
            int blk = blk_off[b * MAXB + kt];
            size_t o = ((size_t)(blk * 64) * NH + h) * HD;
            ks = past_k + o; vs = past_v + o; rstr = NH * HD;
        }
    };
    auto issue_K = [&](int kt) {
        const float* ks; const float* vs; int rstr;
        kv_src(kt, ks, vs, rstr);
#pragma unroll
        for (int l = 0; l < 8; l++) {
            int f4 = tid + l * 256;
            int r = f4 >> 5, c = f4 & 31;
            CP_ASYNC16(kr_base + (uint32_t)(r * 132 + c * 4) * 4,
                       ks + (size_t)r * rstr + c * 4);
        }
    };
    auto issue_V = [&](int kt) {
        const float* ks; const float* vs; int rstr;
        kv_src(kt, ks, vs, rstr);
#pragma unroll
        for (int l = 0; l < 8; l++) {
            int f4 = tid + l * 256;
            int r = f4 >> 5, c = f4 & 31;
            CP_ASYNC16(vr_base + (uint32_t)(r * 136 + c * 4) * 4,
                       vs + (size_t)r * rstr + c * 4);
        }
    };

    // ---- Stage Q once (scaled, hi/lo split) ----
#pragma unroll
    for (int l = 0; l < 8; l++) {
        int f4 = tid + l * 256;
        int r = f4 >> 5;
        int c = (f4 & 31) * 4;
        float4 v = *(const float4*)(g_q + (size_t)(qs + qt * AQ + r) * HID + h * HD + c);
        float xv[4] = {v.x * scale, v.y * scale, v.z * scale, v.w * scale};
#pragma unroll
        for (int s = 0; s < 4; s++) {
            float hi = to_tf32(xv[s]);
            Qh[r * 132 + c + s] = hi;
            Ql[r * 132 + c + s] = to_tf32(xv[s] - hi);
        }
    }
    issue_K(0); CP_COMMIT();
    issue_V(0); CP_COMMIT();

    float m_i[2][2], l_i[2][2], acco[2][4][4];
#pragma unroll
    for (int i = 0; i < 2; i++)
#pragma unroll
        for (int hf = 0; hf < 2; hf++) { m_i[i][hf] = -3.0e38f; l_i[i][hf] = 0.f; }
#pragma unroll
    for (int i = 0; i < 2; i++)
#pragma unroll
        for (int j = 0; j < 4; j++)
#pragma unroll
            for (int e = 0; e < 4; e++) acco[i][j][e] = 0.f;

    for (int kt = 0; kt < ntiles; kt++) {
        CP_WAIT1();
        __syncthreads();   // K(kt) + Q visible

        // ---- S = Q K^T, 3xTF32 (K split in regs) ----
        float accs[2][2][4];
#pragma unroll
        for (int i = 0; i < 2; i++)
#pragma unroll
            for (int j = 0; j < 2; j++)
#pragma unroll
                for (int e = 0; e < 4; e++) accs[i][j][e] = 0.f;

#pragma unroll
        for (int ks = 0; ks < 16; ks++) {
            const int cA = ks * 8 + lc;
            uint32_t ah[2][4], al[2][4], bh[2][2], bl[2][2];
#pragma unroll
            for (int i = 0; i < 2; i++) {
                const int r0 = wm * 32 + i * 16 + lr;
                ah[i][0] = __float_as_uint(Qh[r0 * 132 + cA]);
                ah[i][1] = __float_as_uint(Qh[(r0 + 8) * 132 + cA]);
                ah[i][2] = __float_as_uint(Qh[r0 * 132 + cA + 4]);
                ah[i][3] = __float_as_uint(Qh[(r0 + 8) * 132 + cA + 4]);
                al[i][0] = __float_as_uint(Ql[r0 * 132 + cA]);
                al[i][1] = __float_as_uint(Ql[(r0 + 8) * 132 + cA]);
                al[i][2] = __float_as_uint(Ql[r0 * 132 + cA + 4]);
                al[i][3] = __float_as_uint(Ql[(r0 + 8) * 132 + cA + 4]);
            }
#pragma unroll
            for (int j = 0; j < 2; j++) {
                const int n0 = wn * 16 + j * 8 + lr;
                float r0v = Kr[n0 * 132 + cA];
                float r1v = Kr[n0 * 132 + cA + 4];
                float h0 = to_tf32(r0v), h1 = to_tf32(r1v);
                bh[j][0] = __float_as_uint(h0);
                bh[j][1] = __float_as_uint(h1);
                bl[j][0] = __float_as_uint(to_tf32(r0v - h0));
                bl[j][1] = __float_as_uint(to_tf32(r1v - h1));
            }
#pragma unroll
            for (int i = 0; i < 2; i++)
#pragma unroll
                for (int j = 0; j < 2; j++) {
                    MMA_TF32(accs[i][j], ah[i], bh[j]);
                    MMA_TF32(accs[i][j], ah[i], bl[j]);
                    MMA_TF32(accs[i][j], al[i], bh[j]);
                }
        }

        // ---- Causal mask ----
        const int lim_off = hist + (qt - kt) * 64;
        if (lim_off < 63) {
#pragma unroll
            for (int i = 0; i < 2; i++)
#pragma unroll
                for (int j = 0; j < 2; j++) {
                    const int r0 = wm * 32 + i * 16 + lr;
                    const int c0 = wn * 16 + j * 8 + 2 * lc;
                    if (c0 > lim_off + r0)     accs[i][j][0] = -1e30f;
                    if (c0 + 1 > lim_off + r0) accs[i][j][1] = -1e30f;
                    if (c0 > lim_off + r0 + 8)     accs[i][j][2] = -1e30f;
                    if (c0 + 1 > lim_off + r0 + 8) accs[i][j][3] = -1e30f;
                }
        }

        // ---- Online softmax: cross-warp row max ----
#pragma unroll
        for (int i = 0; i < 2; i++)
#pragma unroll
            for (int hf = 0; hf < 2; hf++) {
                float v = fmaxf(fmaxf(accs[i][0][2 * hf], accs[i][0][2 * hf + 1]),
                                fmaxf(accs[i][1][2 * hf], accs[i][1][2 * hf + 1]));
                v = fmaxf(v, __shfl_xor_sync(0xffffffffu, v, 1));
                v = fmaxf(v, __shfl_xor_sync(0xffffffffu, v, 2));
                if (lc == 0)
                    red[wn * 64 + wm * 32 + i * 16 + hf * 8 + lr] = v;
            }
        __syncthreads();

        float alpha[2][2];
#pragma unroll
        for (int i = 0; i < 2; i++)
#pragma unroll
            for (int hf = 0; hf < 2; hf++) {
                const int r = wm * 32 + i * 16 + hf * 8 + lr;
                float tm = fmaxf(fmaxf(red[r], red[64 + r]),
                                 fmaxf(red[128 + r], red[192 + r]));
                float mnew = fmaxf(m_i[i][hf], tm);
                alpha[i][hf] = __expf(m_i[i][hf] - mnew);
                m_i[i][hf] = mnew;
            }
        __syncthreads();   // red reuse; all Kr reads complete -> prefetch K(t+1)
        if (kt + 1 < ntiles) issue_K(kt + 1);
        CP_COMMIT();

        // ---- p = exp; partial sums; P -> smem ----
#pragma unroll
        for (int i = 0; i < 2; i++)
#pragma unroll
            for (int j = 0; j < 2; j++)
#pragma unroll
                for (int e = 0; e < 4; e++)
                    accs[i][j][e] = __expf(accs[i][j][e] - m_i[i][e >> 1]);

#pragma unroll
        for (int i = 0; i < 2; i++)
#pragma unroll
            for (int hf = 0; hf < 2; hf++) {
                float ps = (accs[i][0][2 * hf] + accs[i][0][2 * hf + 1]) +
                           (accs[i][1][2 * hf] + accs[i][1][2 * hf + 1]);
                ps += __shfl_xor_sync(0xffffffffu, ps, 1);
                ps += __shfl_xor_sync(0xffffffffu, ps, 2);
                if (lc == 0)
                    red[wn * 64 + wm * 32 + i * 16 + hf * 8 + lr] = ps;
            }
#pragma unroll
        for (int i = 0; i < 2; i++)
#pragma unroll
            for (int j = 0; j < 2; j++) {
                const int r0 = wm * 32 + i * 16 + lr;
                const int cp = wn * 16 + j * 8 + 2 * lc;
                Ps[r0 * 68 + cp]           = to_tf32(accs[i][j][0]);
                Ps[r0 * 68 + cp + 1]       = to_tf32(accs[i][j][1]);
                Ps[(r0 + 8) * 68 + cp]     = to_tf32(accs[i][j][2]);
                Ps[(r0 + 8) * 68 + cp + 1] = to_tf32(accs[i][j][3]);
            }
        CP_WAIT1();        // V(kt) complete (K(t+1) may remain pending)
        __syncthreads();   // V, Ps, red sums visible

#pragma unroll
        for (int i = 0; i < 2; i++)
#pragma unroll
            for (int hf = 0; hf < 2; hf++) {
                const int r = wm * 32 + i * 16 + hf * 8 + lr;
                l_i[i][hf] = l_i[i][hf] * alpha[i][hf] +
                             ((red[r] + red[64 + r]) + (red[128 + r] + red[192 + r]));
            }
#pragma unroll
        for (int i = 0; i < 2; i++)
#pragma unroll
            for (int j = 0; j < 4; j++)
#pragma unroll
                for (int e = 0; e < 4; e++)
                    acco[i][j][e] *= alpha[i][e >> 1];

        // ---- O += P V (1x tf32, V read raw tok-major) ----
#pragma unroll
        for (int ks = 0; ks < 8; ks++) {
            const int kk = ks * 8 + lc;
            uint32_t af[2][4], bf[4][2];
#pragma unroll
            for (int i = 0; i < 2; i++) {
                const int r0 = wm * 32 + i * 16 + lr;
                af[i][0] = __float_as_uint(Ps[r0 * 68 + kk]);
                af[i][1] = __float_as_uint(Ps[(r0 + 8) * 68 + kk]);
                af[i][2] = __float_as_uint(Ps[r0 * 68 + kk + 4]);
                af[i][3] = __float_as_uint(Ps[(r0 + 8) * 68 + kk + 4]);
            }
#pragma unroll
            for (int j = 0; j < 4; j++) {
                const int n0 = wn * 32 + j * 8 + lr;   // d index
                bf[j][0] = __float_as_uint(to_tf32(Vr[kk * 136 + n0]));
                bf[j][1] = __float_as_uint(to_tf32(Vr[(kk + 4) * 136 + n0]));
            }
#pragma unroll
            for (int i = 0; i < 2; i++)
#pragma unroll
                for (int j = 0; j < 4; j++)
                    MMA_TF32(acco[i][j], af[i], bf[j]);
        }
        __syncthreads();   // Vr/Ps free -> prefetch V(t+1)
        if (kt + 1 < ntiles) issue_V(kt + 1);
        CP_COMMIT();
    }

    // ---- Epilogue ----
    float inv_l[2][2];
#pragma unroll
    for (int i = 0; i < 2; i++)
#pragma unroll
        for (int hf = 0; hf < 2; hf++) inv_l[i][hf] = 1.0f / l_i[i][hf];

#pragma unroll
    for (int i = 0; i < 2; i++)
#pragma unroll
        for (int j = 0; j < 4; j++) {
            const int r0 = qs + qt * AQ + wm * 32 + i * 16 + lr;
            const int col = h * HD + wn * 32 + j * 8 + 2 * lc;
            float2 v0 = make_float2(to_tf32(acco[i][j][0] * inv_l[i][0]),
                                    to_tf32(acco[i][j][1] * inv_l[i][0]));
            float2 v1 = make_float2(to_tf32(acco[i][j][2] * inv_l[i][1]),
                                    to_tf32(acco[i][j][3] * inv_l[i][1]));
            *(float2*)&g_att[(size_t)r0 * HID + col] = v0;
            *(float2*)&g_att[(size_t)(r0 + 8) * HID + col] = v1;
        }
}

// ---------------------------------------------------------------------------
__device__ float g_bias[3 * HID];
__global__ void pack_bias(const float* __restrict__ bq, const float* __restrict__ bk,
                          const float* __restrict__ bv)
{
    int i = blockIdx.x * blockDim.x + threadIdx.x;
    if (i < HID) {
        g_bias[i] = bq[i];
        g_bias[HID + i] = bk[i];
        g_bias[2 * HID + i] = bv[i];
    }
}

// ---------------------------------------------------------------------------
extern "C" void kernel_launch(void* const* d_in, const int* in_sizes, int n_in,
                              void* d_out, int out_size)
{
    const float* hidden  = (const float*)d_in[0];
    const int*   pos     = (const int*)d_in[1];
    const int*   q_start = (const int*)d_in[2];
    const int*   q_lens  = (const int*)d_in[3];
    const int*   kv_lens = (const int*)d_in[4];
    const int*   blk_off = (const int*)d_in[5];
    const float* past_k  = (const float*)d_in[6];
    const float* past_v  = (const float*)d_in[7];
    const float* Wq = (const float*)d_in[8];
    const float* bq = (const float*)d_in[9];
    const float* Wk = (const float*)d_in[10];
    const float* bk = (const float*)d_in[11];
    const float* Wv = (const float*)d_in[12];
    const float* bv = (const float*)d_in[13];
    const float* Wo = (const float*)d_in[14];
    const float* bo = (const float*)d_in[15];
    float* out = (float*)d_out;

    (void)cudaFuncSetAttribute(qkv_kernel, cudaFuncAttributeMaxDynamicSharedMemorySize, GEMM_SMEM);
    (void)cudaFuncSetAttribute(out_kernel, cudaFuncAttributeMaxDynamicSharedMemorySize, GEMM_SMEM);
    (void)cudaFuncSetAttribute(attn_kernel, cudaFuncAttributeMaxDynamicSharedMemorySize, ATTN_SMEM);

    // 0) tf32 prepass + bias packing
    cvt_prepass<<<dim3(HID * HID / 4 / 256, 5), 256>>>(
        (const float4*)hidden, (const float4*)Wq, (const float4*)Wk,
        (const float4*)Wv, (const float4*)Wo);
    pack_bias<<<(HID + 255) / 256, 256>>>(bq, bk, bv);

    // 1) fused QKV projections (256x128 tiles)
    float* g_bias_ptr = nullptr;
    (void)cudaGetSymbolAddress((void**)&g_bias_ptr, g_bias);
    dim3 gq(HID / GN, TTOK / GM, 3);
    qkv_kernel<<<gq, 512, GEMM_SMEM>>>(g_bias_ptr);

    // 2) RoPE
    rope_kernel<<<(TTOK * 64 + 255) / 256, 256>>>(pos);

    // 3) tensor-core paged causal flash attention (cp.async staged)
    dim3 ga(16, NH, 4);
    attn_kernel<<<ga, 256, ATTN_SMEM>>>(past_k, past_v, q_start, q_lens, kv_lens, blk_off);

    // 4) output projection
    dim3 go(HID / GN, TTOK / GM, 1);
    out_kernel<<<go, 512, GEMM_SMEM>>>(bo, out);
}

// round 12
// speedup vs baseline: 3.3137x; 1.0310x over previous
#include <cuda_runtime.h>
#include <math.h>
#include <stdint.h>

#define TTOK 3072
#define HID  4096
#define NH   32
#define HD   128
#define MAXB 24

// Device-global scratch (no allocations allowed)
__device__ float g_q[TTOK * HID];
__device__ float g_k[TTOK * HID];
__device__ float g_v[TTOK * HID];
__device__ float g_att[TTOK * HID];       // tf32-rounded at production
__device__ float g_x[TTOK * HID];         // tf32-rounded hidden_states
__device__ float g_w[4][HID * HID];       // tf32-rounded Wq,Wk,Wv,Wo

__device__ __forceinline__ float to_tf32(float x) {
    float y;
    asm("cvt.rna.tf32.f32 %0, %1;" : "=f"(y) : "f"(x));
    return y;
}
__device__ __forceinline__ uint32_t smem_u32(const void* p) {
    uint32_t a;
    asm("{ .reg .u64 t; cvta.to.shared.u64 t, %1; cvt.u32.u64 %0, t; }"
        : "=r"(a) : "l"(p));
    return a;
}

#define CP_ASYNC16(dst, src) \
    asm volatile("cp.async.cg.shared.global [%0], [%1], 16;" :: "r"(dst), "l"(src))
#define CP_COMMIT() asm volatile("cp.async.commit_group;" ::: "memory")
#define CP_WAIT1()  asm volatile("cp.async.wait_group 1;"  ::: "memory")
#define CP_WAIT0()  asm volatile("cp.async.wait_group 0;"  ::: "memory")

#define MMA_TF32(acc, a, b) \
    asm volatile("mma.sync.aligned.m16n8k8.row.col.f32.tf32.tf32.f32 " \
        "{%0,%1,%2,%3}, {%4,%5,%6,%7}, {%8,%9}, {%0,%1,%2,%3};" \
        : "+f"((acc)[0]), "+f"((acc)[1]), "+f"((acc)[2]), "+f"((acc)[3]) \
        : "r"((a)[0]), "r"((a)[1]), "r"((a)[2]), "r"((a)[3]), \
          "r"((b)[0]), "r"((b)[1]))

// ===========================================================================
// Prepass: round inputs once to tf32 (grid-stride, memory-bound).
// ===========================================================================
__global__ void cvt_prepass(const float4* __restrict__ X,
                            const float4* __restrict__ Wq, const float4* __restrict__ Wk,
                            const float4* __restrict__ Wv, const float4* __restrict__ Wo)
{
    const int which = blockIdx.y;
    const float4* src;
    float4* dst;
    size_t n;
    if (which < 4) {
        src = (which == 0) ? Wq : (which == 1) ? Wk : (which == 2) ? Wv : Wo;
        dst = (float4*)g_w[which];
        n = (size_t)HID * HID / 4;
    } else {
        src = X; dst = (float4*)g_x; n = (size_t)TTOK * HID / 4;
    }
    const size_t step = (size_t)gridDim.x * blockDim.x;
    for (size_t i = (size_t)blockIdx.x * blockDim.x + threadIdx.x; i < n; i += step) {
        float4 v = src[i];
        v.x = to_tf32(v.x); v.y = to_tf32(v.y);
        v.z = to_tf32(v.z); v.w = to_tf32(v.w);
        dst[i] = v;
    }
}

// ===========================================================================
// TF32 mma.sync GEMM (R9-proven config): 128x128 block tile, BK=32,
// 256 threads (8 warps 2x4), warp tile 64x32, cp.async 3-stage, 2 CTAs/SM.
// ===========================================================================
#define GM 128
#define GN 128
#define GK 32
#define NCHUNK (HID / GK)
#define ASTRIDE 36
#define TILE_WORDS (128 * ASTRIDE)
#define STAGE_WORDS (2 * TILE_WORDS)
#define GEMM_SMEM (3 * STAGE_WORDS * 4)   // 110592 bytes

__device__ __forceinline__ void gemm_issue_stage(
    const float* __restrict__ A, const float* __restrict__ B,
    int m0, int n0, int kt, uint32_t stage_base, int srow, int quad)
{
    const float* ag = A + (size_t)(m0 + srow) * HID + kt * GK + quad * 4;
    const float* bg = B + (size_t)(n0 + srow) * HID + kt * GK + quad * 4;
    const uint32_t off = (uint32_t)(srow * ASTRIDE + quad * 4) * 4;
    const uint32_t as = stage_base + off;
    const uint32_t bs = stage_base + TILE_WORDS * 4 + off;
#pragma unroll
    for (int l = 0; l < 4; l++) {
        CP_ASYNC16(as + l * 32 * ASTRIDE * 4, ag + (size_t)(l * 32) * HID);
        CP_ASYNC16(bs + l * 32 * ASTRIDE * 4, bg + (size_t)(l * 32) * HID);
    }
}

__device__ __forceinline__ void gemm_mma_stage(
    const float* __restrict__ As, const float* __restrict__ Bs,
    float acc[4][4][4], int wm, int wn, int lane)
{
#pragma unroll
    for (int k = 0; k < 4; k++) {
        const int c0 = k * 8 + (lane & 3);
        uint32_t af[4][4];
        uint32_t bf[4][2];
#pragma unroll
        for (int i = 0; i < 4; i++) {
            const int r0 = wm * 64 + i * 16 + (lane >> 2);
            af[i][0] = __float_as_uint(As[r0 * ASTRIDE + c0]);
            af[i][1] = __float_as_uint(As[(r0 + 8) * ASTRIDE + c0]);
            af[i][2] = __float_as_uint(As[r0 * ASTRIDE + c0 + 4]);
            af[i][3] = __float_as_uint(As[(r0 + 8) * ASTRIDE + c0 + 4]);
        }
#pragma unroll
        for (int j = 0; j < 4; j++) {
            const int nn = wn * 32 + j * 8 + (lane >> 2);
            bf[j][0] = __float_as_uint(Bs[nn * ASTRIDE + c0]);
            bf[j][1] = __float_as_uint(Bs[nn * ASTRIDE + c0 + 4]);
        }
#pragma unroll
        for (int i = 0; i < 4; i++)
#pragma unroll
            for (int jn = 0; jn < 4; jn++)
                MMA_TF32(acc[i][jn], af[i], bf[jn]);
    }
}

__device__ __forceinline__ void gemm_body(
    const float* __restrict__ A, const float* __restrict__ B,
    const float* __restrict__ bias, float* __restrict__ C, float* smx)
{
    const int tid = threadIdx.x;
    const int w = tid >> 5, lane = tid & 31;
    const int wm = w >> 2, wn = w & 3;
    const int m0 = blockIdx.y * GM, n0 = blockIdx.x * GN;
    const int srow = tid >> 3, quad = tid & 7;
    const uint32_t sbase = smem_u32(smx);
    const uint32_t stage_addr[3] = {sbase, sbase + STAGE_WORDS * 4,
                                    sbase + 2 * STAGE_WORDS * 4};

    float acc[4][4][4];
#pragma unroll
    for (int i = 0; i < 4; i++)
#pragma unroll
        for (int j = 0; j < 4; j++)
#pragma unroll
            for (int r = 0; r < 4; r++) acc[i][j][r] = 0.f;

    gemm_issue_stage(A, B, m0, n0, 0, stage_addr[0], srow, quad);
    CP_COMMIT();
    gemm_issue_stage(A, B, m0, n0, 1, stage_addr[1], srow, quad);
    CP_COMMIT();

    for (int kt = 0; kt < NCHUNK; kt++) {
        const int s = kt % 3;
        CP_WAIT1();
        __syncthreads();
        const float* As = smx + s * STAGE_WORDS;
        const float* Bs = As + TILE_WORDS;
        gemm_mma_stage(As, Bs, acc, wm, wn, lane);
        if (kt + 2 < NCHUNK)
            gemm_issue_stage(A, B, m0, n0, kt + 2, stage_addr[(kt + 2) % 3], srow, quad);
        CP_COMMIT();
    }
    CP_WAIT0();

    const int qrow = lane >> 2, qcol = (lane & 3) * 2;
#pragma unroll
    for (int jn = 0; jn < 4; jn++) {
        const int colg = n0 + wn * 32 + jn * 8 + qcol;
        const float2 bi = *(const float2*)&bias[colg];
#pragma unroll
        for (int i = 0; i < 4; i++) {
            const int rg = m0 + wm * 64 + i * 16 + qrow;
            float2 v0 = make_float2(acc[i][jn][0] + bi.x, acc[i][jn][1] + bi.y);
            float2 v1 = make_float2(acc[i][jn][2] + bi.x, acc[i][jn][3] + bi.y);
            *(float2*)&C[(size_t)rg * HID + colg] = v0;
            *(float2*)&C[(size_t)(rg + 8) * HID + colg] = v1;
        }
    }
}

__global__ __launch_bounds__(256, 2)
void qkv_kernel(const float* __restrict__ biasq)
{
    extern __shared__ float smx[];
    const float* W = g_w[blockIdx.z];
    float* C = (blockIdx.z == 0) ? g_q : (blockIdx.z == 1) ? g_k : g_v;
    gemm_body(g_x, W, biasq + (size_t)blockIdx.z * HID, C, smx);
}

__global__ __launch_bounds__(256, 2)
void out_kernel(const float* __restrict__ bo, float* __restrict__ out)
{
    extern __shared__ float smx[];
    gemm_body(g_att, g_w[3], bo, out, smx);
}

// ---------------------------------------------------------------------------
// RoPE (unchanged): one thread per (t, pair), angle shared across heads.
// ---------------------------------------------------------------------------
__global__ void rope_kernel(const int* __restrict__ pos)
{
    int idx = blockIdx.x * blockDim.x + threadIdx.x;
    if (idx >= TTOK * 64) return;
    const int p = idx & 63, t = idx >> 6;

    const double inv = exp(-(double)p * (9.210340371976184 / 64.0));
    const double f = (double)pos[t] * inv;
    const double n = rint(f * 0.15915494309189535);
    const float r = (float)(f - n * 6.283185307179586);
    float s, c;
    __sincosf(r, &s, &c);

    size_t base = (size_t)t * HID + p;
#pragma unroll 4
    for (int h = 0; h < NH; h++) {
        const size_t o = base + (size_t)h * HD;
        float q1 = g_q[o], q2 = g_q[o + 64];
        g_q[o]      = q1 * c - q2 * s;
        g_q[o + 64] = q2 * c + q1 * s;
        float k1 = g_k[o], k2 = g_k[o + 64];
        g_k[o]      = k1 * c - k2 * s;
        g_k[o + 64] = k2 * c + k1 * s;
    }
}

// ===========================================================================
// Attention v4: AQ=128 tensor-core flash attention, 512 threads (16 warps,
// 4 row-groups x 4 col-groups). S = QK^T via 3xTF32 (Qh fp32 smem, Ql bf16
// smem, K hi/lo split in regs from raw cp.async smem); PV via 1x tf32 with
// raw tok-major V. Halves per-work sync + staging cost vs AQ=64.
// ===========================================================================
#define AQ 128
#define AK 64
#define QH_OFF 0                       // [128][132] fp32        = 16896
#define QLB_OFF 16896                  // [128][132] bf16 halves =  8448 floats
#define KR_OFF (16896 + 8448)          // 25344: [64][132] fp32  =  8448
#define VR_OFF (25344 + 8448)          // 33792: [64][136] fp32  =  8704
#define PS_OFF (33792 + 8704)          // 42496: [128][68] fp32  =  8704
#define RED_OFF (42496 + 8704)         // 51200: [4][128]        =   512
#define ATTN_SMEM ((51200 + 512) * 4)  // 206848 bytes

__global__ __launch_bounds__(512, 1)
void attn_kernel(const float* __restrict__ past_k, const float* __restrict__ past_v,
                 const int* __restrict__ q_start, const int* __restrict__ q_lens,
                 const int* __restrict__ kv_lens, const int* __restrict__ blk_off)
{
    extern __shared__ float sm[];
    float* Qh = sm + QH_OFF;
    uint16_t* Qlb = (uint16_t*)(sm + QLB_OFF);
    float* Kr = sm + KR_OFF;
    float* Vr = sm + VR_OFF;
    float* Ps = sm + PS_OFF;
    float* red = sm + RED_OFF;

    const int qt = blockIdx.x, h = blockIdx.y, b = blockIdx.z;
    const int qlen = q_lens[b];
    if (qt * AQ >= qlen) return;
    const int kvlen = kv_lens[b];
    const int hist = kvlen - qlen;
    const int qs = q_start[b];
    const int tid = threadIdx.x;
    const int w = tid >> 5, lane = tid & 31;
    const int wm = w & 3, wn = w >> 2;     // rows wm*32.., S-cols wn*16..
    const int lr = lane >> 2, lc = lane & 3;
    const float scale = 0.088388347648318447f;
    const uint32_t sbase = smem_u32(sm);
    const uint32_t kr_base = sbase + KR_OFF * 4;
    const uint32_t vr_base = sbase + VR_OFF * 4;

    const int ntiles = hist / AK + 2 * qt + 2;
    auto kv_src = [&](int kt, const float*& ks, const float*& vs, int& rstr) {
        if (kt * AK >= hist) {
            size_t o = (size_t)(qs + kt * AK - hist) * HID + h * HD;
            ks = g_k + o; vs = g_v + o; rstr = HID;
        } else {
            int blk = blk_off[b * MAXB + kt];
            size_t o = ((size_t)(blk * 64) * NH + h) * HD;
            ks = past_k + o; vs = past_v + o; rstr = NH * HD;
        }
    };
    auto issue_K = [&](int kt) {
        const float* ks; const float* vs; int rstr;
        kv_src(kt, ks, vs, rstr);
#pragma unroll
        for (int l = 0; l < 4; l++) {
            int f4 = tid + l * 512;
            int r = f4 >> 5, c = f4 & 31;
            CP_ASYNC16(kr_base + (uint32_t)(r * 132 + c * 4) * 4,
                       ks + (size_t)r * rstr + c * 4);
        }
    };
    auto issue_V = [&](int kt) {
        const float* ks; const float* vs; int rstr;
        kv_src(kt, ks, vs, rstr);
#pragma unroll
        for (int l = 0; l < 4; l++) {
            int f4 = tid + l * 512;
            int r = f4 >> 5, c = f4 & 31;
            CP_ASYNC16(vr_base + (uint32_t)(r * 136 + c * 4) * 4,
                       vs + (size_t)r * rstr + c * 4);
        }
    };

    // ---- Stage Q once (scaled, hi fp32 / lo bf16) ----
#pragma unroll
    for (int l = 0; l < 8; l++) {
        int f4 = tid + l * 512;
        int r = f4 >> 5;
        int c = (f4 & 31) * 4;
        float4 v = *(const float4*)(g_q + (size_t)(qs + qt * AQ + r) * HID + h * HD + c);
        float xv[4] = {v.x * scale, v.y * scale, v.z * scale, v.w * scale};
#pragma unroll
        for (int s = 0; s < 4; s++) {
            float hi = to_tf32(xv[s]);
            Qh[r * 132 + c + s] = hi;
            uint32_t u = __float_as_uint(xv[s] - hi);
            Qlb[r * 132 + c + s] = (uint16_t)((u + 0x7FFFu + ((u >> 16) & 1u)) >> 16);
        }
    }
    issue_K(0); CP_COMMIT();
    issue_V(0); CP_COMMIT();

    float m_i[2][2], l_i[2][2], acco[2][4][4];
#pragma unroll
    for (int i = 0; i < 2; i++)
#pragma unroll
        for (int hf = 0; hf < 2; hf++) { m_i[i][hf] = -3.0e38f; l_i[i][hf] = 0.f; }
#pragma unroll
    for (int i = 0; i < 2; i++)
#pragma unroll
        for (int j = 0; j < 4; j++)
#pragma unroll
            for (int e = 0; e < 4; e++) acco[i][j][e] = 0.f;

    for (int kt = 0; kt < ntiles; kt++) {
        CP_WAIT1();
        __syncthreads();   // K(kt) + Q visible

        // ---- S = Q K^T, 3xTF32 ----
        float accs[2][2][4];
#pragma unroll
        for (int i = 0; i < 2; i++)
#pragma unroll
            for (int j = 0; j < 2; j++)
#pragma unroll
                for (int e = 0; e < 4; e++) accs[i][j][e] = 0.f;

#pragma unroll
        for (int ks = 0; ks < 16; ks++) {
            const int cA = ks * 8 + lc;
            uint32_t ah[2][4], al[2][4], bh[2][2], bl[2][2];
#pragma unroll
            for (int i = 0; i < 2; i++) {
                const int r0 = wm * 32 + i * 16 + lr;
                ah[i][0] = __float_as_uint(Qh[r0 * 132 + cA]);
                ah[i][1] = __float_as_uint(Qh[(r0 + 8) * 132 + cA]);
                ah[i][2] = __float_as_uint(Qh[r0 * 132 + cA + 4]);
                ah[i][3] = __float_as_uint(Qh[(r0 + 8) * 132 + cA + 4]);
                al[i][0] = (uint32_t)Qlb[r0 * 132 + cA] << 16;
                al[i][1] = (uint32_t)Qlb[(r0 + 8) * 132 + cA] << 16;
                al[i][2] = (uint32_t)Qlb[r0 * 132 + cA + 4] << 16;
                al[i][3] = (uint32_t)Qlb[(r0 + 8) * 132 + cA + 4] << 16;
            }
#pragma unroll
            for (int j = 0; j < 2; j++) {
                const int n0 = wn * 16 + j * 8 + lr;
                float r0v = Kr[n0 * 132 + cA];
                float r1v = Kr[n0 * 132 + cA + 4];
                float h0 = to_tf32(r0v), h1 = to_tf32(r1v);
                bh[j][0] = __float_as_uint(h0);
                bh[j][1] = __float_as_uint(h1);
                bl[j][0] = __float_as_uint(to_tf32(r0v - h0));
                bl[j][1] = __float_as_uint(to_tf32(r1v - h1));
            }
#pragma unroll
            for (int i = 0; i < 2; i++)
#pragma unroll
                for (int j = 0; j < 2; j++) {
                    MMA_TF32(accs[i][j], ah[i], bh[j]);
                    MMA_TF32(accs[i][j], ah[i], bl[j]);
                    MMA_TF32(accs[i][j], al[i], bh[j]);
                }
        }

        // ---- Causal mask (two diagonal-region tiles) ----
        const int lim_off = hist + qt * AQ - kt * 64;
        if (lim_off < 63) {
#pragma unroll
            for (int i = 0; i < 2; i++)
#pragma unroll
                for (int j = 0; j < 2; j++) {
                    const int r0 = wm * 32 + i * 16 + lr;
                    const int c0 = wn * 16 + j * 8 + 2 * lc;
                    if (c0 > lim_off + r0)     accs[i][j][0] = -1e30f;
                    if (c0 + 1 > lim_off + r0) accs[i][j][1] = -1e30f;
                    if (c0 > lim_off + r0 + 8)     accs[i][j][2] = -1e30f;
                    if (c0 + 1 > lim_off + r0 + 8) accs[i][j][3] = -1e30f;
                }
        }

        // ---- Online softmax: cross-warp row max ----
#pragma unroll
        for (int i = 0; i < 2; i++)
#pragma unroll
            for (int hf = 0; hf < 2; hf++) {
                float v = fmaxf(fmaxf(accs[i][0][2 * hf], accs[i][0][2 * hf + 1]),
                                fmaxf(accs[i][1][2 * hf], accs[i][1][2 * hf + 1]));
                v = fmaxf(v, __shfl_xor_sync(0xffffffffu, v, 1));
                v = fmaxf(v, __shfl_xor_sync(0xffffffffu, v, 2));
                if (lc == 0)
                    red[wn * 128 + wm * 32 + i * 16 + hf * 8 + lr] = v;
            }
        __syncthreads();

        float alpha[2][2];
#pragma unroll
        for (int i = 0; i < 2; i++)
#pragma unroll
            for (int hf = 0; hf < 2; hf++) {
                const int r = wm * 32 + i * 16 + hf * 8 + lr;
                float tm = fmaxf(fmaxf(red[r], red[128 + r]),
                                 fmaxf(red[256 + r], red[384 + r]));
                float mnew = fmaxf(m_i[i][hf], tm);
                alpha[i][hf] = __expf(m_i[i][hf] - mnew);
                m_i[i][hf] = mnew;
            }
        __syncthreads();   // red reuse; Kr reads complete -> prefetch K(t+1)
        if (kt + 1 < ntiles) issue_K(kt + 1);
        CP_COMMIT();

        // ---- p = exp; partial sums; P -> smem ----
#pragma unroll
        for (int i = 0; i < 2; i++)
#pragma unroll
            for (int j = 0; j < 2; j++)
#pragma unroll
                for (int e = 0; e < 4; e++)
                    accs[i][j][e] = __expf(accs[i][j][e] - m_i[i][e >> 1]);

#pragma unroll
        for (int i = 0; i < 2; i++)
#pragma unroll
            for (int hf = 0; hf < 2; hf++) {
                float ps = (accs[i][0][2 * hf] + accs[i][0][2 * hf + 1]) +
                           (accs[i][1][2 * hf] + accs[i][1][2 * hf + 1]);
                ps += __shfl_xor_sync(0xffffffffu, ps, 1);
                ps += __shfl_xor_sync(0xffffffffu, ps, 2);
                if (lc == 0)
                    red[wn * 128 + wm * 32 + i * 16 + hf * 8 + lr] = ps;
            }
#pragma unroll
        for (int i = 0; i < 2; i++)
#pragma unroll
            for (int j = 0; j < 2; j++) {
                const int r0 = wm * 32 + i * 16 + lr;
                const int cp = wn * 16 + j * 8 + 2 * lc;
                Ps[r0 * 68 + cp]           = to_tf32(accs[i][j][0]);
                Ps[r0 * 68 + cp + 1]       = to_tf32(accs[i][j][1]);
                Ps[(r0 + 8) * 68 + cp]     = to_tf32(accs[i][j][2]);
                Ps[(r0 + 8) * 68 + cp + 1] = to_tf32(accs[i][j][3]);
            }
        CP_WAIT1();        // V(kt) complete (K(t+1) may remain pending)
        __syncthreads();   // V, Ps, red sums visible

#pragma unroll
        for (int i = 0; i < 2; i++)
#pragma unroll
            for (int hf = 0; hf < 2; hf++) {
                const int r = wm * 32 + i * 16 + hf * 8 + lr;
                l_i[i][hf] = l_i[i][hf] * alpha[i][hf] +
                             ((red[r] + red[128 + r]) + (red[256 + r] + red[384 + r]));
            }
#pragma unroll
        for (int i = 0; i < 2; i++)
#pragma unroll
            for (int j = 0; j < 4; j++)
#pragma unroll
                for (int e = 0; e < 4; e++)
                    acco[i][j][e] *= alpha[i][e >> 1];

        // ---- O += P V (1x tf32, V raw tok-major) ----
#pragma unroll
        for (int ks = 0; ks < 8; ks++) {
            const int kk = ks * 8 + lc;
            uint32_t af[2][4], bf[4][2];
#pragma unroll
            for (int i = 0; i < 2; i++) {
                const int r0 = wm * 32 + i * 16 + lr;
                af[i][0] = __float_as_uint(Ps[r0 * 68 + kk]);
                af[i][1] = __float_as_uint(Ps[(r0 + 8) * 68 + kk]);
                af[i][2] = __float_as_uint(Ps[r0 * 68 + kk + 4]);
                af[i][3] = __float_as_uint(Ps[(r0 + 8) * 68 + kk + 4]);
            }
#pragma unroll
            for (int j = 0; j < 4; j++) {
                const int n0 = wn * 32 + j * 8 + lr;   // d index
                bf[j][0] = __float_as_uint(to_tf32(Vr[kk * 136 + n0]));
                bf[j][1] = __float_as_uint(to_tf32(Vr[(kk + 4) * 136 + n0]));
            }
#pragma unroll
            for (int i = 0; i < 2; i++)
#pragma unroll
                for (int j = 0; j < 4; j++)
                    MMA_TF32(acco[i][j], af[i], bf[j]);
        }
        __syncthreads();   // Vr/Ps free -> prefetch V(t+1)
        if (kt + 1 < ntiles) issue_V(kt + 1);
        CP_COMMIT();
    }

    // ---- Epilogue ----
    float inv_l[2][2];
#pragma unroll
    for (int i = 0; i < 2; i++)
#pragma unroll
        for (int hf = 0; hf < 2; hf++) inv_l[i][hf] = 1.0f / l_i[i][hf];

#pragma unroll
    for (int i = 0; i < 2; i++)
#pragma unroll
        for (int j = 0; j < 4; j++) {
            const int r0 = qs + qt * AQ + wm * 32 + i * 16 + lr;
            const int col = h * HD + wn * 32 + j * 8 + 2 * lc;
            float2 v0 = make_float2(to_tf32(acco[i][j][0] * inv_l[i][0]),
                                    to_tf32(acco[i][j][1] * inv_l[i][0]));
            float2 v1 = make_float2(to_tf32(acco[i][j][2] * inv_l[i][1]),
                                    to_tf32(acco[i][j][3] * inv_l[i][1]));
            *(float2*)&g_att[(size_t)r0 * HID + col] = v0;
            *(float2*)&g_att[(size_t)(r0 + 8) * HID + col] = v1;
        }
}

// ---------------------------------------------------------------------------
__device__ float g_bias[3 * HID];
__global__ void pack_bias(const float* __restrict__ bq, const float* __restrict__ bk,
                          const float* __restrict__ bv)
{
    int i = blockIdx.x * blockDim.x + threadIdx.x;
    if (i < HID) {
        g_bias[i] = bq[i];
        g_bias[HID + i] = bk[i];
        g_bias[2 * HID + i] = bv[i];
    }
}

// ---------------------------------------------------------------------------
extern "C" void kernel_launch(void* const* d_in, const int* in_sizes, int n_in,
                              void* d_out, int out_size)
{
    const float* hidden  = (const float*)d_in[0];
    const int*   pos     = (const int*)d_in[1];
    const int*   q_start = (const int*)d_in[2];
    const int*   q_lens  = (const int*)d_in[3];
    const int*   kv_lens = (const int*)d_in[4];
    const int*   blk_off = (const int*)d_in[5];
    const float* past_k  = (const float*)d_in[6];
    const float* past_v  = (const float*)d_in[7];
    const float* Wq = (const float*)d_in[8];
    const float* bq = (const float*)d_in[9];
    const float* Wk = (const float*)d_in[10];
    const float* bk = (const float*)d_in[11];
    const float* Wv = (const float*)d_in[12];
    const float* bv = (const float*)d_in[13];
    const float* Wo = (const float*)d_in[14];
    const float* bo = (const float*)d_in[15];
    float* out = (float*)d_out;

    (void)cudaFuncSetAttribute(qkv_kernel, cudaFuncAttributeMaxDynamicSharedMemorySize, GEMM_SMEM);
    (void)cudaFuncSetAttribute(out_kernel, cudaFuncAttributeMaxDynamicSharedMemorySize, GEMM_SMEM);
    (void)cudaFuncSetAttribute(attn_kernel, cudaFuncAttributeMaxDynamicSharedMemorySize, ATTN_SMEM);

    // 0) tf32 prepass + bias packing
    cvt_prepass<<<dim3(2048, 5), 256>>>(
        (const float4*)hidden, (const float4*)Wq, (const float4*)Wk,
        (const float4*)Wv, (const float4*)Wo);
    pack_bias<<<(HID + 255) / 256, 256>>>(bq, bk, bv);

    // 1) fused QKV projections (128x128 tiles, 2 CTAs/SM)
    float* g_bias_ptr = nullptr;
    (void)cudaGetSymbolAddress((void**)&g_bias_ptr, g_bias);
    dim3 gq(HID / GN, TTOK / GM, 3);
    qkv_kernel<<<gq, 256, GEMM_SMEM>>>(g_bias_ptr);

    // 2) RoPE
    rope_kernel<<<(TTOK * 64 + 255) / 256, 256>>>(pos);

    // 3) tensor-core paged causal flash attention (AQ=128)
    dim3 ga(8, NH, 4);
    attn_kernel<<<ga, 512, ATTN_SMEM>>>(past_k, past_v, q_start, q_lens, kv_lens, blk_off);

    // 4) output projection
    dim3 go(HID / GN, TTOK / GM, 1);
    out_kernel<<<go, 256, GEMM_SMEM>>>(bo, out);
}

// round 13
// speedup vs baseline: 5.2953x; 1.5980x over previous
#include <cuda_runtime.h>
#include <cuda_fp16.h>
#include <math.h>
#include <stdint.h>

#define TTOK 3072
#define HID  4096
#define NH   32
#define HD   128
#define MAXB 24

// Device-global scratch (no allocations allowed)
__device__ float  g_q[TTOK * HID];
__device__ float  g_k[TTOK * HID];
__device__ float  g_v[TTOK * HID];
__device__ __half g_atth[TTOK * HID];      // fp16 attention output (GEMM input)
__device__ __half g_xh[TTOK * HID];        // fp16 hidden_states
__device__ __half g_wh[4][HID * HID];      // fp16 Wq,Wk,Wv,Wo

__device__ __forceinline__ float to_tf32(float x) {
    float y;
    asm("cvt.rna.tf32.f32 %0, %1;" : "=f"(y) : "f"(x));
    return y;
}
__device__ __forceinline__ uint32_t smem_u32(const void* p) {
    uint32_t a;
    asm("{ .reg .u64 t; cvta.to.shared.u64 t, %1; cvt.u32.u64 %0, t; }"
        : "=r"(a) : "l"(p));
    return a;
}

#define CP_ASYNC16(dst, src) \
    asm volatile("cp.async.cg.shared.global [%0], [%1], 16;" :: "r"(dst), "l"(src))
#define CP_COMMIT() asm volatile("cp.async.commit_group;" ::: "memory")
#define CP_WAIT1()  asm volatile("cp.async.wait_group 1;"  ::: "memory")
#define CP_WAIT0()  asm volatile("cp.async.wait_group 0;"  ::: "memory")

#define MMA_TF32(acc, a, b) \
    asm volatile("mma.sync.aligned.m16n8k8.row.col.f32.tf32.tf32.f32 " \
        "{%0,%1,%2,%3}, {%4,%5,%6,%7}, {%8,%9}, {%0,%1,%2,%3};" \
        : "+f"((acc)[0]), "+f"((acc)[1]), "+f"((acc)[2]), "+f"((acc)[3]) \
        : "r"((a)[0]), "r"((a)[1]), "r"((a)[2]), "r"((a)[3]), \
          "r"((b)[0]), "r"((b)[1]))

#define MMA_F16(acc, a, b) \
    asm volatile("mma.sync.aligned.m16n8k16.row.col.f32.f16.f16.f32 " \
        "{%0,%1,%2,%3}, {%4,%5,%6,%7}, {%8,%9}, {%0,%1,%2,%3};" \
        : "+f"((acc)[0]), "+f"((acc)[1]), "+f"((acc)[2]), "+f"((acc)[3]) \
        : "r"((a)[0]), "r"((a)[1]), "r"((a)[2]), "r"((a)[3]), \
          "r"((b)[0]), "r"((b)[1]))

// ===========================================================================
// Prepass: round X + weights once to fp16 (RN; same 2^-11 mantissa as tf32).
// ===========================================================================
__global__ void cvt_prepass(const float4* __restrict__ X,
                            const float4* __restrict__ Wq, const float4* __restrict__ Wk,
                            const float4* __restrict__ Wv, const float4* __restrict__ Wo)
{
    const int which = blockIdx.y;
    const float4* src;
    __half2* dst;
    size_t n;
    if (which < 4) {
        src = (which == 0) ? Wq : (which == 1) ? Wk : (which == 2) ? Wv : Wo;
        dst = (__half2*)g_wh[which];
        n = (size_t)HID * HID / 4;
    } else {
        src = X; dst = (__half2*)g_xh; n = (size_t)TTOK * HID / 4;
    }
    const size_t step = (size_t)gridDim.x * blockDim.x;
    for (size_t i = (size_t)blockIdx.x * blockDim.x + threadIdx.x; i < n; i += step) {
        float4 v = src[i];
        dst[2 * i]     = __floats2half2_rn(v.x, v.y);
        dst[2 * i + 1] = __floats2half2_rn(v.z, v.w);
    }
}

// ===========================================================================
// FP16 mma.sync GEMM: C[M,N] = A[M,K] @ B[N,K]^T + bias (fp32 accum/out).
// 128x128 block tile, K-chunk = 64 halves (128B rows), 256 threads (8 warps
// 2x4), warp tile 64x32, cp.async 3-stage, 2 CTAs/SM.
// smem rows padded to 72 halves (word stride 36 -> conflict-free LDS.32).
// ===========================================================================
#define GM 128
#define GN 128
#define GKH 64                        // K halves per stage
#define NCHUNK (HID / GKH)            // 64 stages
#define ASTRH 72                      // halves per smem row (144 B)
#define TILE_BYTES_H (128 * ASTRH * 2)        // 18432
#define STAGE_BYTES (2 * TILE_BYTES_H)        // 36864
#define GEMM_SMEM (3 * STAGE_BYTES)           // 110592

__device__ __forceinline__ void gemm_issue_stage(
    const __half* __restrict__ A, const __half* __restrict__ B,
    int m0, int n0, int kt, uint32_t stage_base, int srow, int quad)
{
    // srow 0..31, quad 0..7 (16B chunk within 128B of row data)
    const __half* ag = A + (size_t)(m0 + srow) * HID + kt * GKH + quad * 8;
    const __half* bg = B + (size_t)(n0 + srow) * HID + kt * GKH + quad * 8;
    const uint32_t off = (uint32_t)srow * (ASTRH * 2) + quad * 16;
    const uint32_t as = stage_base + off;
    const uint32_t bs = stage_base + TILE_BYTES_H + off;
#pragma unroll
    for (int l = 0; l < 4; l++) {
        CP_ASYNC16(as + l * 32 * (ASTRH * 2), ag + (size_t)(l * 32) * HID);
        CP_ASYNC16(bs + l * 32 * (ASTRH * 2), bg + (size_t)(l * 32) * HID);
    }
}

__device__ __forceinline__ void gemm_mma_stage(
    const __half* __restrict__ As, const __half* __restrict__ Bs,
    float acc[4][4][4], int wm, int wn, int lane)
{
    const int lr = lane >> 2, lc2 = (lane & 3) * 2;
#pragma unroll
    for (int kk = 0; kk < GKH; kk += 16) {
        uint32_t af[4][4];
        uint32_t bf[4][2];
#pragma unroll
        for (int i = 0; i < 4; i++) {
            const int r0 = wm * 64 + i * 16 + lr;
            af[i][0] = *(const uint32_t*)(As + r0 * ASTRH + kk + lc2);
            af[i][1] = *(const uint32_t*)(As + (r0 + 8) * ASTRH + kk + lc2);
            af[i][2] = *(const uint32_t*)(As + r0 * ASTRH + kk + lc2 + 8);
            af[i][3] = *(const uint32_t*)(As + (r0 + 8) * ASTRH + kk + lc2 + 8);
        }
#pragma unroll
        for (int j = 0; j < 4; j++) {
            const int nn = wn * 32 + j * 8 + lr;
            bf[j][0] = *(const uint32_t*)(Bs + nn * ASTRH + kk + lc2);
            bf[j][1] = *(const uint32_t*)(Bs + nn * ASTRH + kk + lc2 + 8);
        }
#pragma unroll
        for (int i = 0; i < 4; i++)
#pragma unroll
            for (int jn = 0; jn < 4; jn++)
                MMA_F16(acc[i][jn], af[i], bf[jn]);
    }
}

__device__ __forceinline__ void gemm_body(
    const __half* __restrict__ A, const __half* __restrict__ B,
    const float* __restrict__ bias, float* __restrict__ C, char* smx)
{
    const int tid = threadIdx.x;
    const int w = tid >> 5, lane = tid & 31;
    const int wm = w >> 2, wn = w & 3;
    const int m0 = blockIdx.y * GM, n0 = blockIdx.x * GN;
    const int srow = tid >> 3, quad = tid & 7;
    const uint32_t sbase = smem_u32(smx);
    const uint32_t stage_addr[3] = {sbase, sbase + STAGE_BYTES,
                                    sbase + 2 * STAGE_BYTES};

    float acc[4][4][4];
#pragma unroll
    for (int i = 0; i < 4; i++)
#pragma unroll
        for (int j = 0; j < 4; j++)
#pragma unroll
            for (int r = 0; r < 4; r++) acc[i][j][r] = 0.f;

    gemm_issue_stage(A, B, m0, n0, 0, stage_addr[0], srow, quad);
    CP_COMMIT();
    gemm_issue_stage(A, B, m0, n0, 1, stage_addr[1], srow, quad);
    CP_COMMIT();

    for (int kt = 0; kt < NCHUNK; kt++) {
        const int s = kt % 3;
        CP_WAIT1();
        __syncthreads();
        const __half* As = (const __half*)(smx + s * STAGE_BYTES);
        const __half* Bs = (const __half*)(smx + s * STAGE_BYTES + TILE_BYTES_H);
        gemm_mma_stage(As, Bs, acc, wm, wn, lane);
        if (kt + 2 < NCHUNK)
            gemm_issue_stage(A, B, m0, n0, kt + 2, stage_addr[(kt + 2) % 3], srow, quad);
        CP_COMMIT();
    }
    CP_WAIT0();

    const int qrow = lane >> 2, qcol = (lane & 3) * 2;
#pragma unroll
    for (int jn = 0; jn < 4; jn++) {
        const int colg = n0 + wn * 32 + jn * 8 + qcol;
        const float2 bi = *(const float2*)&bias[colg];
#pragma unroll
        for (int i = 0; i < 4; i++) {
            const int rg = m0 + wm * 64 + i * 16 + qrow;
            float2 v0 = make_float2(acc[i][jn][0] + bi.x, acc[i][jn][1] + bi.y);
            float2 v1 = make_float2(acc[i][jn][2] + bi.x, acc[i][jn][3] + bi.y);
            *(float2*)&C[(size_t)rg * HID + colg] = v0;
            *(float2*)&C[(size_t)(rg + 8) * HID + colg] = v1;
        }
    }
}

__global__ __launch_bounds__(256, 2)
void qkv_kernel(const float* __restrict__ biasq)
{
    extern __shared__ char smx[];
    const __half* W = g_wh[blockIdx.z];
    float* C = (blockIdx.z == 0) ? g_q : (blockIdx.z == 1) ? g_k : g_v;
    gemm_body(g_xh, W, biasq + (size_t)blockIdx.z * HID, C, smx);
}

__global__ __launch_bounds__(256, 2)
void out_kernel(const float* __restrict__ bo, float* __restrict__ out)
{
    extern __shared__ char smx[];
    gemm_body(g_atth, g_wh[3], bo, out, smx);
}

// ---------------------------------------------------------------------------
// RoPE (unchanged): one thread per (t, pair), angle shared across heads.
// ---------------------------------------------------------------------------
__global__ void rope_kernel(const int* __restrict__ pos)
{
    int idx = blockIdx.x * blockDim.x + threadIdx.x;
    if (idx >= TTOK * 64) return;
    const int p = idx & 63, t = idx >> 6;

    const double inv = exp(-(double)p * (9.210340371976184 / 64.0));
    const double f = (double)pos[t] * inv;
    const double n = rint(f * 0.15915494309189535);
    const float r = (float)(f - n * 6.283185307179586);
    float s, c;
    __sincosf(r, &s, &c);

    size_t base = (size_t)t * HID + p;
#pragma unroll 4
    for (int h = 0; h < NH; h++) {
        const size_t o = base + (size_t)h * HD;
        float q1 = g_q[o], q2 = g_q[o + 64];
        g_q[o]      = q1 * c - q2 * s;
        g_q[o + 64] = q2 * c + q1 * s;
        float k1 = g_k[o], k2 = g_k[o + 64];
        g_k[o]      = k1 * c - k2 * s;
        g_k[o + 64] = k2 * c + k1 * s;
    }
}

// ===========================================================================
// Attention (R12-proven, unchanged except fp16 g_att store): AQ=128, 512 thr,
// S = QK^T via 3xTF32 (Qh fp32 / Ql bf16 smem, K reg-split), PV via 1x tf32.
// ===========================================================================
#define AQ 128
#define AK 64
#define QH_OFF 0
#define QLB_OFF 16896
#define KR_OFF (16896 + 8448)
#define VR_OFF (25344 + 8448)
#define PS_OFF (33792 + 8704)
#define RED_OFF (42496 + 8704)
#define ATTN_SMEM ((51200 + 512) * 4)

__global__ __launch_bounds__(512, 1)
void attn_kernel(const float* __restrict__ past_k, const float* __restrict__ past_v,
                 const int* __restrict__ q_start, const int* __restrict__ q_lens,
                 const int* __restrict__ kv_lens, const int* __restrict__ blk_off)
{
    extern __shared__ float sm[];
    float* Qh = sm + QH_OFF;
    uint16_t* Qlb = (uint16_t*)(sm + QLB_OFF);
    float* Kr = sm + KR_OFF;
    float* Vr = sm + VR_OFF;
    float* Ps = sm + PS_OFF;
    float* red = sm + RED_OFF;

    const int qt = blockIdx.x, h = blockIdx.y, b = blockIdx.z;
    const int qlen = q_lens[b];
    if (qt * AQ >= qlen) return;
    const int kvlen = kv_lens[b];
    const int hist = kvlen - qlen;
    const int qs = q_start[b];
    const int tid = threadIdx.x;
    const int w = tid >> 5, lane = tid & 31;
    const int wm = w & 3, wn = w >> 2;
    const int lr = lane >> 2, lc = lane & 3;
    const float scale = 0.088388347648318447f;
    const uint32_t sbase = smem_u32(sm);
    const uint32_t kr_base = sbase + KR_OFF * 4;
    const uint32_t vr_base = sbase + VR_OFF * 4;

    const int ntiles = hist / AK + 2 * qt + 2;
    auto kv_src = [&](int kt, const float*& ks, const float*& vs, int& rstr) {
        if (kt * AK >= hist) {
            size_t o = (size_t)(qs + kt * AK - hist) * HID + h * HD;
            ks = g_k + o; vs = g_v + o; rstr = HID;
        } else {
            int blk = blk_off[b * MAXB + kt];
            size_t o = ((size_t)(blk * 64) * NH + h) * HD;
            ks = past_k + o; vs = past_v + o; rstr = NH * HD;
        }
    };
    auto issue_K = [&](int kt) {
        const float* ks; const float* vs; int rstr;
        kv_src(kt, ks, vs, rstr);
#pragma unroll
        for (int l = 0; l < 4; l++) {
            int f4 = tid + l * 512;
            int r = f4 >> 5, c = f4 & 31;
            CP_ASYNC16(kr_base + (uint32_t)(r * 132 + c * 4) * 4,
                       ks + (size_t)r * rstr + c * 4);
        }
    };
    auto issue_V = [&](int kt) {
        const float* ks; const float* vs; int rstr;
        kv_src(kt, ks, vs, rstr);
#pragma unroll
        for (int l = 0; l < 4; l++) {
            int f4 = tid + l * 512;
            int r = f4 >> 5, c = f4 & 31;
            CP_ASYNC16(vr_base + (uint32_t)(r * 136 + c * 4) * 4,
                       vs + (size_t)r * rstr + c * 4);
        }
    };

    // ---- Stage Q once (scaled, hi fp32 / lo bf16) ----
#pragma unroll
    for (int l = 0; l < 8; l++) {
        int f4 = tid + l * 512;
        int r = f4 >> 5;
        int c = (f4 & 31) * 4;
        float4 v = *(const float4*)(g_q + (size_t)(qs + qt * AQ + r) * HID + h * HD + c);
        float xv[4] = {v.x * scale, v.y * scale, v.z * scale, v.w * scale};
#pragma unroll
        for (int s = 0; s < 4; s++) {
            float hi = to_tf32(xv[s]);
            Qh[r * 132 + c + s] = hi;
            uint32_t u = __float_as_uint(xv[s] - hi);
            Qlb[r * 132 + c + s] = (uint16_t)((u + 0x7FFFu + ((u >> 16) & 1u)) >> 16);
        }
    }
    issue_K(0); CP_COMMIT();
    issue_V(0); CP_COMMIT();

    float m_i[2][2], l_i[2][2], acco[2][4][4];
#pragma unroll
    for (int i = 0; i < 2; i++)
#pragma unroll
        for (int hf = 0; hf < 2; hf++) { m_i[i][hf] = -3.0e38f; l_i[i][hf] = 0.f; }
#pragma unroll
    for (int i = 0; i < 2; i++)
#pragma unroll
        for (int j = 0; j < 4; j++)
#pragma unroll
            for (int e = 0; e < 4; e++) acco[i][j][e] = 0.f;

    for (int kt = 0; kt < ntiles; kt++) {
        CP_WAIT1();
        __syncthreads();

        float accs[2][2][4];
#pragma unroll
        for (int i = 0; i < 2; i++)
#pragma unroll
            for (int j = 0; j < 2; j++)
#pragma unroll
                for (int e = 0; e < 4; e++) accs[i][j][e] = 0.f;

#pragma unroll
        for (int ks = 0; ks < 16; ks++) {
            const int cA = ks * 8 + lc;
            uint32_t ah[2][4], al[2][4], bh[2][2], bl[2][2];
#pragma unroll
            for (int i = 0; i < 2; i++) {
                const int r0 = wm * 32 + i * 16 + lr;
                ah[i][0] = __float_as_uint(Qh[r0 * 132 + cA]);
                ah[i][1] = __float_as_uint(Qh[(r0 + 8) * 132 + cA]);
                ah[i][2] = __float_as_uint(Qh[r0 * 132 + cA + 4]);
                ah[i][3] = __float_as_uint(Qh[(r0 + 8) * 132 + cA + 4]);
                al[i][0] = (uint32_t)Qlb[r0 * 132 + cA] << 16;
                al[i][1] = (uint32_t)Qlb[(r0 + 8) * 132 + cA] << 16;
                al[i][2] = (uint32_t)Qlb[r0 * 132 + cA + 4] << 16;
                al[i][3] = (uint32_t)Qlb[(r0 + 8) * 132 + cA + 4] << 16;
            }
#pragma unroll
            for (int j = 0; j < 2; j++) {
                const int n0 = wn * 16 + j * 8 + lr;
                float r0v = Kr[n0 * 132 + cA];
                float r1v = Kr[n0 * 132 + cA + 4];
                float h0 = to_tf32(r0v), h1 = to_tf32(r1v);
                bh[j][0] = __float_as_uint(h0);
                bh[j][1] = __float_as_uint(h1);
                bl[j][0] = __float_as_uint(to_tf32(r0v - h0));
                bl[j][1] = __float_as_uint(to_tf32(r1v - h1));
            }
#pragma unroll
            for (int i = 0; i < 2; i++)
#pragma unroll
                for (int j = 0; j < 2; j++) {
                    MMA_TF32(accs[i][j], ah[i], bh[j]);
                    MMA_TF32(accs[i][j], ah[i], bl[j]);
                    MMA_TF32(accs[i][j], al[i], bh[j]);
                }
        }

        const int lim_off = hist + qt * AQ - kt * 64;
        if (lim_off < 63) {
#pragma unroll
            for (int i = 0; i < 2; i++)
#pragma unroll
                for (int j = 0; j < 2; j++) {
                    const int r0 = wm * 32 + i * 16 + lr;
                    const int c0 = wn * 16 + j * 8 + 2 * lc;
                    if (c0 > lim_off + r0)     accs[i][j][0] = -1e30f;
                    if (c0 + 1 > lim_off + r0) accs[i][j][1] = -1e30f;
                    if (c0 > lim_off + r0 + 8)     accs[i][j][2] = -1e30f;
                    if (c0 + 1 > lim_off + r0 + 8) accs[i][j][3] = -1e30f;
                }
        }

#pragma unroll
        for (int i = 0; i < 2; i++)
#pragma unroll
            for (int hf = 0; hf < 2; hf++) {
                float v = fmaxf(fmaxf(accs[i][0][2 * hf], accs[i][0][2 * hf + 1]),
                                fmaxf(accs[i][1][2 * hf], accs[i][1][2 * hf + 1]));
                v = fmaxf(v, __shfl_xor_sync(0xffffffffu, v, 1));
                v = fmaxf(v, __shfl_xor_sync(0xffffffffu, v, 2));
                if (lc == 0)
                    red[wn * 128 + wm * 32 + i * 16 + hf * 8 + lr] = v;
            }
        __syncthreads();

        float alpha[2][2];
#pragma unroll
        for (int i = 0; i < 2; i++)
#pragma unroll
            for (int hf = 0; hf < 2; hf++) {
                const int r = wm * 32 + i * 16 + hf * 8 + lr;
                float tm = fmaxf(fmaxf(red[r], red[128 + r]),
                                 fmaxf(red[256 + r], red[384 + r]));
                float mnew = fmaxf(m_i[i][hf], tm);
                alpha[i][hf] = __expf(m_i[i][hf] - mnew);
                m_i[i][hf] = mnew;
            }
        __syncthreads();
        if (kt + 1 < ntiles) issue_K(kt + 1);
        CP_COMMIT();

#pragma unroll
        for (int i = 0; i < 2; i++)
#pragma unroll
            for (int j = 0; j < 2; j++)
#pragma unroll
                for (int e = 0; e < 4; e++)
                    accs[i][j][e] = __expf(accs[i][j][e] - m_i[i][e >> 1]);

#pragma unroll
        for (int i = 0; i < 2; i++)
#pragma unroll
            for (int hf = 0; hf < 2; hf++) {
                float ps = (accs[i][0][2 * hf] + accs[i][0][2 * hf + 1]) +
                           (accs[i][1][2 * hf] + accs[i][1][2 * hf + 1]);
                ps += __shfl_xor_sync(0xffffffffu, ps, 1);
                ps += __shfl_xor_sync(0xffffffffu, ps, 2);
                if (lc == 0)
                    red[wn * 128 + wm * 32 + i * 16 + hf * 8 + lr] = ps;
            }
#pragma unroll
        for (int i = 0; i < 2; i++)
#pragma unroll
            for (int j = 0; j < 2; j++) {
                const int r0 = wm * 32 + i * 16 + lr;
                const int cp = wn * 16 + j * 8 + 2 * lc;
                Ps[r0 * 68 + cp]           = to_tf32(accs[i][j][0]);
                Ps[r0 * 68 + cp + 1]       = to_tf32(accs[i][j][1]);
                Ps[(r0 + 8) * 68 + cp]     = to_tf32(accs[i][j][2]);
                Ps[(r0 + 8) * 68 + cp + 1] = to_tf32(accs[i][j][3]);
            }
        CP_WAIT1();
        __syncthreads();

#pragma unroll
        for (int i = 0; i < 2; i++)
#pragma unroll
            for (int hf = 0; hf < 2; hf++) {
                const int r = wm * 32 + i * 16 + hf * 8 + lr;
                l_i[i][hf] = l_i[i][hf] * alpha[i][hf] +
                             ((red[r] + red[128 + r]) + (red[256 + r] + red[384 + r]));
            }
#pragma unroll
        for (int i = 0; i < 2; i++)
#pragma unroll
            for (int j = 0; j < 4; j++)
#pragma unroll
                for (int e = 0; e < 4; e++)
                    acco[i][j][e] *= alpha[i][e >> 1];

#pragma unroll
        for (int ks = 0; ks < 8; ks++) {
            const int kk = ks * 8 + lc;
            uint32_t af[2][4], bf[4][2];
#pragma unroll
            for (int i = 0; i < 2; i++) {
                const int r0 = wm * 32 + i * 16 + lr;
                af[i][0] = __float_as_uint(Ps[r0 * 68 + kk]);
                af[i][1] = __float_as_uint(Ps[(r0 + 8) * 68 + kk]);
                af[i][2] = __float_as_uint(Ps[r0 * 68 + kk + 4]);
                af[i][3] = __float_as_uint(Ps[(r0 + 8) * 68 + kk + 4]);
            }
#pragma unroll
            for (int j = 0; j < 4; j++) {
                const int n0 = wn * 32 + j * 8 + lr;
                bf[j][0] = __float_as_uint(to_tf32(Vr[kk * 136 + n0]));
                bf[j][1] = __float_as_uint(to_tf32(Vr[(kk + 4) * 136 + n0]));
            }
#pragma unroll
            for (int i = 0; i < 2; i++)
#pragma unroll
                for (int j = 0; j < 4; j++)
                    MMA_TF32(acco[i][j], af[i], bf[j]);
        }
        __syncthreads();
        if (kt + 1 < ntiles) issue_V(kt + 1);
        CP_COMMIT();
    }

    // ---- Epilogue: normalize, store fp16 ----
    float inv_l[2][2];
#pragma unroll
    for (int i = 0; i < 2; i++)
#pragma unroll
        for (int hf = 0; hf < 2; hf++) inv_l[i][hf] = 1.0f / l_i[i][hf];

#pragma unroll
    for (int i = 0; i < 2; i++)
#pragma unroll
        for (int j = 0; j < 4; j++) {
            const int r0 = qs + qt * AQ + wm * 32 + i * 16 + lr;
            const int col = h * HD + wn * 32 + j * 8 + 2 * lc;
            *(__half2*)&g_atth[(size_t)r0 * HID + col] =
                __floats2half2_rn(acco[i][j][0] * inv_l[i][0],
                                  acco[i][j][1] * inv_l[i][0]);
            *(__half2*)&g_atth[(size_t)(r0 + 8) * HID + col] =
                __floats2half2_rn(acco[i][j][2] * inv_l[i][1],
                                  acco[i][j][3] * inv_l[i][1]);
        }
}

// ---------------------------------------------------------------------------
__device__ float g_bias[3 * HID];
__global__ void pack_bias(const float* __restrict__ bq, const float* __restrict__ bk,
                          const float* __restrict__ bv)
{
    int i = blockIdx.x * blockDim.x + threadIdx.x;
    if (i < HID) {
        g_bias[i] = bq[i];
        g_bias[HID + i] = bk[i];
        g_bias[2 * HID + i] = bv[i];
    }
}

// ---------------------------------------------------------------------------
extern "C" void kernel_launch(void* const* d_in, const int* in_sizes, int n_in,
                              void* d_out, int out_size)
{
    const float* hidden  = (const float*)d_in[0];
    const int*   pos     = (const int*)d_in[1];
    const int*   q_start = (const int*)d_in[2];
    const int*   q_lens  = (const int*)d_in[3];
    const int*   kv_lens = (const int*)d_in[4];
    const int*   blk_off = (const int*)d_in[5];
    const float* past_k  = (const float*)d_in[6];
    const float* past_v  = (const float*)d_in[7];
    const float* Wq = (const float*)d_in[8];
    const float* bq = (const float*)d_in[9];
    const float* Wk = (const float*)d_in[10];
    const float* bk = (const float*)d_in[11];
    const float* Wv = (const float*)d_in[12];
    const float* bv = (const float*)d_in[13];
    const float* Wo = (const float*)d_in[14];
    const float* bo = (const float*)d_in[15];
    float* out = (float*)d_out;

    (void)cudaFuncSetAttribute(qkv_kernel, cudaFuncAttributeMaxDynamicSharedMemorySize, GEMM_SMEM);
    (void)cudaFuncSetAttribute(out_kernel, cudaFuncAttributeMaxDynamicSharedMemorySize, GEMM_SMEM);
    (void)cudaFuncSetAttribute(attn_kernel, cudaFuncAttributeMaxDynamicSharedMemorySize, ATTN_SMEM);

    // 0) fp16 prepass + bias packing
    cvt_prepass<<<dim3(2048, 5), 256>>>(
        (const float4*)hidden, (const float4*)Wq, (const float4*)Wk,
        (const float4*)Wv, (const float4*)Wo);
    pack_bias<<<(HID + 255) / 256, 256>>>(bq, bk, bv);

    // 1) fused QKV projections (fp16 mma)
    float* g_bias_ptr = nullptr;
    (void)cudaGetSymbolAddress((void**)&g_bias_ptr, g_bias);
    dim3 gq(HID / GN, TTOK / GM, 3);
    qkv_kernel<<<gq, 256, GEMM_SMEM>>>(g_bias_ptr);

    // 2) RoPE
    rope_kernel<<<(TTOK * 64 + 255) / 256, 256>>>(pos);

    // 3) tensor-core paged causal flash attention (AQ=128, tf32)
    dim3 ga(8, NH, 4);
    attn_kernel<<<ga, 512, ATTN_SMEM>>>(past_k, past_v, q_start, q_lens, kv_lens, blk_off);

    // 4) output projection (fp16 mma)
    dim3 go(HID / GN, TTOK / GM, 1);
    out_kernel<<<go, 256, GEMM_SMEM>>>(bo, out);
}

// round 14
// speedup vs baseline: 5.8904x; 1.1124x over previous
#include <cuda_runtime.h>
#include <cuda_fp16.h>
#include <math.h>
#include <stdint.h>

#define TTOK 3072
#define HID  4096
#define NH   32
#define HD   128
#define MAXB 24

// Device-global scratch (no allocations allowed)
__device__ float  g_q[TTOK * HID];
__device__ float  g_k[TTOK * HID];
__device__ float  g_v[TTOK * HID];
__device__ __half g_atth[TTOK * HID];      // fp16 attention output (GEMM input)
__device__ __half g_xh[TTOK * HID];        // fp16 hidden_states
__device__ __half g_wh[4][HID * HID];      // fp16 Wq,Wk,Wv,Wo

__device__ __forceinline__ uint32_t smem_u32(const void* p) {
    uint32_t a;
    asm("{ .reg .u64 t; cvta.to.shared.u64 t, %1; cvt.u32.u64 %0, t; }"
        : "=r"(a) : "l"(p));
    return a;
}
__device__ __forceinline__ uint32_t h2_u32(__half2 h) {
    return *(uint32_t*)&h;
}

#define CP_ASYNC16(dst, src) \
    asm volatile("cp.async.cg.shared.global [%0], [%1], 16;" :: "r"(dst), "l"(src))
#define CP_COMMIT() asm volatile("cp.async.commit_group;" ::: "memory")
#define CP_WAIT1()  asm volatile("cp.async.wait_group 1;"  ::: "memory")
#define CP_WAIT0()  asm volatile("cp.async.wait_group 0;"  ::: "memory")

#define MMA_F16(acc, a, b) \
    asm volatile("mma.sync.aligned.m16n8k16.row.col.f32.f16.f16.f32 " \
        "{%0,%1,%2,%3}, {%4,%5,%6,%7}, {%8,%9}, {%0,%1,%2,%3};" \
        : "+f"((acc)[0]), "+f"((acc)[1]), "+f"((acc)[2]), "+f"((acc)[3]) \
        : "r"((a)[0]), "r"((a)[1]), "r"((a)[2]), "r"((a)[3]), \
          "r"((b)[0]), "r"((b)[1]))

// ===========================================================================
// Prepass: round X + weights once to fp16 (RN; same 2^-11 mantissa as tf32).
// ===========================================================================
__global__ void cvt_prepass(const float4* __restrict__ X,
                            const float4* __restrict__ Wq, const float4* __restrict__ Wk,
                            const float4* __restrict__ Wv, const float4* __restrict__ Wo)
{
    const int which = blockIdx.y;
    const float4* src;
    __half2* dst;
    size_t n;
    if (which < 4) {
        src = (which == 0) ? Wq : (which == 1) ? Wk : (which == 2) ? Wv : Wo;
        dst = (__half2*)g_wh[which];
        n = (size_t)HID * HID / 4;
    } else {
        src = X; dst = (__half2*)g_xh; n = (size_t)TTOK * HID / 4;
    }
    const size_t step = (size_t)gridDim.x * blockDim.x;
    for (size_t i = (size_t)blockIdx.x * blockDim.x + threadIdx.x; i < n; i += step) {
        float4 v = src[i];
        dst[2 * i]     = __floats2half2_rn(v.x, v.y);
        dst[2 * i + 1] = __floats2half2_rn(v.z, v.w);
    }
}

// ===========================================================================
// FP16 mma.sync GEMM (R13-proven, unchanged): 128x128, K-chunk 64 halves,
// 256 thr, cp.async 3-stage, 2 CTAs/SM.
// ===========================================================================
#define GM 128
#define GN 128
#define GKH 64
#define NCHUNK (HID / GKH)
#define ASTRH 72
#define TILE_BYTES_H (128 * ASTRH * 2)
#define STAGE_BYTES (2 * TILE_BYTES_H)
#define GEMM_SMEM (3 * STAGE_BYTES)

__device__ __forceinline__ void gemm_issue_stage(
    const __half* __restrict__ A, const __half* __restrict__ B,
    int m0, int n0, int kt, uint32_t stage_base, int srow, int quad)
{
    const __half* ag = A + (size_t)(m0 + srow) * HID + kt * GKH + quad * 8;
    const __half* bg = B + (size_t)(n0 + srow) * HID + kt * GKH + quad * 8;
    const uint32_t off = (uint32_t)srow * (ASTRH * 2) + quad * 16;
    const uint32_t as = stage_base + off;
    const uint32_t bs = stage_base + TILE_BYTES_H + off;
#pragma unroll
    for (int l = 0; l < 4; l++) {
        CP_ASYNC16(as + l * 32 * (ASTRH * 2), ag + (size_t)(l * 32) * HID);
        CP_ASYNC16(bs + l * 32 * (ASTRH * 2), bg + (size_t)(l * 32) * HID);
    }
}

__device__ __forceinline__ void gemm_mma_stage(
    const __half* __restrict__ As, const __half* __restrict__ Bs,
    float acc[4][4][4], int wm, int wn, int lane)
{
    const int lr = lane >> 2, lc2 = (lane & 3) * 2;
#pragma unroll
    for (int kk = 0; kk < GKH; kk += 16) {
        uint32_t af[4][4];
        uint32_t bf[4][2];
#pragma unroll
        for (int i = 0; i < 4; i++) {
            const int r0 = wm * 64 + i * 16 + lr;
            af[i][0] = *(const uint32_t*)(As + r0 * ASTRH + kk + lc2);
            af[i][1] = *(const uint32_t*)(As + (r0 + 8) * ASTRH + kk + lc2);
            af[i][2] = *(const uint32_t*)(As + r0 * ASTRH + kk + lc2 + 8);
            af[i][3] = *(const uint32_t*)(As + (r0 + 8) * ASTRH + kk + lc2 + 8);
        }
#pragma unroll
        for (int j = 0; j < 4; j++) {
            const int nn = wn * 32 + j * 8 + lr;
            bf[j][0] = *(const uint32_t*)(Bs + nn * ASTRH + kk + lc2);
            bf[j][1] = *(const uint32_t*)(Bs + nn * ASTRH + kk + lc2 + 8);
        }
#pragma unroll
        for (int i = 0; i < 4; i++)
#pragma unroll
            for (int jn = 0; jn < 4; jn++)
                MMA_F16(acc[i][jn], af[i], bf[jn]);
    }
}

__device__ __forceinline__ void gemm_body(
    const __half* __restrict__ A, const __half* __restrict__ B,
    const float* __restrict__ bias, float* __restrict__ C, char* smx)
{
    const int tid = threadIdx.x;
    const int w = tid >> 5, lane = tid & 31;
    const int wm = w >> 2, wn = w & 3;
    const int m0 = blockIdx.y * GM, n0 = blockIdx.x * GN;
    const int srow = tid >> 3, quad = tid & 7;
    const uint32_t sbase = smem_u32(smx);
    const uint32_t stage_addr[3] = {sbase, sbase + STAGE_BYTES,
                                    sbase + 2 * STAGE_BYTES};

    float acc[4][4][4];
#pragma unroll
    for (int i = 0; i < 4; i++)
#pragma unroll
        for (int j = 0; j < 4; j++)
#pragma unroll
            for (int r = 0; r < 4; r++) acc[i][j][r] = 0.f;

    gemm_issue_stage(A, B, m0, n0, 0, stage_addr[0], srow, quad);
    CP_COMMIT();
    gemm_issue_stage(A, B, m0, n0, 1, stage_addr[1], srow, quad);
    CP_COMMIT();

    for (int kt = 0; kt < NCHUNK; kt++) {
        const int s = kt % 3;
        CP_WAIT1();
        __syncthreads();
        const __half* As = (const __half*)(smx + s * STAGE_BYTES);
        const __half* Bs = (const __half*)(smx + s * STAGE_BYTES + TILE_BYTES_H);
        gemm_mma_stage(As, Bs, acc, wm, wn, lane);
        if (kt + 2 < NCHUNK)
            gemm_issue_stage(A, B, m0, n0, kt + 2, stage_addr[(kt + 2) % 3], srow, quad);
        CP_COMMIT();
    }
    CP_WAIT0();

    const int qrow = lane >> 2, qcol = (lane & 3) * 2;
#pragma unroll
    for (int jn = 0; jn < 4; jn++) {
        const int colg = n0 + wn * 32 + jn * 8 + qcol;
        const float2 bi = *(const float2*)&bias[colg];
#pragma unroll
        for (int i = 0; i < 4; i++) {
            const int rg = m0 + wm * 64 + i * 16 + qrow;
            float2 v0 = make_float2(acc[i][jn][0] + bi.x, acc[i][jn][1] + bi.y);
            float2 v1 = make_float2(acc[i][jn][2] + bi.x, acc[i][jn][3] + bi.y);
            *(float2*)&C[(size_t)rg * HID + colg] = v0;
            *(float2*)&C[(size_t)(rg + 8) * HID + colg] = v1;
        }
    }
}

__global__ __launch_bounds__(256, 2)
void qkv_kernel(const float* __restrict__ biasq)
{
    extern __shared__ char smx[];
    const __half* W = g_wh[blockIdx.z];
    float* C = (blockIdx.z == 0) ? g_q : (blockIdx.z == 1) ? g_k : g_v;
    gemm_body(g_xh, W, biasq + (size_t)blockIdx.z * HID, C, smx);
}

__global__ __launch_bounds__(256, 2)
void out_kernel(const float* __restrict__ bo, float* __restrict__ out)
{
    extern __shared__ char smx[];
    gemm_body(g_atth, g_wh[3], bo, out, smx);
}

// ---------------------------------------------------------------------------
// RoPE (unchanged).
// ---------------------------------------------------------------------------
__global__ void rope_kernel(const int* __restrict__ pos)
{
    int idx = blockIdx.x * blockDim.x + threadIdx.x;
    if (idx >= TTOK * 64) return;
    const int p = idx & 63, t = idx >> 6;

    const double inv = exp(-(double)p * (9.210340371976184 / 64.0));
    const double f = (double)pos[t] * inv;
    const double n = rint(f * 0.15915494309189535);
    const float r = (float)(f - n * 6.283185307179586);
    float s, c;
    __sincosf(r, &s, &c);

    size_t base = (size_t)t * HID + p;
#pragma unroll 4
    for (int h = 0; h < NH; h++) {
        const size_t o = base + (size_t)h * HD;
        float q1 = g_q[o], q2 = g_q[o + 64];
        g_q[o]      = q1 * c - q2 * s;
        g_q[o + 64] = q2 * c + q1 * s;
        float k1 = g_k[o], k2 = g_k[o + 64];
        g_k[o]      = k1 * c - k2 * s;
        g_k[o + 64] = k2 * c + k1 * s;
    }
}

// ===========================================================================
// Attention v5: fp16-split tensor-core flash attention. AQ=128, 512 threads.
// S = QK^T via fp16 hi/lo 3-term split (fp32 accum); PV via 1x fp16.
// Q staged as fp16 hi+lo halves; K,V raw fp32 cp.async, fp16-split at
// fragment load. Same staging/sync schedule as the R12/R13-proven kernel.
// Smem word offsets:
//   Qh  [128][136]h = 8704w   Ql  [128][136]h = 8704w
//   Kr  [64][132]f  = 8448w   Vr  [64][136]f  = 8704w
//   Ps  [128][72]h  = 4608w   red [4][128]    = 512w
// ===========================================================================
#define AQ 128
#define AK 64
#define QH_OFF 0
#define QL_OFF 8704
#define KR_OFF 17408
#define VR_OFF 25856
#define PS_OFF 34560
#define RED_OFF 39168
#define ATTN_SMEM ((39168 + 512) * 4)   // 158720 bytes

__global__ __launch_bounds__(512, 1)
void attn_kernel(const float* __restrict__ past_k, const float* __restrict__ past_v,
                 const int* __restrict__ q_start, const int* __restrict__ q_lens,
                 const int* __restrict__ kv_lens, const int* __restrict__ blk_off)
{
    extern __shared__ float sm[];
    __half* Qh = (__half*)(sm + QH_OFF);      // [128][136] halves
    __half* Ql = (__half*)(sm + QL_OFF);      // [128][136] halves
    float* Kr = sm + KR_OFF;                  // [64][132] fp32
    float* Vr = sm + VR_OFF;                  // [64][136] fp32
    __half* Ps = (__half*)(sm + PS_OFF);      // [128][72] halves
    float* red = sm + RED_OFF;

    const int qt = blockIdx.x, h = blockIdx.y, b = blockIdx.z;
    const int qlen = q_lens[b];
    if (qt * AQ >= qlen) return;
    const int kvlen = kv_lens[b];
    const int hist = kvlen - qlen;
    const int qs = q_start[b];
    const int tid = threadIdx.x;
    const int w = tid >> 5, lane = tid & 31;
    const int wm = w & 3, wn = w >> 2;
    const int lr = lane >> 2, lc = lane & 3;
    const float scale = 0.088388347648318447f;
    const uint32_t sbase = smem_u32(sm);
    const uint32_t kr_base = sbase + KR_OFF * 4;
    const uint32_t vr_base = sbase + VR_OFF * 4;

    const int ntiles = hist / AK + 2 * qt + 2;
    auto kv_src = [&](int kt, const float*& ks, const float*& vs, int& rstr) {
        if (kt * AK >= hist) {
            size_t o = (size_t)(qs + kt * AK - hist) * HID + h * HD;
            ks = g_k + o; vs = g_v + o; rstr = HID;
        } else {
            int blk = blk_off[b * MAXB + kt];
            size_t o = ((size_t)(blk * 64) * NH + h) * HD;
            ks = past_k + o; vs = past_v + o; rstr = NH * HD;
        }
    };
    auto issue_K = [&](int kt) {
        const float* ks; const float* vs; int rstr;
        kv_src(kt, ks, vs, rstr);
#pragma unroll
        for (int l = 0; l < 4; l++) {
            int f4 = tid + l * 512;
            int r = f4 >> 5, c = f4 & 31;
            CP_ASYNC16(kr_base + (uint32_t)(r * 132 + c * 4) * 4,
                       ks + (size_t)r * rstr + c * 4);
        }
    };
    auto issue_V = [&](int kt) {
        const float* ks; const float* vs; int rstr;
        kv_src(kt, ks, vs, rstr);
#pragma unroll
        for (int l = 0; l < 4; l++) {
            int f4 = tid + l * 512;
            int r = f4 >> 5, c = f4 & 31;
            CP_ASYNC16(vr_base + (uint32_t)(r * 136 + c * 4) * 4,
                       vs + (size_t)r * rstr + c * 4);
        }
    };

    // ---- Stage Q once (scaled, fp16 hi / fp16 lo residual) ----
#pragma unroll
    for (int l = 0; l < 8; l++) {
        int f4 = tid + l * 512;
        int r = f4 >> 5;
        int c = (f4 & 31) * 4;
        float4 v = *(const float4*)(g_q + (size_t)(qs + qt * AQ + r) * HID + h * HD + c);
        float xv[4] = {v.x * scale, v.y * scale, v.z * scale, v.w * scale};
        __half hi[4];
        float  lo[4];
#pragma unroll
        for (int s = 0; s < 4; s++) {
            hi[s] = __float2half_rn(xv[s]);
            lo[s] = xv[s] - __half2float(hi[s]);
        }
        *(__half2*)(Qh + r * 136 + c)     = __halves2half2(hi[0], hi[1]);
        *(__half2*)(Qh + r * 136 + c + 2) = __halves2half2(hi[2], hi[3]);
        *(__half2*)(Ql + r * 136 + c)     = __floats2half2_rn(lo[0], lo[1]);
        *(__half2*)(Ql + r * 136 + c + 2) = __floats2half2_rn(lo[2], lo[3]);
    }
    issue_K(0); CP_COMMIT();
    issue_V(0); CP_COMMIT();

    float m_i[2][2], l_i[2][2], acco[2][4][4];
#pragma unroll
    for (int i = 0; i < 2; i++)
#pragma unroll
        for (int hf = 0; hf < 2; hf++) { m_i[i][hf] = -3.0e38f; l_i[i][hf] = 0.f; }
#pragma unroll
    for (int i = 0; i < 2; i++)
#pragma unroll
        for (int j = 0; j < 4; j++)
#pragma unroll
            for (int e = 0; e < 4; e++) acco[i][j][e] = 0.f;

    for (int kt = 0; kt < ntiles; kt++) {
        CP_WAIT1();
        __syncthreads();   // K(kt) + Q visible

        // ---- S = Q K^T, fp16 3-term split, k16 steps ----
        float accs[2][2][4];
#pragma unroll
        for (int i = 0; i < 2; i++)
#pragma unroll
            for (int j = 0; j < 2; j++)
#pragma unroll
                for (int e = 0; e < 4; e++) accs[i][j][e] = 0.f;

#pragma unroll
        for (int ks = 0; ks < 8; ks++) {
            const int kk = ks * 16;
            const int ka = kk + 2 * lc;
            uint32_t ah[2][4], al[2][4], bh[2][2], bl[2][2];
#pragma unroll
            for (int i = 0; i < 2; i++) {
                const int r0 = wm * 32 + i * 16 + lr;
                ah[i][0] = *(const uint32_t*)(Qh + r0 * 136 + ka);
                ah[i][1] = *(const uint32_t*)(Qh + (r0 + 8) * 136 + ka);
                ah[i][2] = *(const uint32_t*)(Qh + r0 * 136 + ka + 8);
                ah[i][3] = *(const uint32_t*)(Qh + (r0 + 8) * 136 + ka + 8);
                al[i][0] = *(const uint32_t*)(Ql + r0 * 136 + ka);
                al[i][1] = *(const uint32_t*)(Ql + (r0 + 8) * 136 + ka);
                al[i][2] = *(const uint32_t*)(Ql + r0 * 136 + ka + 8);
                al[i][3] = *(const uint32_t*)(Ql + (r0 + 8) * 136 + ka + 8);
            }
#pragma unroll
            for (int j = 0; j < 2; j++) {
                const int n0 = wn * 16 + j * 8 + lr;
                float2 f01 = *(const float2*)(Kr + n0 * 132 + ka);
                float2 f23 = *(const float2*)(Kr + n0 * 132 + ka + 8);
                __half2 h01 = __floats2half2_rn(f01.x, f01.y);
                __half2 h23 = __floats2half2_rn(f23.x, f23.y);
                bh[j][0] = h2_u32(h01);
                bh[j][1] = h2_u32(h23);
                bl[j][0] = h2_u32(__floats2half2_rn(
                    f01.x - __half2float(__low2half(h01)),
                    f01.y - __half2float(__high2half(h01))));
                bl[j][1] = h2_u32(__floats2half2_rn(
                    f23.x - __half2float(__low2half(h23)),
                    f23.y - __half2float(__high2half(h23))));
            }
#pragma unroll
            for (int i = 0; i < 2; i++)
#pragma unroll
                for (int j = 0; j < 2; j++) {
                    MMA_F16(accs[i][j], ah[i], bh[j]);
                    MMA_F16(accs[i][j], ah[i], bl[j]);
                    MMA_F16(accs[i][j], al[i], bh[j]);
                }
        }

        // ---- Causal mask ----
        const int lim_off = hist + qt * AQ - kt * 64;
        if (lim_off < 63) {
#pragma unroll
            for (int i = 0; i < 2; i++)
#pragma unroll
                for (int j = 0; j < 2; j++) {
                    const int r0 = wm * 32 + i * 16 + lr;
                    const int c0 = wn * 16 + j * 8 + 2 * lc;
                    if (c0 > lim_off + r0)     accs[i][j][0] = -1e30f;
                    if (c0 + 1 > lim_off + r0) accs[i][j][1] = -1e30f;
                    if (c0 > lim_off + r0 + 8)     accs[i][j][2] = -1e30f;
                    if (c0 + 1 > lim_off + r0 + 8) accs[i][j][3] = -1e30f;
                }
        }

        // ---- Online softmax: cross-warp row max ----
#pragma unroll
        for (int i = 0; i < 2; i++)
#pragma unroll
            for (int hf = 0; hf < 2; hf++) {
                float v = fmaxf(fmaxf(accs[i][0][2 * hf], accs[i][0][2 * hf + 1]),
                                fmaxf(accs[i][1][2 * hf], accs[i][1][2 * hf + 1]));
                v = fmaxf(v, __shfl_xor_sync(0xffffffffu, v, 1));
                v = fmaxf(v, __shfl_xor_sync(0xffffffffu, v, 2));
                if (lc == 0)
                    red[wn * 128 + wm * 32 + i * 16 + hf * 8 + lr] = v;
            }
        __syncthreads();

        float alpha[2][2];
#pragma unroll
        for (int i = 0; i < 2; i++)
#pragma unroll
            for (int hf = 0; hf < 2; hf++) {
                const int r = wm * 32 + i * 16 + hf * 8 + lr;
                float tm = fmaxf(fmaxf(red[r], red[128 + r]),
                                 fmaxf(red[256 + r], red[384 + r]));
                float mnew = fmaxf(m_i[i][hf], tm);
                alpha[i][hf] = __expf(m_i[i][hf] - mnew);
                m_i[i][hf] = mnew;
            }
        __syncthreads();
        if (kt + 1 < ntiles) issue_K(kt + 1);
        CP_COMMIT();

        // ---- p = exp; partial sums; P -> smem (fp16) ----
#pragma unroll
        for (int i = 0; i < 2; i++)
#pragma unroll
            for (int j = 0; j < 2; j++)
#pragma unroll
                for (int e = 0; e < 4; e++)
                    accs[i][j][e] = __expf(accs[i][j][e] - m_i[i][e >> 1]);

#pragma unroll
        for (int i = 0; i < 2; i++)
#pragma unroll
            for (int hf = 0; hf < 2; hf++) {
                float ps = (accs[i][0][2 * hf] + accs[i][0][2 * hf + 1]) +
                           (accs[i][1][2 * hf] + accs[i][1][2 * hf + 1]);
                ps += __shfl_xor_sync(0xffffffffu, ps, 1);
                ps += __shfl_xor_sync(0xffffffffu, ps, 2);
                if (lc == 0)
                    red[wn * 128 + wm * 32 + i * 16 + hf * 8 + lr] = ps;
            }
#pragma unroll
        for (int i = 0; i < 2; i++)
#pragma unroll
            for (int j = 0; j < 2; j++) {
                const int r0 = wm * 32 + i * 16 + lr;
                const int cp = wn * 16 + j * 8 + 2 * lc;
                *(__half2*)(Ps + r0 * 72 + cp) =
                    __floats2half2_rn(accs[i][j][0], accs[i][j][1]);
                *(__half2*)(Ps + (r0 + 8) * 72 + cp) =
                    __floats2half2_rn(accs[i][j][2], accs[i][j][3]);
            }
        CP_WAIT1();
        __syncthreads();   // V, Ps, red sums visible

#pragma unroll
        for (int i = 0; i < 2; i++)
#pragma unroll
            for (int hf = 0; hf < 2; hf++) {
                const int r = wm * 32 + i * 16 + hf * 8 + lr;
                l_i[i][hf] = l_i[i][hf] * alpha[i][hf] +
                             ((red[r] + red[128 + r]) + (red[256 + r] + red[384 + r]));
            }
#pragma unroll
        for (int i = 0; i < 2; i++)
#pragma unroll
            for (int j = 0; j < 4; j++)
#pragma unroll
                for (int e = 0; e < 4; e++)
                    acco[i][j][e] *= alpha[i][e >> 1];

        // ---- O += P V (1x fp16, V fp16-rounded at load), k16 steps ----
#pragma unroll
        for (int ks = 0; ks < 4; ks++) {
            const int kk = ks * 16;
            const int ka = kk + 2 * lc;
            uint32_t af[2][4], bf[4][2];
#pragma unroll
            for (int i = 0; i < 2; i++) {
                const int r0 = wm * 32 + i * 16 + lr;
                af[i][0] = *(const uint32_t*)(Ps + r0 * 72 + ka);
                af[i][1] = *(const uint32_t*)(Ps + (r0 + 8) * 72 + ka);
                af[i][2] = *(const uint32_t*)(Ps + r0 * 72 + ka + 8);
                af[i][3] = *(const uint32_t*)(Ps + (r0 + 8) * 72 + ka + 8);
            }
#pragma unroll
            for (int j = 0; j < 4; j++) {
                const int n0 = wn * 32 + j * 8 + lr;   // d index
                float v0 = Vr[(ka) * 136 + n0];
                float v1 = Vr[(ka + 1) * 136 + n0];
                float v2 = Vr[(ka + 8) * 136 + n0];
                float v3 = Vr[(ka + 9) * 136 + n0];
                bf[j][0] = h2_u32(__floats2half2_rn(v0, v1));
                bf[j][1] = h2_u32(__floats2half2_rn(v2, v3));
            }
#pragma unroll
            for (int i = 0; i < 2; i++)
#pragma unroll
                for (int j = 0; j < 4; j++)
                    MMA_F16(acco[i][j], af[i], bf[j]);
        }
        __syncthreads();
        if (kt + 1 < ntiles) issue_V(kt + 1);
        CP_COMMIT();
    }

    // ---- Epilogue: normalize, store fp16 ----
    float inv_l[2][2];
#pragma unroll
    for (int i = 0; i < 2; i++)
#pragma unroll
        for (int hf = 0; hf < 2; hf++) inv_l[i][hf] = 1.0f / l_i[i][hf];

#pragma unroll
    for (int i = 0; i < 2; i++)
#pragma unroll
        for (int j = 0; j < 4; j++) {
            const int r0 = qs + qt * AQ + wm * 32 + i * 16 + lr;
            const int col = h * HD + wn * 32 + j * 8 + 2 * lc;
            *(__half2*)&g_atth[(size_t)r0 * HID + col] =
                __floats2half2_rn(acco[i][j][0] * inv_l[i][0],
                                  acco[i][j][1] * inv_l[i][0]);
            *(__half2*)&g_atth[(size_t)(r0 + 8) * HID + col] =
                __floats2half2_rn(acco[i][j][2] * inv_l[i][1],
                                  acco[i][j][3] * inv_l[i][1]);
        }
}

// ---------------------------------------------------------------------------
__device__ float g_bias[3 * HID];
__global__ void pack_bias(const float* __restrict__ bq, const float* __restrict__ bk,
                          const float* __restrict__ bv)
{
    int i = blockIdx.x * blockDim.x + threadIdx.x;
    if (i < HID) {
        g_bias[i] = bq[i];
        g_bias[HID + i] = bk[i];
        g_bias[2 * HID + i] = bv[i];
    }
}

// ---------------------------------------------------------------------------
extern "C" void kernel_launch(void* const* d_in, const int* in_sizes, int n_in,
                              void* d_out, int out_size)
{
    const float* hidden  = (const float*)d_in[0];
    const int*   pos     = (const int*)d_in[1];
    const int*   q_start = (const int*)d_in[2];
    const int*   q_lens  = (const int*)d_in[3];
    const int*   kv_lens = (const int*)d_in[4];
    const int*   blk_off = (const int*)d_in[5];
    const float* past_k  = (const float*)d_in[6];
    const float* past_v  = (const float*)d_in[7];
    const float* Wq = (const float*)d_in[8];
    const float* bq = (const float*)d_in[9];
    const float* Wk = (const float*)d_in[10];
    const float* bk = (const float*)d_in[11];
    const float* Wv = (const float*)d_in[12];
    const float* bv = (const float*)d_in[13];
    const float* Wo = (const float*)d_in[14];
    const float* bo = (const float*)d_in[15];
    float* out = (float*)d_out;

    (void)cudaFuncSetAttribute(qkv_kernel, cudaFuncAttributeMaxDynamicSharedMemorySize, GEMM_SMEM);
    (void)cudaFuncSetAttribute(out_kernel, cudaFuncAttributeMaxDynamicSharedMemorySize, GEMM_SMEM);
    (void)cudaFuncSetAttribute(attn_kernel, cudaFuncAttributeMaxDynamicSharedMemorySize, ATTN_SMEM);

    // 0) fp16 prepass + bias packing
    cvt_prepass<<<dim3(2048, 5), 256>>>(
        (const float4*)hidden, (const float4*)Wq, (const float4*)Wk,
        (const float4*)Wv, (const float4*)Wo);
    pack_bias<<<(HID + 255) / 256, 256>>>(bq, bk, bv);

    // 1) fused QKV projections (fp16 mma)
    float* g_bias_ptr = nullptr;
    (void)cudaGetSymbolAddress((void**)&g_bias_ptr, g_bias);
    dim3 gq(HID / GN, TTOK / GM, 3);
    qkv_kernel<<<gq, 256, GEMM_SMEM>>>(g_bias_ptr);

    // 2) RoPE
    rope_kernel<<<(TTOK * 64 + 255) / 256, 256>>>(pos);

    // 3) fp16-split tensor-core paged causal flash attention
    dim3 ga(8, NH, 4);
    attn_kernel<<<ga, 512, ATTN_SMEM>>>(past_k, past_v, q_start, q_lens, kv_lens, blk_off);

    // 4) output projection (fp16 mma)
    dim3 go(HID / GN, TTOK / GM, 1);
    out_kernel<<<go, 256, GEMM_SMEM>>>(bo, out);
}

// round 15
// speedup vs baseline: 5.9097x; 1.0033x over previous
#include <cuda_runtime.h>
#include <cuda_fp16.h>
#include <math.h>
#include <stdint.h>

#define TTOK 3072
#define HID  4096
#define NH   32
#define HD   128
#define MAXB 24

// Device-global scratch (no allocations allowed)
__device__ float  g_q[TTOK * HID];
__device__ float  g_k[TTOK * HID];
__device__ float  g_v[TTOK * HID];
__device__ __half g_atth[TTOK * HID];      // fp16 attention output (GEMM input)
__device__ __half g_xh[TTOK * HID];        // fp16 hidden_states
__device__ __half g_wh[4][HID * HID];      // fp16 Wq,Wk,Wv,Wo

__device__ __forceinline__ uint32_t smem_u32(const void* p) {
    uint32_t a;
    asm("{ .reg .u64 t; cvta.to.shared.u64 t, %1; cvt.u32.u64 %0, t; }"
        : "=r"(a) : "l"(p));
    return a;
}
__device__ __forceinline__ uint32_t h2_u32(__half2 h) {
    return *(uint32_t*)&h;
}

#define CP_ASYNC16(dst, src) \
    asm volatile("cp.async.cg.shared.global [%0], [%1], 16;" :: "r"(dst), "l"(src))
#define CP_COMMIT() asm volatile("cp.async.commit_group;" ::: "memory")
#define CP_WAIT1()  asm volatile("cp.async.wait_group 1;"  ::: "memory")
#define CP_WAIT0()  asm volatile("cp.async.wait_group 0;"  ::: "memory")

#define MMA_F16(acc, a, b) \
    asm volatile("mma.sync.aligned.m16n8k16.row.col.f32.f16.f16.f32 " \
        "{%0,%1,%2,%3}, {%4,%5,%6,%7}, {%8,%9}, {%0,%1,%2,%3};" \
        : "+f"((acc)[0]), "+f"((acc)[1]), "+f"((acc)[2]), "+f"((acc)[3]) \
        : "r"((a)[0]), "r"((a)[1]), "r"((a)[2]), "r"((a)[3]), \
          "r"((b)[0]), "r"((b)[1]))

#define LDSM_X4(r0, r1, r2, r3, addr) \
    asm volatile("ldmatrix.sync.aligned.m8n8.x4.shared.b16 {%0,%1,%2,%3}, [%4];" \
        : "=r"(r0), "=r"(r1), "=r"(r2), "=r"(r3) : "r"(addr))

// ===========================================================================
// Prepass: round X + weights once to fp16.
// ===========================================================================
__global__ void cvt_prepass(const float4* __restrict__ X,
                            const float4* __restrict__ Wq, const float4* __restrict__ Wk,
                            const float4* __restrict__ Wv, const float4* __restrict__ Wo)
{
    const int which = blockIdx.y;
    const float4* src;
    __half2* dst;
    size_t n;
    if (which < 4) {
        src = (which == 0) ? Wq : (which == 1) ? Wk : (which == 2) ? Wv : Wo;
        dst = (__half2*)g_wh[which];
        n = (size_t)HID * HID / 4;
    } else {
        src = X; dst = (__half2*)g_xh; n = (size_t)TTOK * HID / 4;
    }
    const size_t step = (size_t)gridDim.x * blockDim.x;
    for (size_t i = (size_t)blockIdx.x * blockDim.x + threadIdx.x; i < n; i += step) {
        float4 v = src[i];
        dst[2 * i]     = __floats2half2_rn(v.x, v.y);
        dst[2 * i + 1] = __floats2half2_rn(v.z, v.w);
    }
}

// ===========================================================================
// FP16 mma.sync GEMM with ldmatrix fragment loads.
// 128x128, K-chunk 64 halves, 256 thr, cp.async 3-stage, 2 CTAs/SM.
// smem rows padded to 72 halves (144 B -> 16 mod 128: LDSM conflict-free).
// ===========================================================================
#define GM 128
#define GN 128
#define GKH 64
#define NCHUNK (HID / GKH)
#define ASTRH 72
#define TILE_BYTES_H (128 * ASTRH * 2)
#define STAGE_BYTES (2 * TILE_BYTES_H)
#define GEMM_SMEM (3 * STAGE_BYTES)

__device__ __forceinline__ void gemm_issue_stage(
    const __half* __restrict__ A, const __half* __restrict__ B,
    int m0, int n0, int kt, uint32_t stage_base, int srow, int quad)
{
    const __half* ag = A + (size_t)(m0 + srow) * HID + kt * GKH + quad * 8;
    const __half* bg = B + (size_t)(n0 + srow) * HID + kt * GKH + quad * 8;
    const uint32_t off = (uint32_t)srow * (ASTRH * 2) + quad * 16;
    const uint32_t as = stage_base + off;
    const uint32_t bs = stage_base + TILE_BYTES_H + off;
#pragma unroll
    for (int l = 0; l < 4; l++) {
        CP_ASYNC16(as + l * 32 * (ASTRH * 2), ag + (size_t)(l * 32) * HID);
        CP_ASYNC16(bs + l * 32 * (ASTRH * 2), bg + (size_t)(l * 32) * HID);
    }
}

__device__ __forceinline__ void gemm_mma_stage(
    uint32_t As_addr, uint32_t Bs_addr,
    float acc[4][4][4], int wm, int wn, int lane)
{
    const int lrow = lane & 15, lcol = (lane >> 4) * 8;
    uint32_t a_addr[4], b_addr[2];
#pragma unroll
    for (int i = 0; i < 4; i++)
        a_addr[i] = As_addr + (uint32_t)((wm * 64 + i * 16 + lrow) * ASTRH + lcol) * 2;
#pragma unroll
    for (int j2 = 0; j2 < 2; j2++)
        b_addr[j2] = Bs_addr + (uint32_t)((wn * 32 + j2 * 16 + lrow) * ASTRH + lcol) * 2;

#pragma unroll
    for (int kk = 0; kk < GKH; kk += 16) {
        uint32_t af[4][4];
        uint32_t bf[4][2];
#pragma unroll
        for (int i = 0; i < 4; i++)
            LDSM_X4(af[i][0], af[i][1], af[i][2], af[i][3], a_addr[i] + kk * 2);
#pragma unroll
        for (int j2 = 0; j2 < 2; j2++)
            LDSM_X4(bf[2 * j2][0], bf[2 * j2 + 1][0],
                    bf[2 * j2][1], bf[2 * j2 + 1][1], b_addr[j2] + kk * 2);
#pragma unroll
        for (int i = 0; i < 4; i++)
#pragma unroll
            for (int jn = 0; jn < 4; jn++)
                MMA_F16(acc[i][jn], af[i], bf[jn]);
    }
}

__device__ __forceinline__ void gemm_body(
    const __half* __restrict__ A, const __half* __restrict__ B,
    const float* __restrict__ bias, float* __restrict__ C, char* smx)
{
    const int tid = threadIdx.x;
    const int w = tid >> 5, lane = tid & 31;
    const int wm = w >> 2, wn = w & 3;
    const int m0 = blockIdx.y * GM, n0 = blockIdx.x * GN;
    const int srow = tid >> 3, quad = tid & 7;
    const uint32_t sbase = smem_u32(smx);
    const uint32_t stage_addr[3] = {sbase, sbase + STAGE_BYTES,
                                    sbase + 2 * STAGE_BYTES};

    float acc[4][4][4];
#pragma unroll
    for (int i = 0; i < 4; i++)
#pragma unroll
        for (int j = 0; j < 4; j++)
#pragma unroll
            for (int r = 0; r < 4; r++) acc[i][j][r] = 0.f;

    gemm_issue_stage(A, B, m0, n0, 0, stage_addr[0], srow, quad);
    CP_COMMIT();
    gemm_issue_stage(A, B, m0, n0, 1, stage_addr[1], srow, quad);
    CP_COMMIT();

    for (int kt = 0; kt < NCHUNK; kt++) {
        const int s = kt % 3;
        CP_WAIT1();
        __syncthreads();
        gemm_mma_stage(stage_addr[s], stage_addr[s] + TILE_BYTES_H,
                       acc, wm, wn, lane);
        if (kt + 2 < NCHUNK)
            gemm_issue_stage(A, B, m0, n0, kt + 2, stage_addr[(kt + 2) % 3], srow, quad);
        CP_COMMIT();
    }
    CP_WAIT0();

    const int qrow = lane >> 2, qcol = (lane & 3) * 2;
#pragma unroll
    for (int jn = 0; jn < 4; jn++) {
        const int colg = n0 + wn * 32 + jn * 8 + qcol;
        const float2 bi = *(const float2*)&bias[colg];
#pragma unroll
        for (int i = 0; i < 4; i++) {
            const int rg = m0 + wm * 64 + i * 16 + qrow;
            float2 v0 = make_float2(acc[i][jn][0] + bi.x, acc[i][jn][1] + bi.y);
            float2 v1 = make_float2(acc[i][jn][2] + bi.x, acc[i][jn][3] + bi.y);
            *(float2*)&C[(size_t)rg * HID + colg] = v0;
            *(float2*)&C[(size_t)(rg + 8) * HID + colg] = v1;
        }
    }
}

__global__ __launch_bounds__(256, 2)
void qkv_kernel(const float* __restrict__ biasq)
{
    extern __shared__ char smx[];
    const __half* W = g_wh[blockIdx.z];
    float* C = (blockIdx.z == 0) ? g_q : (blockIdx.z == 1) ? g_k : g_v;
    gemm_body(g_xh, W, biasq + (size_t)blockIdx.z * HID, C, smx);
}

__global__ __launch_bounds__(256, 2)
void out_kernel(const float* __restrict__ bo, float* __restrict__ out)
{
    extern __shared__ char smx[];
    gemm_body(g_atth, g_wh[3], bo, out, smx);
}

// ---------------------------------------------------------------------------
// RoPE (unchanged).
// ---------------------------------------------------------------------------
__global__ void rope_kernel(const int* __restrict__ pos)
{
    int idx = blockIdx.x * blockDim.x + threadIdx.x;
    if (idx >= TTOK * 64) return;
    const int p = idx & 63, t = idx >> 6;

    const double inv = exp(-(double)p * (9.210340371976184 / 64.0));
    const double f = (double)pos[t] * inv;
    const double n = rint(f * 0.15915494309189535);
    const float r = (float)(f - n * 6.283185307179586);
    float s, c;
    __sincosf(r, &s, &c);

    size_t base = (size_t)t * HID + p;
#pragma unroll 4
    for (int h = 0; h < NH; h++) {
        const size_t o = base + (size_t)h * HD;
        float q1 = g_q[o], q2 = g_q[o + 64];
        g_q[o]      = q1 * c - q2 * s;
        g_q[o + 64] = q2 * c + q1 * s;
        float k1 = g_k[o], k2 = g_k[o + 64];
        g_k[o]      = k1 * c - k2 * s;
        g_k[o + 64] = k2 * c + k1 * s;
    }
}

// ===========================================================================
// Attention (R14 fp16-split + ldmatrix for Q/P fragments). AQ=128, 512 thr.
// Row strides: Qh/Ql 136h (272B), Ps 72h (144B) -> 16 mod 128, LDSM-clean.
// ===========================================================================
#define AQ 128
#define AK 64
#define QH_OFF 0
#define QL_OFF 8704
#define KR_OFF 17408
#define VR_OFF 25856
#define PS_OFF 34560
#define RED_OFF 39168
#define ATTN_SMEM ((39168 + 512) * 4)   // 158720 bytes

__global__ __launch_bounds__(512, 1)
void attn_kernel(const float* __restrict__ past_k, const float* __restrict__ past_v,
                 const int* __restrict__ q_start, const int* __restrict__ q_lens,
                 const int* __restrict__ kv_lens, const int* __restrict__ blk_off)
{
    extern __shared__ float sm[];
    __half* Qh = (__half*)(sm + QH_OFF);
    __half* Ql = (__half*)(sm + QL_OFF);
    float* Kr = sm + KR_OFF;
    float* Vr = sm + VR_OFF;
    __half* Ps = (__half*)(sm + PS_OFF);
    float* red = sm + RED_OFF;

    const int qt = blockIdx.x, h = blockIdx.y, b = blockIdx.z;
    const int qlen = q_lens[b];
    if (qt * AQ >= qlen) return;
    const int kvlen = kv_lens[b];
    const int hist = kvlen - qlen;
    const int qs = q_start[b];
    const int tid = threadIdx.x;
    const int w = tid >> 5, lane = tid & 31;
    const int wm = w & 3, wn = w >> 2;
    const int lr = lane >> 2, lc = lane & 3;
    const int lrow = lane & 15, lcol = (lane >> 4) * 8;
    const float scale = 0.088388347648318447f;
    const uint32_t sbase = smem_u32(sm);
    const uint32_t kr_base = sbase + KR_OFF * 4;
    const uint32_t vr_base = sbase + VR_OFF * 4;

    // LDSM base addresses (per-lane) for Q and P fragments
    uint32_t qh_addr[2], ql_addr[2], ps_addr[2];
#pragma unroll
    for (int i = 0; i < 2; i++) {
        const uint32_t roff = (uint32_t)(wm * 32 + i * 16 + lrow);
        qh_addr[i] = sbase + QH_OFF * 4 + (roff * 136 + lcol) * 2;
        ql_addr[i] = sbase + QL_OFF * 4 + (roff * 136 + lcol) * 2;
        ps_addr[i] = sbase + PS_OFF * 4 + (roff * 72 + lcol) * 2;
    }

    const int ntiles = hist / AK + 2 * qt + 2;
    auto kv_src = [&](int kt, const float*& ks, const float*& vs, int& rstr) {
        if (kt * AK >= hist) {
            size_t o = (size_t)(qs + kt * AK - hist) * HID + h * HD;
            ks = g_k + o; vs = g_v + o; rstr = HID;
        } else {
            int blk = blk_off[b * MAXB + kt];
            size_t o = ((size_t)(blk * 64) * NH + h) * HD;
            ks = past_k + o; vs = past_v + o; rstr = NH * HD;
        }
    };
    auto issue_K = [&](int kt) {
        const float* ks; const float* vs; int rstr;
        kv_src(kt, ks, vs, rstr);
#pragma unroll
        for (int l = 0; l < 4; l++) {
            int f4 = tid + l * 512;
            int r = f4 >> 5, c = f4 & 31;
            CP_ASYNC16(kr_base + (uint32_t)(r * 132 + c * 4) * 4,
                       ks + (size_t)r * rstr + c * 4);
        }
    };
    auto issue_V = [&](int kt) {
        const float* ks; const float* vs; int rstr;
        kv_src(kt, ks, vs, rstr);
#pragma unroll
        for (int l = 0; l < 4; l++) {
            int f4 = tid + l * 512;
            int r = f4 >> 5, c = f4 & 31;
            CP_ASYNC16(vr_base + (uint32_t)(r * 136 + c * 4) * 4,
                       vs + (size_t)r * rstr + c * 4);
        }
    };

    // ---- Stage Q once (scaled, fp16 hi / fp16 lo residual) ----
#pragma unroll
    for (int l = 0; l < 8; l++) {
        int f4 = tid + l * 512;
        int r = f4 >> 5;
        int c = (f4 & 31) * 4;
        float4 v = *(const float4*)(g_q + (size_t)(qs + qt * AQ + r) * HID + h * HD + c);
        float xv[4] = {v.x * scale, v.y * scale, v.z * scale, v.w * scale};
        __half hi[4];
        float  lo[4];
#pragma unroll
        for (int s = 0; s < 4; s++) {
            hi[s] = __float2half_rn(xv[s]);
            lo[s] = xv[s] - __half2float(hi[s]);
        }
        *(__half2*)(Qh + r * 136 + c)     = __halves2half2(hi[0], hi[1]);
        *(__half2*)(Qh + r * 136 + c + 2) = __halves2half2(hi[2], hi[3]);
        *(__half2*)(Ql + r * 136 + c)     = __floats2half2_rn(lo[0], lo[1]);
        *(__half2*)(Ql + r * 136 + c + 2) = __floats2half2_rn(lo[2], lo[3]);
    }
    issue_K(0); CP_COMMIT();
    issue_V(0); CP_COMMIT();

    float m_i[2][2], l_i[2][2], acco[2][4][4];
#pragma unroll
    for (int i = 0; i < 2; i++)
#pragma unroll
        for (int hf = 0; hf < 2; hf++) { m_i[i][hf] = -3.0e38f; l_i[i][hf] = 0.f; }
#pragma unroll
    for (int i = 0; i < 2; i++)
#pragma unroll
        for (int j = 0; j < 4; j++)
#pragma unroll
            for (int e = 0; e < 4; e++) acco[i][j][e] = 0.f;

    for (int kt = 0; kt < ntiles; kt++) {
        CP_WAIT1();
        __syncthreads();

        // ---- S = Q K^T, fp16 3-term split ----
        float accs[2][2][4];
#pragma unroll
        for (int i = 0; i < 2; i++)
#pragma unroll
            for (int j = 0; j < 2; j++)
#pragma unroll
                for (int e = 0; e < 4; e++) accs[i][j][e] = 0.f;

#pragma unroll
        for (int ks = 0; ks < 8; ks++) {
            const int kk = ks * 16;
            const int ka = kk + 2 * lc;
            uint32_t ah[2][4], al[2][4], bh[2][2], bl[2][2];
#pragma unroll
            for (int i = 0; i < 2; i++) {
                LDSM_X4(ah[i][0], ah[i][1], ah[i][2], ah[i][3], qh_addr[i] + kk * 2);
                LDSM_X4(al[i][0], al[i][1], al[i][2], al[i][3], ql_addr[i] + kk * 2);
            }
#pragma unroll
            for (int j = 0; j < 2; j++) {
                const int n0 = wn * 16 + j * 8 + lr;
                float2 f01 = *(const float2*)(Kr + n0 * 132 + ka);
                float2 f23 = *(const float2*)(Kr + n0 * 132 + ka + 8);
                __half2 h01 = __floats2half2_rn(f01.x, f01.y);
                __half2 h23 = __floats2half2_rn(f23.x, f23.y);
                bh[j][0] = h2_u32(h01);
                bh[j][1] = h2_u32(h23);
                bl[j][0] = h2_u32(__floats2half2_rn(
                    f01.x - __half2float(__low2half(h01)),
                    f01.y - __half2float(__high2half(h01))));
                bl[j][1] = h2_u32(__floats2half2_rn(
                    f23.x - __half2float(__low2half(h23)),
                    f23.y - __half2float(__high2half(h23))));
            }
#pragma unroll
            for (int i = 0; i < 2; i++)
#pragma unroll
                for (int j = 0; j < 2; j++) {
                    MMA_F16(accs[i][j], ah[i], bh[j]);
                    MMA_F16(accs[i][j], ah[i], bl[j]);
                    MMA_F16(accs[i][j], al[i], bh[j]);
                }
        }

        // ---- Causal mask ----
        const int lim_off = hist + qt * AQ - kt * 64;
        if (lim_off < 63) {
#pragma unroll
            for (int i = 0; i < 2; i++)
#pragma unroll
                for (int j = 0; j < 2; j++) {
                    const int r0 = wm * 32 + i * 16 + lr;
                    const int c0 = wn * 16 + j * 8 + 2 * lc;
                    if (c0 > lim_off + r0)     accs[i][j][0] = -1e30f;
                    if (c0 + 1 > lim_off + r0) accs[i][j][1] = -1e30f;
                    if (c0 > lim_off + r0 + 8)     accs[i][j][2] = -1e30f;
                    if (c0 + 1 > lim_off + r0 + 8) accs[i][j][3] = -1e30f;
                }
        }

        // ---- Online softmax: cross-warp row max ----
#pragma unroll
        for (int i = 0; i < 2; i++)
#pragma unroll
            for (int hf = 0; hf < 2; hf++) {
                float v = fmaxf(fmaxf(accs[i][0][2 * hf], accs[i][0][2 * hf + 1]),
                                fmaxf(accs[i][1][2 * hf], accs[i][1][2 * hf + 1]));
                v = fmaxf(v, __shfl_xor_sync(0xffffffffu, v, 1));
                v = fmaxf(v, __shfl_xor_sync(0xffffffffu, v, 2));
                if (lc == 0)
                    red[wn * 128 + wm * 32 + i * 16 + hf * 8 + lr] = v;
            }
        __syncthreads();

        float alpha[2][2];
#pragma unroll
        for (int i = 0; i < 2; i++)
#pragma unroll
            for (int hf = 0; hf < 2; hf++) {
                const int r = wm * 32 + i * 16 + hf * 8 + lr;
                float tm = fmaxf(fmaxf(red[r], red[128 + r]),
                                 fmaxf(red[256 + r], red[384 + r]));
                float mnew = fmaxf(m_i[i][hf], tm);
                alpha[i][hf] = __expf(m_i[i][hf] - mnew);
                m_i[i][hf] = mnew;
            }
        __syncthreads();
        if (kt + 1 < ntiles) issue_K(kt + 1);
        CP_COMMIT();

        // ---- p = exp; partial sums; P -> smem (fp16) ----
#pragma unroll
        for (int i = 0; i < 2; i++)
#pragma unroll
            for (int j = 0; j < 2; j++)
#pragma unroll
                for (int e = 0; e < 4; e++)
                    accs[i][j][e] = __expf(accs[i][j][e] - m_i[i][e >> 1]);

#pragma unroll
        for (int i = 0; i < 2; i++)
#pragma unroll
            for (int hf = 0; hf < 2; hf++) {
                float ps = (accs[i][0][2 * hf] + accs[i][0][2 * hf + 1]) +
                           (accs[i][1][2 * hf] + accs[i][1][2 * hf + 1]);
                ps += __shfl_xor_sync(0xffffffffu, ps, 1);
                ps += __shfl_xor_sync(0xffffffffu, ps, 2);
                if (lc == 0)
                    red[wn * 128 + wm * 32 + i * 16 + hf * 8 + lr] = ps;
            }
#pragma unroll
        for (int i = 0; i < 2; i++)
#pragma unroll
            for (int j = 0; j < 2; j++) {
                const int r0 = wm * 32 + i * 16 + lr;
                const int cp = wn * 16 + j * 8 + 2 * lc;
                *(__half2*)(Ps + r0 * 72 + cp) =
                    __floats2half2_rn(accs[i][j][0], accs[i][j][1]);
                *(__half2*)(Ps + (r0 + 8) * 72 + cp) =
                    __floats2half2_rn(accs[i][j][2], accs[i][j][3]);
            }
        CP_WAIT1();
        __syncthreads();

#pragma unroll
        for (int i = 0; i < 2; i++)
#pragma unroll
            for (int hf = 0; hf < 2; hf++) {
                const int r = wm * 32 + i * 16 + hf * 8 + lr;
                l_i[i][hf] = l_i[i][hf] * alpha[i][hf] +
                             ((red[r] + red[128 + r]) + (red[256 + r] + red[384 + r]));
            }
#pragma unroll
        for (int i = 0; i < 2; i++)
#pragma unroll
            for (int j = 0; j < 4; j++)
#pragma unroll
                for (int e = 0; e < 4; e++)
                    acco[i][j][e] *= alpha[i][e >> 1];

        // ---- O += P V (1x fp16, P via ldmatrix, V fp16-rounded at load) ----
#pragma unroll
        for (int ks = 0; ks < 4; ks++) {
            const int kk = ks * 16;
            const int ka = kk + 2 * lc;
            uint32_t af[2][4], bf[4][2];
#pragma unroll
            for (int i = 0; i < 2; i++)
                LDSM_X4(af[i][0], af[i][1], af[i][2], af[i][3], ps_addr[i] + kk * 2);
#pragma unroll
            for (int j = 0; j < 4; j++) {
                const int n0 = wn * 32 + j * 8 + lr;
                float v0 = Vr[(ka) * 136 + n0];
                float v1 = Vr[(ka + 1) * 136 + n0];
                float v2 = Vr[(ka + 8) * 136 + n0];
                float v3 = Vr[(ka + 9) * 136 + n0];
                bf[j][0] = h2_u32(__floats2half2_rn(v0, v1));
                bf[j][1] = h2_u32(__floats2half2_rn(v2, v3));
            }
#pragma unroll
            for (int i = 0; i < 2; i++)
#pragma unroll
                for (int j = 0; j < 4; j++)
                    MMA_F16(acco[i][j], af[i], bf[j]);
        }
        __syncthreads();
        if (kt + 1 < ntiles) issue_V(kt + 1);
        CP_COMMIT();
    }

    // ---- Epilogue: normalize, store fp16 ----
    float inv_l[2][2];
#pragma unroll
    for (int i = 0; i < 2; i++)
#pragma unroll
        for (int hf = 0; hf < 2; hf++) inv_l[i][hf] = 1.0f / l_i[i][hf];

#pragma unroll
    for (int i = 0; i < 2; i++)
#pragma unroll
        for (int j = 0; j < 4; j++) {
            const int r0 = qs + qt * AQ + wm * 32 + i * 16 + lr;
            const int col = h * HD + wn * 32 + j * 8 + 2 * lc;
            *(__half2*)&g_atth[(size_t)r0 * HID + col] =
                __floats2half2_rn(acco[i][j][0] * inv_l[i][0],
                                  acco[i][j][1] * inv_l[i][0]);
            *(__half2*)&g_atth[(size_t)(r0 + 8) * HID + col] =
                __floats2half2_rn(acco[i][j][2] * inv_l[i][1],
                                  acco[i][j][3] * inv_l[i][1]);
        }
}

// ---------------------------------------------------------------------------
__device__ float g_bias[3 * HID];
__global__ void pack_bias(const float* __restrict__ bq, const float* __restrict__ bk,
                          const float* __restrict__ bv)
{
    int i = blockIdx.x * blockDim.x + threadIdx.x;
    if (i < HID) {
        g_bias[i] = bq[i];
        g_bias[HID + i] = bk[i];
        g_bias[2 * HID + i] = bv[i];
    }
}

// ---------------------------------------------------------------------------
extern "C" void kernel_launch(void* const* d_in, const int* in_sizes, int n_in,
                              void* d_out, int out_size)
{
    const float* hidden  = (const float*)d_in[0];
    const int*   pos     = (const int*)d_in[1];
    const int*   q_start = (const int*)d_in[2];
    const int*   q_lens  = (const int*)d_in[3];
    const int*   kv_lens = (const int*)d_in[4];
    const int*   blk_off = (const int*)d_in[5];
    const float* past_k  = (const float*)d_in[6];
    const float* past_v  = (const float*)d_in[7];
    const float* Wq = (const float*)d_in[8];
    const float* bq = (const float*)d_in[9];
    const float* Wk = (const float*)d_in[10];
    const float* bk = (const float*)d_in[11];
    const float* Wv = (const float*)d_in[12];
    const float* bv = (const float*)d_in[13];
    const float* Wo = (const float*)d_in[14];
    const float* bo = (const float*)d_in[15];
    float* out = (float*)d_out;

    (void)cudaFuncSetAttribute(qkv_kernel, cudaFuncAttributeMaxDynamicSharedMemorySize, GEMM_SMEM);
    (void)cudaFuncSetAttribute(out_kernel, cudaFuncAttributeMaxDynamicSharedMemorySize, GEMM_SMEM);
    (void)cudaFuncSetAttribute(attn_kernel, cudaFuncAttributeMaxDynamicSharedMemorySize, ATTN_SMEM);

    // 0) fp16 prepass + bias packing
    cvt_prepass<<<dim3(2048, 5), 256>>>(
        (const float4*)hidden, (const float4*)Wq, (const float4*)Wk,
        (const float4*)Wv, (const float4*)Wo);
    pack_bias<<<(HID + 255) / 256, 256>>>(bq, bk, bv);

    // 1) fused QKV projections (fp16 mma + ldmatrix)
    float* g_bias_ptr = nullptr;
    (void)cudaGetSymbolAddress((void**)&g_bias_ptr, g_bias);
    dim3 gq(HID / GN, TTOK / GM, 3);
    qkv_kernel<<<gq, 256, GEMM_SMEM>>>(g_bias_ptr);

    // 2) RoPE
    rope_kernel<<<(TTOK * 64 + 255) / 256, 256>>>(pos);

    // 3) fp16-split tensor-core paged causal flash attention
    dim3 ga(8, NH, 4);
    attn_kernel<<<ga, 512, ATTN_SMEM>>>(past_k, past_v, q_start, q_lens, kv_lens, blk_off);

    // 4) output projection (fp16 mma + ldmatrix)
    dim3 go(HID / GN, TTOK / GM, 1);
    out_kernel<<<go, 256, GEMM_SMEM>>>(bo, out);
}